// round 1
// baseline (speedup 1.0000x reference)
#include <cuda_runtime.h>
#include <cuda_bf16.h>
#include <cstdint>
#include <cstdio>

// ---------------------------------------------------------------------------
// Het_GNN forward. Sizes are fixed by the problem.
// ---------------------------------------------------------------------------
#define BB   512          // batch
#define PP   24           // posts per batch
#define UU   24           // users per batch
#define MPU  (BB*PP)      // 12288
#define EE   2000         // embed dim (2H)
#define INI  512
#define WRS  (3*2000*512) // reordered lstm weight elems per set
#define BRS  (3*2000)

// ---------------- scratch (device globals; no allocation allowed) ----------
__device__ float g_bufX[MPU * INI];        // projected inputs   [12288,512]
__device__ float g_Hc  [BB  * EE];         // center embed       [512,2000]
__device__ float g_Hp  [MPU * EE];         // post embeds        [12288,2000]
__device__ float g_Hu  [MPU * EE];         // user embeds        [12288,2000]
__device__ float g_H2  [MPU * EE];         // agg lstm out
__device__ float g_Z   [MPU * EE];         // agg out linear
__device__ float g_uagg[BB * EE];
__device__ float g_pagg[BB * EE];
__device__ float g_Wr  [5 * WRS];          // reordered lstm weights (t,i,o,ua,pa)
__device__ float g_br  [5 * BRS];

// ---------------- helpers ---------------------------------------------------
__device__ __forceinline__ unsigned tf32cvt(float x) {
    unsigned r;
    asm("cvt.rna.tf32.f32 %0, %1;" : "=r"(r) : "f"(x));
    return r;
}

__device__ __forceinline__ void mma_tf32(float& d0, float& d1, float& d2, float& d3,
                                         unsigned a0, unsigned a1, unsigned a2, unsigned a3,
                                         unsigned b0, unsigned b1) {
    asm volatile(
        "mma.sync.aligned.m16n8k8.row.col.f32.tf32.tf32.f32 "
        "{%0,%1,%2,%3}, {%4,%5,%6,%7}, {%8,%9}, {%0,%1,%2,%3};"
        : "+f"(d0), "+f"(d1), "+f"(d2), "+f"(d3)
        : "r"(a0), "r"(a1), "r"(a2), "r"(a3), "r"(b0), "r"(b1));
}

__device__ __forceinline__ float sigf(float x) {
    return 1.0f / (1.0f + __expf(-x));
}
__device__ __forceinline__ float tanh_fast(float x) {
    // tanh(x) = 2*sigmoid(2x) - 1 ; saturates correctly at +-inf
    return 2.0f / (1.0f + __expf(-2.0f * x)) - 1.0f;
}

// ---------------- weight reorder: [2,4H,512] -> [3,2000,512] (i,g,o) --------
__global__ void reorder_lstm(const float* __restrict__ W, const float* __restrict__ b,
                             float* __restrict__ Wr, float* __restrict__ br) {
    int idx = blockIdx.x * blockDim.x + threadIdx.x;
    const int TOT = 3 * 2000 * 512;
    if (idx < TOT) {
        int k = idx & 511;
        int n = (idx >> 9) % 2000;
        int t = idx / (2000 * 512);
        int d = n / 1000, j = n % 1000;
        int toff = (t == 0) ? 0 : (t == 1 ? 2000 : 3000);
        Wr[idx] = W[(size_t)(d * 4000 + toff + j) * 512 + k];
    }
    if (idx < 3 * 2000) {
        int n = idx % 2000;
        int t = idx / 2000;
        int d = n / 1000, j = n % 1000;
        int toff = (t == 0) ? 0 : (t == 1 ? 2000 : 3000);
        br[idx] = b[d * 4000 + toff + j];
    }
}

// ---------------- generic linear: C[M,N] = A[M,K] @ W[N,K]^T + bias ---------
// tf32 mma.sync, BM=128 BN=64 BK=16, 256 threads (8 warps, 4x2)
__global__ __launch_bounds__(256, 1) void gemm_lin(
    const float* __restrict__ A, const float* __restrict__ W,
    const float* __restrict__ bias, float* __restrict__ C,
    int M, int N, int K) {
    __shared__ float As[16][136];
    __shared__ float Bs[16][72];
    const int tid = threadIdx.x;
    const int wid = tid >> 5, lane = tid & 31;
    const int wm = wid & 3, wn = wid >> 2;
    const int lr = lane >> 2, lc = lane & 3;
    const int m0 = blockIdx.y * 128, n0 = blockIdx.x * 64;
    const int ar = tid & 63, aj = tid >> 6;

    float acc[2][4][4];
#pragma unroll
    for (int mi = 0; mi < 2; mi++)
#pragma unroll
        for (int ni = 0; ni < 4; ni++)
#pragma unroll
            for (int r = 0; r < 4; r++) acc[mi][ni][r] = 0.0f;

    for (int kt = 0; kt < K; kt += 16) {
#pragma unroll
        for (int p = 0; p < 2; p++) {
            int r = ar + (p << 6);
            const float4 v = *reinterpret_cast<const float4*>(A + (size_t)(m0 + r) * K + kt + (aj << 2));
            As[(aj << 2) + 0][r] = __uint_as_float(tf32cvt(v.x));
            As[(aj << 2) + 1][r] = __uint_as_float(tf32cvt(v.y));
            As[(aj << 2) + 2][r] = __uint_as_float(tf32cvt(v.z));
            As[(aj << 2) + 3][r] = __uint_as_float(tf32cvt(v.w));
        }
        {
            float4 v = make_float4(0.f, 0.f, 0.f, 0.f);
            if (n0 + ar < N)
                v = *reinterpret_cast<const float4*>(W + (size_t)(n0 + ar) * K + kt + (aj << 2));
            Bs[(aj << 2) + 0][ar] = __uint_as_float(tf32cvt(v.x));
            Bs[(aj << 2) + 1][ar] = __uint_as_float(tf32cvt(v.y));
            Bs[(aj << 2) + 2][ar] = __uint_as_float(tf32cvt(v.z));
            Bs[(aj << 2) + 3][ar] = __uint_as_float(tf32cvt(v.w));
        }
        __syncthreads();
#pragma unroll
        for (int ks = 0; ks < 16; ks += 8) {
            unsigned af[2][4], bf[4][2];
#pragma unroll
            for (int mi = 0; mi < 2; mi++) {
                int mb = wm * 32 + mi * 16;
                af[mi][0] = __float_as_uint(As[ks + lc][mb + lr]);
                af[mi][1] = __float_as_uint(As[ks + lc][mb + lr + 8]);
                af[mi][2] = __float_as_uint(As[ks + lc + 4][mb + lr]);
                af[mi][3] = __float_as_uint(As[ks + lc + 4][mb + lr + 8]);
            }
#pragma unroll
            for (int ni = 0; ni < 4; ni++) {
                int nb = wn * 32 + ni * 8;
                bf[ni][0] = __float_as_uint(Bs[ks + lc][nb + lr]);
                bf[ni][1] = __float_as_uint(Bs[ks + lc + 4][nb + lr]);
            }
#pragma unroll
            for (int mi = 0; mi < 2; mi++)
#pragma unroll
                for (int ni = 0; ni < 4; ni++)
                    mma_tf32(acc[mi][ni][0], acc[mi][ni][1], acc[mi][ni][2], acc[mi][ni][3],
                             af[mi][0], af[mi][1], af[mi][2], af[mi][3],
                             bf[ni][0], bf[ni][1]);
        }
        __syncthreads();
    }

#pragma unroll
    for (int mi = 0; mi < 2; mi++)
#pragma unroll
        for (int ni = 0; ni < 4; ni++) {
            int m = m0 + wm * 32 + mi * 16 + lr;
            int n = n0 + wn * 32 + ni * 8 + lc * 2;
            if (n < N) {
                C[(size_t)m * N + n] = acc[mi][ni][0] + bias[n];
                C[(size_t)(m + 8) * N + n] = acc[mi][ni][2] + bias[n];
            }
            if (n + 1 < N) {
                C[(size_t)m * N + n + 1] = acc[mi][ni][1] + bias[n + 1];
                C[(size_t)(m + 8) * N + n + 1] = acc[mi][ni][3] + bias[n + 1];
            }
        }
}

// ---------------- fused single-step BiLSTM GEMM -----------------------------
// H[M,2000] = scale * act( X[M,512] @ Wr[3,2000,512]^T + br[3,2000] ) (+ H)
// where act per col n: h = sigmoid(g_o) * tanh( sigmoid(g_i) * tanh(g_g) )
__global__ __launch_bounds__(256, 1) void gemm_lstm(
    const float* __restrict__ X, const float* __restrict__ Wr,
    const float* __restrict__ br, float* __restrict__ C,
    int M, int K, float scale, int accum) {
    const int N = 2000;
    __shared__ float As[16][136];
    __shared__ float Bs[3][16][72];
    const int tid = threadIdx.x;
    const int wid = tid >> 5, lane = tid & 31;
    const int wm = wid & 3, wn = wid >> 2;
    const int lr = lane >> 2, lc = lane & 3;
    const int m0 = blockIdx.y * 128, n0 = blockIdx.x * 64;
    const int ar = tid & 63, aj = tid >> 6;

    float acc[3][2][4][4];
#pragma unroll
    for (int t = 0; t < 3; t++)
#pragma unroll
        for (int mi = 0; mi < 2; mi++)
#pragma unroll
            for (int ni = 0; ni < 4; ni++)
#pragma unroll
                for (int r = 0; r < 4; r++) acc[t][mi][ni][r] = 0.0f;

    for (int kt = 0; kt < K; kt += 16) {
#pragma unroll
        for (int p = 0; p < 2; p++) {
            int r = ar + (p << 6);
            const float4 v = *reinterpret_cast<const float4*>(X + (size_t)(m0 + r) * K + kt + (aj << 2));
            As[(aj << 2) + 0][r] = __uint_as_float(tf32cvt(v.x));
            As[(aj << 2) + 1][r] = __uint_as_float(tf32cvt(v.y));
            As[(aj << 2) + 2][r] = __uint_as_float(tf32cvt(v.z));
            As[(aj << 2) + 3][r] = __uint_as_float(tf32cvt(v.w));
        }
#pragma unroll
        for (int t = 0; t < 3; t++) {
            float4 v = make_float4(0.f, 0.f, 0.f, 0.f);
            if (n0 + ar < N)
                v = *reinterpret_cast<const float4*>(Wr + (size_t)(t * 2000 + n0 + ar) * K + kt + (aj << 2));
            Bs[t][(aj << 2) + 0][ar] = __uint_as_float(tf32cvt(v.x));
            Bs[t][(aj << 2) + 1][ar] = __uint_as_float(tf32cvt(v.y));
            Bs[t][(aj << 2) + 2][ar] = __uint_as_float(tf32cvt(v.z));
            Bs[t][(aj << 2) + 3][ar] = __uint_as_float(tf32cvt(v.w));
        }
        __syncthreads();
#pragma unroll
        for (int ks = 0; ks < 16; ks += 8) {
            unsigned af[2][4], bf[3][4][2];
#pragma unroll
            for (int mi = 0; mi < 2; mi++) {
                int mb = wm * 32 + mi * 16;
                af[mi][0] = __float_as_uint(As[ks + lc][mb + lr]);
                af[mi][1] = __float_as_uint(As[ks + lc][mb + lr + 8]);
                af[mi][2] = __float_as_uint(As[ks + lc + 4][mb + lr]);
                af[mi][3] = __float_as_uint(As[ks + lc + 4][mb + lr + 8]);
            }
#pragma unroll
            for (int t = 0; t < 3; t++)
#pragma unroll
                for (int ni = 0; ni < 4; ni++) {
                    int nb = wn * 32 + ni * 8;
                    bf[t][ni][0] = __float_as_uint(Bs[t][ks + lc][nb + lr]);
                    bf[t][ni][1] = __float_as_uint(Bs[t][ks + lc + 4][nb + lr]);
                }
#pragma unroll
            for (int t = 0; t < 3; t++)
#pragma unroll
                for (int mi = 0; mi < 2; mi++)
#pragma unroll
                    for (int ni = 0; ni < 4; ni++)
                        mma_tf32(acc[t][mi][ni][0], acc[t][mi][ni][1], acc[t][mi][ni][2], acc[t][mi][ni][3],
                                 af[mi][0], af[mi][1], af[mi][2], af[mi][3],
                                 bf[t][ni][0], bf[t][ni][1]);
        }
        __syncthreads();
    }

#pragma unroll
    for (int mi = 0; mi < 2; mi++)
#pragma unroll
        for (int ni = 0; ni < 4; ni++) {
            int mA = m0 + wm * 32 + mi * 16 + lr;
            int nA = n0 + wn * 32 + ni * 8 + lc * 2;
#pragma unroll
            for (int r = 0; r < 4; r++) {
                int mm = mA + ((r >= 2) ? 8 : 0);
                int nn = nA + (r & 1);
                if (nn < N) {
                    float gi = acc[0][mi][ni][r] + br[nn];
                    float gg = acc[1][mi][ni][r] + br[2000 + nn];
                    float go = acc[2][mi][ni][r] + br[4000 + nn];
                    float cc = sigf(gi) * tanh_fast(gg);
                    float h = sigf(go) * tanh_fast(cc);
                    float o = scale * h;
                    if (accum) o += C[(size_t)mm * N + nn];
                    C[(size_t)mm * N + nn] = o;
                }
            }
        }
}

// ---------------- neighbor mean: [B,24,E] -> [B,E] --------------------------
__global__ void mean_kernel(const float* __restrict__ Z, float* __restrict__ out) {
    int idx = blockIdx.x * blockDim.x + threadIdx.x;
    if (idx >= BB * EE) return;
    int b = idx / EE, n = idx % EE;
    float s = 0.f;
#pragma unroll 4
    for (int j = 0; j < 24; j++) s += Z[(size_t)(b * 24 + j) * EE + n];
    out[idx] = s * (1.0f / 24.0f);
}

// ---------------- 3-way attention combine -----------------------------------
__global__ void attention_kernel(const float* __restrict__ c, const float* __restrict__ u,
                                 const float* __restrict__ p, const float* __restrict__ att,
                                 float* __restrict__ out) {
    int b = blockIdx.x, tid = threadIdx.x;
    const float* cb = c + (size_t)b * EE;
    const float* ub = u + (size_t)b * EE;
    const float* pb = p + (size_t)b * EE;
    float s0 = 0.f, s1 = 0.f, s2 = 0.f, s3 = 0.f;
    for (int n = tid; n < EE; n += 256) {
        float a0 = att[n], a1 = att[EE + n];
        float cv = cb[n];
        s0 += cv * a0;
        s1 += cv * a1;
        s2 += ub[n] * a1;
        s3 += pb[n] * a1;
    }
    __shared__ float red[4][256];
    red[0][tid] = s0; red[1][tid] = s1; red[2][tid] = s2; red[3][tid] = s3;
    __syncthreads();
    for (int s = 128; s > 0; s >>= 1) {
        if (tid < s) {
#pragma unroll
            for (int q = 0; q < 4; q++) red[q][tid] += red[q][tid + s];
        }
        __syncthreads();
    }
    __shared__ float w[3];
    if (tid == 0) {
        float sc[3];
        sc[0] = red[0][0] + red[1][0];
        sc[1] = red[0][0] + red[2][0];
        sc[2] = red[0][0] + red[3][0];
#pragma unroll
        for (int k = 0; k < 3; k++) sc[k] = sc[k] > 0.f ? sc[k] : 0.01f * sc[k];
        float mx = fmaxf(sc[0], fmaxf(sc[1], sc[2]));
        float e0 = __expf(sc[0] - mx), e1 = __expf(sc[1] - mx), e2 = __expf(sc[2] - mx);
        float inv = 1.0f / (e0 + e1 + e2);
        w[0] = e0 * inv; w[1] = e1 * inv; w[2] = e2 * inv;
    }
    __syncthreads();
    float w0 = w[0], w1 = w[1], w2 = w[2];
    for (int n = tid; n < EE; n += 256)
        out[(size_t)b * EE + n] = w0 * cb[n] + w1 * ub[n] + w2 * pb[n];
}

// ---------------------------------------------------------------------------
extern "C" void kernel_launch(void* const* d_in, const int* in_sizes, int n_in,
                              void* d_out, int out_size) {
    const float* c_text  = (const float*)d_in[0];
    const float* c_image = (const float*)d_in[1];
    const float* p_text  = (const float*)d_in[2];
    const float* p_image = (const float*)d_in[3];
    const float* u_text  = (const float*)d_in[4];
    const float* u_other = (const float*)d_in[5];
    const float* W_lt = (const float*)d_in[6],  *b_lt = (const float*)d_in[7];
    const float* W_li = (const float*)d_in[8],  *b_li = (const float*)d_in[9];
    const float* W_lo = (const float*)d_in[10], *b_lo = (const float*)d_in[11];
    const float* lstm_t_W = (const float*)d_in[12], *lstm_t_b = (const float*)d_in[13];
    const float* lstm_i_W = (const float*)d_in[14], *lstm_i_b = (const float*)d_in[15];
    const float* lstm_o_W = (const float*)d_in[16], *lstm_o_b = (const float*)d_in[17];
    const float* ua_lin_W = (const float*)d_in[18], *ua_lin_b = (const float*)d_in[19];
    const float* ua_lstm_W = (const float*)d_in[20], *ua_lstm_b = (const float*)d_in[21];
    const float* ua_out_W = (const float*)d_in[22], *ua_out_b = (const float*)d_in[23];
    const float* pa_lin_W = (const float*)d_in[24], *pa_lin_b = (const float*)d_in[25];
    const float* pa_lstm_W = (const float*)d_in[26], *pa_lstm_b = (const float*)d_in[27];
    const float* pa_out_W = (const float*)d_in[28], *pa_out_b = (const float*)d_in[29];
    const float* p_att = (const float*)d_in[30];
    float* out = (float*)d_out;

    float *bufX, *Hc, *Hp, *Hu, *H2, *Z, *uagg, *pagg, *Wr, *br;
    cudaGetSymbolAddress((void**)&bufX, g_bufX);
    cudaGetSymbolAddress((void**)&Hc,   g_Hc);
    cudaGetSymbolAddress((void**)&Hp,   g_Hp);
    cudaGetSymbolAddress((void**)&Hu,   g_Hu);
    cudaGetSymbolAddress((void**)&H2,   g_H2);
    cudaGetSymbolAddress((void**)&Z,    g_Z);
    cudaGetSymbolAddress((void**)&uagg, g_uagg);
    cudaGetSymbolAddress((void**)&pagg, g_pagg);
    cudaGetSymbolAddress((void**)&Wr,   g_Wr);
    cudaGetSymbolAddress((void**)&br,   g_br);

    const int RB = (3 * 2000 * 512 + 255) / 256;
    reorder_lstm<<<RB, 256>>>(lstm_t_W,  lstm_t_b,  Wr + 0 * WRS, br + 0 * BRS);
    reorder_lstm<<<RB, 256>>>(lstm_i_W,  lstm_i_b,  Wr + 1 * WRS, br + 1 * BRS);
    reorder_lstm<<<RB, 256>>>(lstm_o_W,  lstm_o_b,  Wr + 2 * WRS, br + 2 * BRS);
    reorder_lstm<<<RB, 256>>>(ua_lstm_W, ua_lstm_b, Wr + 3 * WRS, br + 3 * BRS);
    reorder_lstm<<<RB, 256>>>(pa_lstm_W, pa_lstm_b, Wr + 4 * WRS, br + 4 * BRS);

    auto L1 = [&](const float* A, const float* W, const float* b, float* C,
                  int M, int N, int K) {
        dim3 g((N + 63) / 64, M / 128);
        gemm_lin<<<g, 256>>>(A, W, b, C, M, N, K);
    };
    auto L2 = [&](const float* X, int wi, float* C, int M, float scale, int accum) {
        dim3 g((2000 + 63) / 64, M / 128);
        gemm_lstm<<<g, 256>>>(X, Wr + (size_t)wi * WRS, br + (size_t)wi * BRS,
                              C, M, 512, scale, accum);
    };

    // ---- per-type input linear + BiLSTM ----
    L1(c_text,  W_lt, b_lt, bufX, BB, 512, 768);    L2(bufX, 0, Hc, BB, 0.5f, 0);
    L1(c_image, W_li, b_li, bufX, BB, 512, 2048);   L2(bufX, 1, Hc, BB, 0.5f, 1);
    L1(p_text,  W_lt, b_lt, bufX, MPU, 512, 768);   L2(bufX, 0, Hp, MPU, 0.5f, 0);
    L1(p_image, W_li, b_li, bufX, MPU, 512, 2048);  L2(bufX, 1, Hp, MPU, 0.5f, 1);
    L1(u_text,  W_lt, b_lt, bufX, MPU, 512, 768);   L2(bufX, 0, Hu, MPU, 0.5f, 0);
    L1(u_other, W_lo, b_lo, bufX, MPU, 512, 512);   L2(bufX, 2, Hu, MPU, 0.5f, 1);

    // ---- user aggregation ----
    L1(Hu, ua_lin_W, ua_lin_b, bufX, MPU, 512, 2000);
    L2(bufX, 3, H2, MPU, 1.0f, 0);
    L1(H2, ua_out_W, ua_out_b, Z, MPU, 2000, 2000);
    mean_kernel<<<(BB * EE + 255) / 256, 256>>>(Z, uagg);

    // ---- post aggregation ----
    L1(Hp, pa_lin_W, pa_lin_b, bufX, MPU, 512, 2000);
    L2(bufX, 4, H2, MPU, 1.0f, 0);
    L1(H2, pa_out_W, pa_out_b, Z, MPU, 2000, 2000);
    mean_kernel<<<(BB * EE + 255) / 256, 256>>>(Z, pagg);

    // ---- attention combine ----
    attention_kernel<<<BB, 256>>>(Hc, uagg, pagg, p_att, out);
}

// round 2
// speedup vs baseline: 1.6181x; 1.6181x over previous
#include <cuda_runtime.h>
#include <cuda_bf16.h>
#include <cstdint>

// ---------------------------------------------------------------------------
// Het_GNN forward. Sizes fixed by the problem.
// ---------------------------------------------------------------------------
#define BB   512
#define PP   24
#define MPU  (BB*PP)      // 12288
#define EE   2000
#define INI  512

// ---------------- scratch (device globals; no allocation allowed) ----------
__device__ float g_bufX[MPU * INI];
__device__ float g_Hc  [BB  * EE];
__device__ float g_Hp  [MPU * EE];
__device__ float g_Hu  [MPU * EE];
__device__ float g_H2  [MPU * EE];
__device__ float g_Z   [MPU * EE];
__device__ float g_uagg[BB * EE];
__device__ float g_pagg[BB * EE];

// ---------------- helpers ---------------------------------------------------
__device__ __forceinline__ unsigned tf32cvt(float x) {
    unsigned r;
    asm("cvt.rna.tf32.f32 %0, %1;" : "=r"(r) : "f"(x));
    return r;
}
__device__ __forceinline__ float u2f(unsigned x) { return __uint_as_float(x); }
__device__ __forceinline__ unsigned f2u(float x) { return __float_as_uint(x); }

__device__ __forceinline__ void mma_tf32(float& d0, float& d1, float& d2, float& d3,
                                         unsigned a0, unsigned a1, unsigned a2, unsigned a3,
                                         unsigned b0, unsigned b1) {
    asm volatile(
        "mma.sync.aligned.m16n8k8.row.col.f32.tf32.tf32.f32 "
        "{%0,%1,%2,%3}, {%4,%5,%6,%7}, {%8,%9}, {%0,%1,%2,%3};"
        : "+f"(d0), "+f"(d1), "+f"(d2), "+f"(d3)
        : "r"(a0), "r"(a1), "r"(a2), "r"(a3), "r"(b0), "r"(b1));
}

__device__ __forceinline__ float sigf(float x) { return 1.0f / (1.0f + __expf(-x)); }
__device__ __forceinline__ float tanh_fast(float x) {
    return 2.0f / (1.0f + __expf(-2.0f * x)) - 1.0f;
}

// ===========================================================================
// gemm_lin v2: C[M,N] = A[M,K] @ W[N,K]^T + bias
// block tile 256x128, BK=16, 8 warps (4m x 2n), warp tile 64x64.
// double-buffered smem + register prefetch, 1 syncthreads per K-tile.
// XOR bank swizzle: element (k,m) stored at col m ^ (((k>>2)&3)<<3).
// ===========================================================================
#define PADA 264     // 256 + 8  (stride ≡ 8 mod 32)
#define PADB 136     // 128 + 8
#define SMEM_LIN ((2*16*PADA + 2*16*PADB) * 4)

__global__ __launch_bounds__(256, 1) void gemm_lin(
    const float* __restrict__ A, const float* __restrict__ W,
    const float* __restrict__ bias, float* __restrict__ C,
    int M, int N, int K) {
    extern __shared__ float sm[];
    float* AsB = sm;                       // [2][16][PADA]
    float* BsB = sm + 2 * 16 * PADA;       // [2][16][PADB]

    const int tid = threadIdx.x;
    const int wid = tid >> 5, lane = tid & 31;
    const int wm = wid & 3, wn = wid >> 2;       // 4 x 2 warps
    const int lr = lane >> 2, lc = lane & 3;
    const int m0 = blockIdx.y * 256, n0 = blockIdx.x * 128;

    const int rowA = tid >> 2;      // 0..63
    const int kq   = tid & 3;       // 0..3 (16-byte chunk within 16-wide k)
    const int swz  = kq << 3;

    const float* aP = A + (size_t)(m0 + rowA) * K + kq * 4;

    float acc[4][8][4];
#pragma unroll
    for (int mi = 0; mi < 4; mi++)
#pragma unroll
        for (int ni = 0; ni < 8; ni++)
#pragma unroll
            for (int r = 0; r < 4; r++) acc[mi][ni][r] = 0.0f;

    float4 pa[4], pb[2];

    auto LDG = [&](int kt) {
#pragma unroll
        for (int p = 0; p < 4; p++)
            pa[p] = *reinterpret_cast<const float4*>(aP + (size_t)(p * 64) * K + kt);
#pragma unroll
        for (int p = 0; p < 2; p++) {
            int n = n0 + rowA + p * 64;
            pb[p] = (n < N)
                ? *reinterpret_cast<const float4*>(W + (size_t)n * K + kq * 4 + kt)
                : make_float4(0.f, 0.f, 0.f, 0.f);
        }
    };
    auto STS = [&](int buf) {
        float* As = AsB + buf * 16 * PADA;
        float* Bs = BsB + buf * 16 * PADB;
#pragma unroll
        for (int p = 0; p < 4; p++) {
            int c = (rowA + p * 64) ^ swz;
            As[(kq * 4 + 0) * PADA + c] = u2f(tf32cvt(pa[p].x));
            As[(kq * 4 + 1) * PADA + c] = u2f(tf32cvt(pa[p].y));
            As[(kq * 4 + 2) * PADA + c] = u2f(tf32cvt(pa[p].z));
            As[(kq * 4 + 3) * PADA + c] = u2f(tf32cvt(pa[p].w));
        }
#pragma unroll
        for (int p = 0; p < 2; p++) {
            int c = (rowA + p * 64) ^ swz;
            Bs[(kq * 4 + 0) * PADB + c] = u2f(tf32cvt(pb[p].x));
            Bs[(kq * 4 + 1) * PADB + c] = u2f(tf32cvt(pb[p].y));
            Bs[(kq * 4 + 2) * PADB + c] = u2f(tf32cvt(pb[p].z));
            Bs[(kq * 4 + 3) * PADB + c] = u2f(tf32cvt(pb[p].w));
        }
    };
    auto COMP = [&](int buf) {
        const float* As = AsB + buf * 16 * PADA;
        const float* Bs = BsB + buf * 16 * PADB;
#pragma unroll
        for (int ks = 0; ks < 16; ks += 8) {
            const int k0 = ks + lc, k1 = ks + lc + 4;
            const int s0 = ((k0 >> 2) & 3) << 3;
            const int s1 = ((k1 >> 2) & 3) << 3;
            unsigned af[4][4], bf[8][2];
#pragma unroll
            for (int mi = 0; mi < 4; mi++) {
                int mb = wm * 64 + mi * 16 + lr;
                af[mi][0] = f2u(As[k0 * PADA + (mb ^ s0)]);
                af[mi][1] = f2u(As[k0 * PADA + ((mb + 8) ^ s0)]);
                af[mi][2] = f2u(As[k1 * PADA + (mb ^ s1)]);
                af[mi][3] = f2u(As[k1 * PADA + ((mb + 8) ^ s1)]);
            }
#pragma unroll
            for (int ni = 0; ni < 8; ni++) {
                int nb = wn * 64 + ni * 8 + lr;
                bf[ni][0] = f2u(Bs[k0 * PADB + (nb ^ s0)]);
                bf[ni][1] = f2u(Bs[k1 * PADB + (nb ^ s1)]);
            }
#pragma unroll
            for (int mi = 0; mi < 4; mi++)
#pragma unroll
                for (int ni = 0; ni < 8; ni++)
                    mma_tf32(acc[mi][ni][0], acc[mi][ni][1], acc[mi][ni][2], acc[mi][ni][3],
                             af[mi][0], af[mi][1], af[mi][2], af[mi][3],
                             bf[ni][0], bf[ni][1]);
        }
    };

    const int nt = K >> 4;
    LDG(0);
    STS(0);
    __syncthreads();
    for (int i = 0; i < nt; i++) {
        if (i + 1 < nt) LDG((i + 1) << 4);
        COMP(i & 1);
        if (i + 1 < nt) STS((i + 1) & 1);
        __syncthreads();
    }

#pragma unroll
    for (int mi = 0; mi < 4; mi++) {
        int m = m0 + wm * 64 + mi * 16 + lr;
#pragma unroll
        for (int ni = 0; ni < 8; ni++) {
            int n = n0 + wn * 64 + ni * 8 + lc * 2;
            if (n + 1 < N) {
                float b0 = bias[n], b1 = bias[n + 1];
                float2 v0 = make_float2(acc[mi][ni][0] + b0, acc[mi][ni][1] + b1);
                float2 v1 = make_float2(acc[mi][ni][2] + b0, acc[mi][ni][3] + b1);
                *reinterpret_cast<float2*>(C + (size_t)m * N + n) = v0;
                *reinterpret_cast<float2*>(C + (size_t)(m + 8) * N + n) = v1;
            } else if (n < N) {
                float b0 = bias[n];
                C[(size_t)m * N + n] = acc[mi][ni][0] + b0;
                C[(size_t)(m + 8) * N + n] = acc[mi][ni][2] + b0;
            }
        }
    }
}

// ===========================================================================
// gemm_lstm v2: fused single-step BiLSTM (i,g,o gates; f is dead at h0=c0=0)
// H[M,2000] = scale*act(X[M,512] @ Wg^T + bg) (+= H)
// gates gathered directly from original W layout [2, 4H, 512].
// block tile 128x64, BK=16, 8 warps (4m x 2n), warp tile 32x32 x 3 gates.
// ===========================================================================
#define PADLA 136   // 128 + 8
#define PADLB 72    // 64 + 8

__device__ __forceinline__ int gather_row(int n, int t) {
    // t: 0=i, 1=g, 2=o ; original row = d*4000 + {0,2000,3000}[t] + (n - d*1000)
    int d = (n >= 1000);
    int j = n - d * 1000;
    int toff = (t == 0) ? 0 : (t == 1 ? 2000 : 3000);
    return d * 4000 + toff + j;
}

__global__ __launch_bounds__(256, 1) void gemm_lstm(
    const float* __restrict__ X, const float* __restrict__ W,
    const float* __restrict__ b, float* __restrict__ C,
    int M, float scale, int accum) {
    const int N = 2000, K = 512;
    __shared__ float AsB[2][16][PADLA];
    __shared__ float BsB[2][3][16][PADLB];

    const int tid = threadIdx.x;
    const int wid = tid >> 5, lane = tid & 31;
    const int wm = wid & 3, wn = wid >> 2;
    const int lr = lane >> 2, lc = lane & 3;
    const int m0 = blockIdx.y * 128, n0 = blockIdx.x * 64;

    const int rowA = tid >> 2;   // 0..63
    const int kq   = tid & 3;
    const int swz  = kq << 3;

    const float* aP = X + (size_t)(m0 + rowA) * K + kq * 4;
    const int nB = n0 + rowA;
    int brow[3];
#pragma unroll
    for (int t = 0; t < 3; t++) brow[t] = (nB < N) ? gather_row(nB, t) : 0;
    const bool bok = (nB < N);

    float acc[3][2][4][4];
#pragma unroll
    for (int t = 0; t < 3; t++)
#pragma unroll
        for (int mi = 0; mi < 2; mi++)
#pragma unroll
            for (int ni = 0; ni < 4; ni++)
#pragma unroll
                for (int r = 0; r < 4; r++) acc[t][mi][ni][r] = 0.0f;

    float4 pa[2], pb[3];

    auto LDG = [&](int kt) {
#pragma unroll
        for (int p = 0; p < 2; p++)
            pa[p] = *reinterpret_cast<const float4*>(aP + (size_t)(p * 64) * K + kt);
#pragma unroll
        for (int t = 0; t < 3; t++)
            pb[t] = bok
                ? *reinterpret_cast<const float4*>(W + (size_t)brow[t] * K + kq * 4 + kt)
                : make_float4(0.f, 0.f, 0.f, 0.f);
    };
    auto STS = [&](int buf) {
#pragma unroll
        for (int p = 0; p < 2; p++) {
            int c = (rowA + p * 64) ^ swz;
            AsB[buf][kq * 4 + 0][c] = u2f(tf32cvt(pa[p].x));
            AsB[buf][kq * 4 + 1][c] = u2f(tf32cvt(pa[p].y));
            AsB[buf][kq * 4 + 2][c] = u2f(tf32cvt(pa[p].z));
            AsB[buf][kq * 4 + 3][c] = u2f(tf32cvt(pa[p].w));
        }
        int c = rowA ^ swz;
#pragma unroll
        for (int t = 0; t < 3; t++) {
            BsB[buf][t][kq * 4 + 0][c] = u2f(tf32cvt(pb[t].x));
            BsB[buf][t][kq * 4 + 1][c] = u2f(tf32cvt(pb[t].y));
            BsB[buf][t][kq * 4 + 2][c] = u2f(tf32cvt(pb[t].z));
            BsB[buf][t][kq * 4 + 3][c] = u2f(tf32cvt(pb[t].w));
        }
    };
    auto COMP = [&](int buf) {
#pragma unroll
        for (int ks = 0; ks < 16; ks += 8) {
            const int k0 = ks + lc, k1 = ks + lc + 4;
            const int s0 = ((k0 >> 2) & 3) << 3;
            const int s1 = ((k1 >> 2) & 3) << 3;
            unsigned af[2][4], bf[3][4][2];
#pragma unroll
            for (int mi = 0; mi < 2; mi++) {
                int mb = wm * 32 + mi * 16 + lr;
                af[mi][0] = f2u(AsB[buf][k0][mb ^ s0]);
                af[mi][1] = f2u(AsB[buf][k0][(mb + 8) ^ s0]);
                af[mi][2] = f2u(AsB[buf][k1][mb ^ s1]);
                af[mi][3] = f2u(AsB[buf][k1][(mb + 8) ^ s1]);
            }
#pragma unroll
            for (int t = 0; t < 3; t++)
#pragma unroll
                for (int ni = 0; ni < 4; ni++) {
                    int nb = wn * 32 + ni * 8 + lr;
                    bf[t][ni][0] = f2u(BsB[buf][t][k0][nb ^ s0]);
                    bf[t][ni][1] = f2u(BsB[buf][t][k1][nb ^ s1]);
                }
#pragma unroll
            for (int t = 0; t < 3; t++)
#pragma unroll
                for (int mi = 0; mi < 2; mi++)
#pragma unroll
                    for (int ni = 0; ni < 4; ni++)
                        mma_tf32(acc[t][mi][ni][0], acc[t][mi][ni][1],
                                 acc[t][mi][ni][2], acc[t][mi][ni][3],
                                 af[mi][0], af[mi][1], af[mi][2], af[mi][3],
                                 bf[t][ni][0], bf[t][ni][1]);
        }
    };

    const int nt = K >> 4;   // 32
    LDG(0);
    STS(0);
    __syncthreads();
    for (int i = 0; i < nt; i++) {
        if (i + 1 < nt) LDG((i + 1) << 4);
        COMP(i & 1);
        if (i + 1 < nt) STS((i + 1) & 1);
        __syncthreads();
    }

#pragma unroll
    for (int mi = 0; mi < 2; mi++)
#pragma unroll
        for (int ni = 0; ni < 4; ni++) {
            int mA = m0 + wm * 32 + mi * 16 + lr;
            int nA = n0 + wn * 32 + ni * 8 + lc * 2;
#pragma unroll
            for (int r = 0; r < 4; r++) {
                int mm = mA + ((r >= 2) ? 8 : 0);
                int nn = nA + (r & 1);
                if (nn < N) {
                    int d = (nn >= 1000);
                    int base = d * 4000 + (nn - d * 1000);
                    float gi = acc[0][mi][ni][r] + b[base];
                    float gg = acc[1][mi][ni][r] + b[base + 2000];
                    float go = acc[2][mi][ni][r] + b[base + 3000];
                    float cc = sigf(gi) * tanh_fast(gg);
                    float h = sigf(go) * tanh_fast(cc);
                    float o = scale * h;
                    if (accum) o += C[(size_t)mm * N + nn];
                    C[(size_t)mm * N + nn] = o;
                }
            }
        }
}

// ---------------- neighbor mean: [B,24,E] -> [B,E] --------------------------
__global__ void mean_kernel(const float* __restrict__ Z, float* __restrict__ out) {
    int idx = blockIdx.x * blockDim.x + threadIdx.x;
    if (idx >= BB * EE) return;
    int bI = idx / EE, n = idx % EE;
    float s = 0.f;
#pragma unroll 4
    for (int j = 0; j < 24; j++) s += Z[(size_t)(bI * 24 + j) * EE + n];
    out[idx] = s * (1.0f / 24.0f);
}

// ---------------- 3-way attention combine -----------------------------------
__global__ void attention_kernel(const float* __restrict__ c, const float* __restrict__ u,
                                 const float* __restrict__ p, const float* __restrict__ att,
                                 float* __restrict__ out) {
    int bI = blockIdx.x, tid = threadIdx.x;
    const float* cb = c + (size_t)bI * EE;
    const float* ub = u + (size_t)bI * EE;
    const float* pb = p + (size_t)bI * EE;
    float s0 = 0.f, s1 = 0.f, s2 = 0.f, s3 = 0.f;
    for (int n = tid; n < EE; n += 256) {
        float a0 = att[n], a1 = att[EE + n];
        float cv = cb[n];
        s0 += cv * a0;
        s1 += cv * a1;
        s2 += ub[n] * a1;
        s3 += pb[n] * a1;
    }
    __shared__ float red[4][256];
    red[0][tid] = s0; red[1][tid] = s1; red[2][tid] = s2; red[3][tid] = s3;
    __syncthreads();
    for (int s = 128; s > 0; s >>= 1) {
        if (tid < s) {
#pragma unroll
            for (int q = 0; q < 4; q++) red[q][tid] += red[q][tid + s];
        }
        __syncthreads();
    }
    __shared__ float w[3];
    if (tid == 0) {
        float sc[3];
        sc[0] = red[0][0] + red[1][0];
        sc[1] = red[0][0] + red[2][0];
        sc[2] = red[0][0] + red[3][0];
#pragma unroll
        for (int k = 0; k < 3; k++) sc[k] = sc[k] > 0.f ? sc[k] : 0.01f * sc[k];
        float mx = fmaxf(sc[0], fmaxf(sc[1], sc[2]));
        float e0 = __expf(sc[0] - mx), e1 = __expf(sc[1] - mx), e2 = __expf(sc[2] - mx);
        float inv = 1.0f / (e0 + e1 + e2);
        w[0] = e0 * inv; w[1] = e1 * inv; w[2] = e2 * inv;
    }
    __syncthreads();
    float w0 = w[0], w1 = w[1], w2 = w[2];
    for (int n = tid; n < EE; n += 256)
        out[(size_t)bI * EE + n] = w0 * cb[n] + w1 * ub[n] + w2 * pb[n];
}

// ---------------------------------------------------------------------------
extern "C" void kernel_launch(void* const* d_in, const int* in_sizes, int n_in,
                              void* d_out, int out_size) {
    const float* c_text  = (const float*)d_in[0];
    const float* c_image = (const float*)d_in[1];
    const float* p_text  = (const float*)d_in[2];
    const float* p_image = (const float*)d_in[3];
    const float* u_text  = (const float*)d_in[4];
    const float* u_other = (const float*)d_in[5];
    const float* W_lt = (const float*)d_in[6],  *b_lt = (const float*)d_in[7];
    const float* W_li = (const float*)d_in[8],  *b_li = (const float*)d_in[9];
    const float* W_lo = (const float*)d_in[10], *b_lo = (const float*)d_in[11];
    const float* lstm_t_W = (const float*)d_in[12], *lstm_t_b = (const float*)d_in[13];
    const float* lstm_i_W = (const float*)d_in[14], *lstm_i_b = (const float*)d_in[15];
    const float* lstm_o_W = (const float*)d_in[16], *lstm_o_b = (const float*)d_in[17];
    const float* ua_lin_W = (const float*)d_in[18], *ua_lin_b = (const float*)d_in[19];
    const float* ua_lstm_W = (const float*)d_in[20], *ua_lstm_b = (const float*)d_in[21];
    const float* ua_out_W = (const float*)d_in[22], *ua_out_b = (const float*)d_in[23];
    const float* pa_lin_W = (const float*)d_in[24], *pa_lin_b = (const float*)d_in[25];
    const float* pa_lstm_W = (const float*)d_in[26], *pa_lstm_b = (const float*)d_in[27];
    const float* pa_out_W = (const float*)d_in[28], *pa_out_b = (const float*)d_in[29];
    const float* p_att = (const float*)d_in[30];
    float* out = (float*)d_out;

    float *bufX, *Hc, *Hp, *Hu, *H2, *Z, *uagg, *pagg;
    cudaGetSymbolAddress((void**)&bufX, g_bufX);
    cudaGetSymbolAddress((void**)&Hc,   g_Hc);
    cudaGetSymbolAddress((void**)&Hp,   g_Hp);
    cudaGetSymbolAddress((void**)&Hu,   g_Hu);
    cudaGetSymbolAddress((void**)&H2,   g_H2);
    cudaGetSymbolAddress((void**)&Z,    g_Z);
    cudaGetSymbolAddress((void**)&uagg, g_uagg);
    cudaGetSymbolAddress((void**)&pagg, g_pagg);

    cudaFuncSetAttribute(gemm_lin, cudaFuncAttributeMaxDynamicSharedMemorySize, SMEM_LIN);

    auto L1 = [&](const float* A, const float* W, const float* b, float* C,
                  int M, int N, int K) {
        dim3 g((N + 127) / 128, M / 256);
        gemm_lin<<<g, 256, SMEM_LIN>>>(A, W, b, C, M, N, K);
    };
    auto L2 = [&](const float* X, const float* W, const float* b, float* C,
                  int M, float scale, int accum) {
        dim3 g((2000 + 63) / 64, M / 128);
        gemm_lstm<<<g, 256>>>(X, W, b, C, M, scale, accum);
    };

    // ---- per-type input linear + BiLSTM ----
    L1(c_text,  W_lt, b_lt, bufX, BB, 512, 768);    L2(bufX, lstm_t_W, lstm_t_b, Hc, BB, 0.5f, 0);
    L1(c_image, W_li, b_li, bufX, BB, 512, 2048);   L2(bufX, lstm_i_W, lstm_i_b, Hc, BB, 0.5f, 1);
    L1(p_text,  W_lt, b_lt, bufX, MPU, 512, 768);   L2(bufX, lstm_t_W, lstm_t_b, Hp, MPU, 0.5f, 0);
    L1(p_image, W_li, b_li, bufX, MPU, 512, 2048);  L2(bufX, lstm_i_W, lstm_i_b, Hp, MPU, 0.5f, 1);
    L1(u_text,  W_lt, b_lt, bufX, MPU, 512, 768);   L2(bufX, lstm_t_W, lstm_t_b, Hu, MPU, 0.5f, 0);
    L1(u_other, W_lo, b_lo, bufX, MPU, 512, 512);   L2(bufX, lstm_o_W, lstm_o_b, Hu, MPU, 0.5f, 1);

    // ---- user aggregation ----
    L1(Hu, ua_lin_W, ua_lin_b, bufX, MPU, 512, 2000);
    L2(bufX, ua_lstm_W, ua_lstm_b, H2, MPU, 1.0f, 0);
    L1(H2, ua_out_W, ua_out_b, Z, MPU, 2000, 2000);
    mean_kernel<<<(BB * EE + 255) / 256, 256>>>(Z, uagg);

    // ---- post aggregation ----
    L1(Hp, pa_lin_W, pa_lin_b, bufX, MPU, 512, 2000);
    L2(bufX, pa_lstm_W, pa_lstm_b, H2, MPU, 1.0f, 0);
    L1(H2, pa_out_W, pa_out_b, Z, MPU, 2000, 2000);
    mean_kernel<<<(BB * EE + 255) / 256, 256>>>(Z, pagg);

    // ---- attention combine ----
    attention_kernel<<<BB, 256>>>(Hc, uagg, pagg, p_att, out);
}

// round 4
// speedup vs baseline: 2.0458x; 1.2643x over previous
#include <cuda_runtime.h>
#include <cstdint>

// ---------------------------------------------------------------------------
// Het_GNN forward — mma.sync tf32 (legacy tensor path; harness builds sm_103
// without the 'a' suffix, so tcgen05 is unavailable).
// ---------------------------------------------------------------------------
#define BB   512
#define MPU  12288
#define EE   2000
#define INI  512

// ---------------- scratch (device globals; no allocation allowed) ----------
__device__ float g_bufX[MPU * INI];
__device__ float g_Hc  [BB  * EE];
__device__ float g_Hp  [MPU * EE];
__device__ float g_Hu  [MPU * EE];
__device__ float g_H2  [MPU * EE];
__device__ float g_Hm  [BB  * EE];     // neighbor-mean of H2
__device__ float g_uagg[BB * EE];
__device__ float g_pagg[BB * EE];

// ---------------- helpers ---------------------------------------------------
__device__ __forceinline__ unsigned tf32cvt(float x) {
    unsigned r;
    asm("cvt.rna.tf32.f32 %0, %1;" : "=r"(r) : "f"(x));
    return r;
}
__device__ __forceinline__ float u2f(unsigned x) { return __uint_as_float(x); }
__device__ __forceinline__ unsigned f2u(float x) { return __float_as_uint(x); }

__device__ __forceinline__ void mma_tf32(float& d0, float& d1, float& d2, float& d3,
                                         unsigned a0, unsigned a1, unsigned a2, unsigned a3,
                                         unsigned b0, unsigned b1) {
    asm volatile(
        "mma.sync.aligned.m16n8k8.row.col.f32.tf32.tf32.f32 "
        "{%0,%1,%2,%3}, {%4,%5,%6,%7}, {%8,%9}, {%0,%1,%2,%3};"
        : "+f"(d0), "+f"(d1), "+f"(d2), "+f"(d3)
        : "r"(a0), "r"(a1), "r"(a2), "r"(a3), "r"(b0), "r"(b1));
}

__device__ __forceinline__ float sigf(float x) { return 1.0f / (1.0f + __expf(-x)); }
__device__ __forceinline__ float tanh_fast(float x) {
    return 2.0f / (1.0f + __expf(-2.0f * x)) - 1.0f;
}

// ===========================================================================
// gemm_lin v3: C[M,N] = A[M,K] @ W[N,K]^T + bias
// block 256x128, BK=16, 512 threads (16 warps 4m x 4n), warp tile 64x32.
// double-buffered smem + register prefetch; XOR swizzle col = r ^ (((k>>2)&3)<<3)
// ===========================================================================
#define PADA 264
#define PADB 136
#define SMEM_LIN ((2*16*PADA + 2*16*PADB) * 4)

__global__ __launch_bounds__(512, 1) void gemm_lin(
    const float* __restrict__ A, const float* __restrict__ W,
    const float* __restrict__ bias, float* __restrict__ C,
    int M, int N, int K) {
    extern __shared__ float sm[];
    float* AsB = sm;                       // [2][16][PADA]
    float* BsB = sm + 2 * 16 * PADA;       // [2][16][PADB]

    const int tid = threadIdx.x;
    const int wid = tid >> 5, lane = tid & 31;
    const int wm = wid & 3, wn = wid >> 2;       // 4 x 4 warps
    const int lr = lane >> 2, lc = lane & 3;
    const int m0 = blockIdx.y * 256, n0 = blockIdx.x * 128;

    const int rowA = tid >> 2;      // 0..127
    const int kq   = tid & 3;
    const int swz  = kq << 3;

    const float* aP = A + (size_t)(m0 + rowA) * K + kq * 4;
    const int nB = n0 + rowA;
    const bool bok = (nB < N);
    const float* bP = W + (size_t)(bok ? nB : 0) * K + kq * 4;

    float acc[4][4][4];
#pragma unroll
    for (int mi = 0; mi < 4; mi++)
#pragma unroll
        for (int ni = 0; ni < 4; ni++)
#pragma unroll
            for (int r = 0; r < 4; r++) acc[mi][ni][r] = 0.0f;

    float4 pa[2], pb;

    auto LDG = [&](int kt) {
        pa[0] = *reinterpret_cast<const float4*>(aP + kt);
        pa[1] = *reinterpret_cast<const float4*>(aP + (size_t)128 * K + kt);
        pb = bok ? *reinterpret_cast<const float4*>(bP + kt)
                 : make_float4(0.f, 0.f, 0.f, 0.f);
    };
    auto STS = [&](int buf) {
        float* As = AsB + buf * 16 * PADA;
        float* Bs = BsB + buf * 16 * PADB;
#pragma unroll
        for (int p = 0; p < 2; p++) {
            int c = (rowA + p * 128) ^ swz;
            As[(kq * 4 + 0) * PADA + c] = u2f(tf32cvt(pa[p].x));
            As[(kq * 4 + 1) * PADA + c] = u2f(tf32cvt(pa[p].y));
            As[(kq * 4 + 2) * PADA + c] = u2f(tf32cvt(pa[p].z));
            As[(kq * 4 + 3) * PADA + c] = u2f(tf32cvt(pa[p].w));
        }
        {
            int c = rowA ^ swz;
            Bs[(kq * 4 + 0) * PADB + c] = u2f(tf32cvt(pb.x));
            Bs[(kq * 4 + 1) * PADB + c] = u2f(tf32cvt(pb.y));
            Bs[(kq * 4 + 2) * PADB + c] = u2f(tf32cvt(pb.z));
            Bs[(kq * 4 + 3) * PADB + c] = u2f(tf32cvt(pb.w));
        }
    };
    auto COMP = [&](int buf) {
        const float* As = AsB + buf * 16 * PADA;
        const float* Bs = BsB + buf * 16 * PADB;
#pragma unroll
        for (int ks = 0; ks < 16; ks += 8) {
            const int k0 = ks + lc, k1 = ks + lc + 4;
            const int s0 = ((k0 >> 2) & 3) << 3;
            const int s1 = ((k1 >> 2) & 3) << 3;
            unsigned af[4][4], bf[4][2];
#pragma unroll
            for (int mi = 0; mi < 4; mi++) {
                int mb = wm * 64 + mi * 16 + lr;
                af[mi][0] = f2u(As[k0 * PADA + (mb ^ s0)]);
                af[mi][1] = f2u(As[k0 * PADA + ((mb + 8) ^ s0)]);
                af[mi][2] = f2u(As[k1 * PADA + (mb ^ s1)]);
                af[mi][3] = f2u(As[k1 * PADA + ((mb + 8) ^ s1)]);
            }
#pragma unroll
            for (int ni = 0; ni < 4; ni++) {
                int nb = wn * 32 + ni * 8 + lr;
                bf[ni][0] = f2u(Bs[k0 * PADB + (nb ^ s0)]);
                bf[ni][1] = f2u(Bs[k1 * PADB + (nb ^ s1)]);
            }
#pragma unroll
            for (int mi = 0; mi < 4; mi++)
#pragma unroll
                for (int ni = 0; ni < 4; ni++)
                    mma_tf32(acc[mi][ni][0], acc[mi][ni][1], acc[mi][ni][2], acc[mi][ni][3],
                             af[mi][0], af[mi][1], af[mi][2], af[mi][3],
                             bf[ni][0], bf[ni][1]);
        }
    };

    const int nt = K >> 4;
    LDG(0);
    STS(0);
    __syncthreads();
    for (int i = 0; i < nt; i++) {
        if (i + 1 < nt) LDG((i + 1) << 4);
        COMP(i & 1);
        if (i + 1 < nt) STS((i + 1) & 1);
        __syncthreads();
    }

#pragma unroll
    for (int mi = 0; mi < 4; mi++) {
        int m = m0 + wm * 64 + mi * 16 + lr;
#pragma unroll
        for (int ni = 0; ni < 4; ni++) {
            int n = n0 + wn * 32 + ni * 8 + lc * 2;
            if (n + 1 < N) {
                float b0 = bias[n], b1 = bias[n + 1];
                float2 v0 = make_float2(acc[mi][ni][0] + b0, acc[mi][ni][1] + b1);
                float2 v1 = make_float2(acc[mi][ni][2] + b0, acc[mi][ni][3] + b1);
                *reinterpret_cast<float2*>(C + (size_t)m * N + n) = v0;
                *reinterpret_cast<float2*>(C + (size_t)(m + 8) * N + n) = v1;
            } else if (n < N) {
                float b0 = bias[n];
                C[(size_t)m * N + n] = acc[mi][ni][0] + b0;
                C[(size_t)(m + 8) * N + n] = acc[mi][ni][2] + b0;
            }
        }
    }
}

// ===========================================================================
// gemm_lstm v3: fused single-step BiLSTM (i,g,o; f dead at h0=c0=0)
// H[M,2000] = scale*act(X[M,512] @ Wg^T + bg) (+= H)
// block 128x64x3gates, BK=32, 512 threads (16 warps 4m x 4n), warp 32x16x3.
// ===========================================================================
#define PADLA 136
#define PADLB 72
#define SMEM_LSTM ((2*32*PADLA + 2*3*32*PADLB) * 4)   // 90112 B

__device__ __forceinline__ int gather_row(int n, int t) {
    int d = (n >= 1000);
    int j = n - d * 1000;
    int toff = (t == 0) ? 0 : (t == 1 ? 2000 : 3000);
    return d * 4000 + toff + j;
}

__global__ __launch_bounds__(512, 1) void gemm_lstm(
    const float* __restrict__ X, const float* __restrict__ W,
    const float* __restrict__ b, float* __restrict__ C,
    int M, float scale, int accum) {
    const int N = 2000, K = 512;
    extern __shared__ float sm[];
    float* AsB = sm;                        // [2][32][PADLA]
    float* BsB = sm + 2 * 32 * PADLA;       // [2][3][32][PADLB]

    const int tid = threadIdx.x;
    const int wid = tid >> 5, lane = tid & 31;
    const int wm = wid & 3, wn = wid >> 2;      // 4 x 4
    const int lr = lane >> 2, lc = lane & 3;
    const int m0 = blockIdx.y * 128, n0 = blockIdx.x * 64;

    const int rowA = tid >> 3;   // 0..63
    const int kq   = tid & 7;    // 0..7
    const int swz  = (kq & 3) << 3;

    const float* aP = X + (size_t)(m0 + rowA) * K + kq * 4;
    const int nB = n0 + rowA;
    const bool bok = (nB < N);
    const float* bP[3];
#pragma unroll
    for (int t = 0; t < 3; t++)
        bP[t] = W + (size_t)(bok ? gather_row(nB, t) : 0) * K + kq * 4;

    float acc[3][2][2][4];
#pragma unroll
    for (int t = 0; t < 3; t++)
#pragma unroll
        for (int mi = 0; mi < 2; mi++)
#pragma unroll
            for (int ni = 0; ni < 2; ni++)
#pragma unroll
                for (int r = 0; r < 4; r++) acc[t][mi][ni][r] = 0.0f;

    float4 pa[2], pb[3];

    auto LDG = [&](int kt) {
        pa[0] = *reinterpret_cast<const float4*>(aP + kt);
        pa[1] = *reinterpret_cast<const float4*>(aP + (size_t)64 * K + kt);
#pragma unroll
        for (int t = 0; t < 3; t++)
            pb[t] = bok ? *reinterpret_cast<const float4*>(bP[t] + kt)
                        : make_float4(0.f, 0.f, 0.f, 0.f);
    };
    auto STS = [&](int buf) {
        float* As = AsB + buf * 32 * PADLA;
#pragma unroll
        for (int p = 0; p < 2; p++) {
            int c = (rowA + p * 64) ^ swz;
            As[(kq * 4 + 0) * PADLA + c] = u2f(tf32cvt(pa[p].x));
            As[(kq * 4 + 1) * PADLA + c] = u2f(tf32cvt(pa[p].y));
            As[(kq * 4 + 2) * PADLA + c] = u2f(tf32cvt(pa[p].z));
            As[(kq * 4 + 3) * PADLA + c] = u2f(tf32cvt(pa[p].w));
        }
        int c = rowA ^ swz;
#pragma unroll
        for (int t = 0; t < 3; t++) {
            float* Bs = BsB + (buf * 3 + t) * 32 * PADLB;
            Bs[(kq * 4 + 0) * PADLB + c] = u2f(tf32cvt(pb[t].x));
            Bs[(kq * 4 + 1) * PADLB + c] = u2f(tf32cvt(pb[t].y));
            Bs[(kq * 4 + 2) * PADLB + c] = u2f(tf32cvt(pb[t].z));
            Bs[(kq * 4 + 3) * PADLB + c] = u2f(tf32cvt(pb[t].w));
        }
    };
    auto COMP = [&](int buf) {
        const float* As = AsB + buf * 32 * PADLA;
#pragma unroll
        for (int ks = 0; ks < 32; ks += 8) {
            const int k0 = ks + lc, k1 = ks + lc + 4;
            const int s0 = ((k0 >> 2) & 3) << 3;
            const int s1 = ((k1 >> 2) & 3) << 3;
            unsigned af[2][4], bf[3][2][2];
#pragma unroll
            for (int mi = 0; mi < 2; mi++) {
                int mb = wm * 32 + mi * 16 + lr;
                af[mi][0] = f2u(As[k0 * PADLA + (mb ^ s0)]);
                af[mi][1] = f2u(As[k0 * PADLA + ((mb + 8) ^ s0)]);
                af[mi][2] = f2u(As[k1 * PADLA + (mb ^ s1)]);
                af[mi][3] = f2u(As[k1 * PADLA + ((mb + 8) ^ s1)]);
            }
#pragma unroll
            for (int t = 0; t < 3; t++) {
                const float* Bs = BsB + (buf * 3 + t) * 32 * PADLB;
#pragma unroll
                for (int ni = 0; ni < 2; ni++) {
                    int nb = wn * 16 + ni * 8 + lr;
                    bf[t][ni][0] = f2u(Bs[k0 * PADLB + (nb ^ s0)]);
                    bf[t][ni][1] = f2u(Bs[k1 * PADLB + (nb ^ s1)]);
                }
            }
#pragma unroll
            for (int t = 0; t < 3; t++)
#pragma unroll
                for (int mi = 0; mi < 2; mi++)
#pragma unroll
                    for (int ni = 0; ni < 2; ni++)
                        mma_tf32(acc[t][mi][ni][0], acc[t][mi][ni][1],
                                 acc[t][mi][ni][2], acc[t][mi][ni][3],
                                 af[mi][0], af[mi][1], af[mi][2], af[mi][3],
                                 bf[t][ni][0], bf[t][ni][1]);
        }
    };

    const int nt = K >> 5;   // 16
    LDG(0);
    STS(0);
    __syncthreads();
    for (int i = 0; i < nt; i++) {
        if (i + 1 < nt) LDG((i + 1) << 5);
        COMP(i & 1);
        if (i + 1 < nt) STS((i + 1) & 1);
        __syncthreads();
    }

#pragma unroll
    for (int mi = 0; mi < 2; mi++)
#pragma unroll
        for (int ni = 0; ni < 2; ni++) {
            int mA = m0 + wm * 32 + mi * 16 + lr;
            int nA = n0 + wn * 16 + ni * 8 + lc * 2;
#pragma unroll
            for (int r = 0; r < 4; r++) {
                int mm = mA + ((r >= 2) ? 8 : 0);
                int nn = nA + (r & 1);
                if (nn < N) {
                    int d = (nn >= 1000);
                    int base = d * 4000 + (nn - d * 1000);
                    float gi = acc[0][mi][ni][r] + b[base];
                    float gg = acc[1][mi][ni][r] + b[base + 2000];
                    float go = acc[2][mi][ni][r] + b[base + 3000];
                    float cc = sigf(gi) * tanh_fast(gg);
                    float h = sigf(go) * tanh_fast(cc);
                    float o = scale * h;
                    if (accum) o += C[(size_t)mm * N + nn];
                    C[(size_t)mm * N + nn] = o;
                }
            }
        }
}

// ---------------- neighbor mean: [B,24,E] -> [B,E] --------------------------
__global__ void mean_kernel(const float* __restrict__ Z, float* __restrict__ out) {
    int idx = blockIdx.x * blockDim.x + threadIdx.x;
    if (idx >= BB * EE) return;
    int bI = idx / EE, n = idx % EE;
    float s = 0.f;
#pragma unroll 4
    for (int j = 0; j < 24; j++) s += Z[(size_t)(bI * 24 + j) * EE + n];
    out[idx] = s * (1.0f / 24.0f);
}

// ---------------- 3-way attention combine -----------------------------------
__global__ void attention_kernel(const float* __restrict__ c, const float* __restrict__ u,
                                 const float* __restrict__ p, const float* __restrict__ att,
                                 float* __restrict__ out) {
    int bI = blockIdx.x, tid = threadIdx.x;
    const float* cb = c + (size_t)bI * EE;
    const float* ub = u + (size_t)bI * EE;
    const float* pb = p + (size_t)bI * EE;
    float s0 = 0.f, s1 = 0.f, s2 = 0.f, s3 = 0.f;
    for (int n = tid; n < EE; n += 256) {
        float a0 = att[n], a1 = att[EE + n];
        float cv = cb[n];
        s0 += cv * a0;
        s1 += cv * a1;
        s2 += ub[n] * a1;
        s3 += pb[n] * a1;
    }
    __shared__ float red[4][256];
    red[0][tid] = s0; red[1][tid] = s1; red[2][tid] = s2; red[3][tid] = s3;
    __syncthreads();
    for (int s = 128; s > 0; s >>= 1) {
        if (tid < s) {
#pragma unroll
            for (int q = 0; q < 4; q++) red[q][tid] += red[q][tid + s];
        }
        __syncthreads();
    }
    __shared__ float w[3];
    if (tid == 0) {
        float sc[3];
        sc[0] = red[0][0] + red[1][0];
        sc[1] = red[0][0] + red[2][0];
        sc[2] = red[0][0] + red[3][0];
#pragma unroll
        for (int k = 0; k < 3; k++) sc[k] = sc[k] > 0.f ? sc[k] : 0.01f * sc[k];
        float mx = fmaxf(sc[0], fmaxf(sc[1], sc[2]));
        float e0 = __expf(sc[0] - mx), e1 = __expf(sc[1] - mx), e2 = __expf(sc[2] - mx);
        float inv = 1.0f / (e0 + e1 + e2);
        w[0] = e0 * inv; w[1] = e1 * inv; w[2] = e2 * inv;
    }
    __syncthreads();
    float w0 = w[0], w1 = w[1], w2 = w[2];
    for (int n = tid; n < EE; n += 256)
        out[(size_t)bI * EE + n] = w0 * cb[n] + w1 * ub[n] + w2 * pb[n];
}

// ---------------------------------------------------------------------------
extern "C" void kernel_launch(void* const* d_in, const int* in_sizes, int n_in,
                              void* d_out, int out_size) {
    const float* c_text  = (const float*)d_in[0];
    const float* c_image = (const float*)d_in[1];
    const float* p_text  = (const float*)d_in[2];
    const float* p_image = (const float*)d_in[3];
    const float* u_text  = (const float*)d_in[4];
    const float* u_other = (const float*)d_in[5];
    const float* W_lt = (const float*)d_in[6],  *b_lt = (const float*)d_in[7];
    const float* W_li = (const float*)d_in[8],  *b_li = (const float*)d_in[9];
    const float* W_lo = (const float*)d_in[10], *b_lo = (const float*)d_in[11];
    const float* lstm_t_W = (const float*)d_in[12], *lstm_t_b = (const float*)d_in[13];
    const float* lstm_i_W = (const float*)d_in[14], *lstm_i_b = (const float*)d_in[15];
    const float* lstm_o_W = (const float*)d_in[16], *lstm_o_b = (const float*)d_in[17];
    const float* ua_lin_W = (const float*)d_in[18], *ua_lin_b = (const float*)d_in[19];
    const float* ua_lstm_W = (const float*)d_in[20], *ua_lstm_b = (const float*)d_in[21];
    const float* ua_out_W = (const float*)d_in[22], *ua_out_b = (const float*)d_in[23];
    const float* pa_lin_W = (const float*)d_in[24], *pa_lin_b = (const float*)d_in[25];
    const float* pa_lstm_W = (const float*)d_in[26], *pa_lstm_b = (const float*)d_in[27];
    const float* pa_out_W = (const float*)d_in[28], *pa_out_b = (const float*)d_in[29];
    const float* p_att = (const float*)d_in[30];
    float* out = (float*)d_out;

    float *bufX, *Hc, *Hp, *Hu, *H2, *Hm, *uagg, *pagg;
    cudaGetSymbolAddress((void**)&bufX, g_bufX);
    cudaGetSymbolAddress((void**)&Hc,   g_Hc);
    cudaGetSymbolAddress((void**)&Hp,   g_Hp);
    cudaGetSymbolAddress((void**)&Hu,   g_Hu);
    cudaGetSymbolAddress((void**)&H2,   g_H2);
    cudaGetSymbolAddress((void**)&Hm,   g_Hm);
    cudaGetSymbolAddress((void**)&uagg, g_uagg);
    cudaGetSymbolAddress((void**)&pagg, g_pagg);

    cudaFuncSetAttribute(gemm_lin,  cudaFuncAttributeMaxDynamicSharedMemorySize, SMEM_LIN);
    cudaFuncSetAttribute(gemm_lstm, cudaFuncAttributeMaxDynamicSharedMemorySize, SMEM_LSTM);

    auto L1 = [&](const float* A, const float* W, const float* b, float* C,
                  int M, int N, int K) {
        dim3 g((N + 127) / 128, M / 256);
        gemm_lin<<<g, 512, SMEM_LIN>>>(A, W, b, C, M, N, K);
    };
    auto L2 = [&](const float* X, const float* W, const float* b, float* C,
                  int M, float scale, int accum) {
        dim3 g((EE + 63) / 64, M / 128);
        gemm_lstm<<<g, 512, SMEM_LSTM>>>(X, W, b, C, M, scale, accum);
    };

    // ---- per-type input linear + BiLSTM ----
    L1(c_text,  W_lt, b_lt, bufX, BB, 512, 768);    L2(bufX, lstm_t_W, lstm_t_b, Hc, BB, 0.5f, 0);
    L1(c_image, W_li, b_li, bufX, BB, 512, 2048);   L2(bufX, lstm_i_W, lstm_i_b, Hc, BB, 0.5f, 1);
    L1(p_text,  W_lt, b_lt, bufX, MPU, 512, 768);   L2(bufX, lstm_t_W, lstm_t_b, Hp, MPU, 0.5f, 0);
    L1(p_image, W_li, b_li, bufX, MPU, 512, 2048);  L2(bufX, lstm_i_W, lstm_i_b, Hp, MPU, 0.5f, 1);
    L1(u_text,  W_lt, b_lt, bufX, MPU, 512, 768);   L2(bufX, lstm_t_W, lstm_t_b, Hu, MPU, 0.5f, 0);
    L1(u_other, W_lo, b_lo, bufX, MPU, 512, 512);   L2(bufX, lstm_o_W, lstm_o_b, Hu, MPU, 0.5f, 1);

    // ---- user aggregation (mean commuted before the out-linear) ----
    L1(Hu, ua_lin_W, ua_lin_b, bufX, MPU, 512, 2000);
    L2(bufX, ua_lstm_W, ua_lstm_b, H2, MPU, 1.0f, 0);
    mean_kernel<<<(BB * EE + 255) / 256, 256>>>(H2, Hm);
    L1(Hm, ua_out_W, ua_out_b, uagg, BB, 2000, 2000);

    // ---- post aggregation ----
    L1(Hp, pa_lin_W, pa_lin_b, bufX, MPU, 512, 2000);
    L2(bufX, pa_lstm_W, pa_lstm_b, H2, MPU, 1.0f, 0);
    mean_kernel<<<(BB * EE + 255) / 256, 256>>>(H2, Hm);
    L1(Hm, pa_out_W, pa_out_b, pagg, BB, 2000, 2000);

    // ---- attention combine ----
    attention_kernel<<<BB, 256>>>(Hc, uagg, pagg, p_att, out);
}

// round 5
// speedup vs baseline: 3.2327x; 1.5802x over previous
#include <cuda_runtime.h>
#include <cuda_fp16.h>
#include <cstdint>

// ---------------------------------------------------------------------------
// Het_GNN forward — fp16-operand mma.sync (f32 accumulate), sm_103 baseline.
// ---------------------------------------------------------------------------
#define BB   512
#define MPU  12288
#define EE   2000
#define INI  512

// ---------------- scratch (device globals; no allocation allowed) ----------
__device__ float g_bufX[MPU * INI];
__device__ float g_Hc  [BB  * EE];
__device__ float g_Hp  [MPU * EE];
__device__ float g_Hu  [MPU * EE];
__device__ float g_H2  [MPU * EE];
__device__ float g_Hm  [BB  * EE];
__device__ float g_uagg[BB * EE];
__device__ float g_pagg[BB * EE];

// ---------------- helpers ---------------------------------------------------
__device__ __forceinline__ unsigned f16x2(float hi, float lo) {
    unsigned r;
    asm("cvt.rn.f16x2.f32 %0, %1, %2;" : "=r"(r) : "f"(hi), "f"(lo));
    return r;
}
__device__ __forceinline__ void mma_f16(float& d0, float& d1, float& d2, float& d3,
                                        unsigned a0, unsigned a1, unsigned a2, unsigned a3,
                                        unsigned b0, unsigned b1) {
    asm volatile(
        "mma.sync.aligned.m16n8k16.row.col.f32.f16.f16.f32 "
        "{%0,%1,%2,%3}, {%4,%5,%6,%7}, {%8,%9}, {%0,%1,%2,%3};"
        : "+f"(d0), "+f"(d1), "+f"(d2), "+f"(d3)
        : "r"(a0), "r"(a1), "r"(a2), "r"(a3), "r"(b0), "r"(b1));
}
__device__ __forceinline__ float sigf(float x) { return 1.0f / (1.0f + __expf(-x)); }
__device__ __forceinline__ float tanh_fast(float x) {
    return 2.0f / (1.0f + __expf(-2.0f * x)) - 1.0f;
}

// Swizzled fp16 tile rows: 32 halves (64B) per row, four 16B chunks.
// Chunk c of row m stored at position c ^ ((m>>1)&3). Conflict-free for both
// the STS.64 producer pattern and the half2 fragment LDS pattern.
__device__ __forceinline__ void sts_row(char* base, int m, int q, float4 v) {
    int pos = (q >> 1) ^ ((m >> 1) & 3);
    *(uint2*)(base + m * 64 + pos * 16 + (q & 1) * 8) =
        make_uint2(f16x2(v.y, v.x), f16x2(v.w, v.z));
}

// ===========================================================================
// gemm_lin: C[M,N] = A[M,K] @ W[N,K]^T + bias
// block 256x128, BK=32 (fp16), 512 threads (16 warps 4m x 4n), warp 64x32.
// ===========================================================================
__global__ __launch_bounds__(512, 1) void gemm_lin(
    const float* __restrict__ A, const float* __restrict__ W,
    const float* __restrict__ bias, float* __restrict__ C,
    int M, int N, int K) {
    __shared__ __align__(16) char AsB[2][256 * 64];   // 32KB
    __shared__ __align__(16) char BsB[2][128 * 64];   // 16KB

    const int tid = threadIdx.x;
    const int wid = tid >> 5, lane = tid & 31;
    const int wm = wid & 3, wn = wid >> 2;
    const int lr = lane >> 2, lc = lane & 3;
    const int lc4 = lc * 4;
    const int sw = (lr >> 1) & 3;
    const int m0 = blockIdx.y * 256, n0 = blockIdx.x * 128;

    const int rowA = tid >> 3;      // 0..63
    const int kq   = tid & 7;       // 0..7

    const float* aP[4];
#pragma unroll
    for (int p = 0; p < 4; p++)
        aP[p] = A + (size_t)(m0 + rowA + 64 * p) * K + kq * 4;
    const float* bP[2];
    bool bok[2];
#pragma unroll
    for (int p = 0; p < 2; p++) {
        int n = n0 + rowA + 64 * p;
        bok[p] = (n < N);
        bP[p] = W + (size_t)(bok[p] ? n : 0) * K + kq * 4;
    }

    float acc[4][4][4];
#pragma unroll
    for (int mi = 0; mi < 4; mi++)
#pragma unroll
        for (int ni = 0; ni < 4; ni++)
#pragma unroll
            for (int r = 0; r < 4; r++) acc[mi][ni][r] = 0.0f;

    float4 pa[4], pb[2];

    auto LDG = [&](int kt) {
        const bool kok = (kt + kq * 4) < K;
#pragma unroll
        for (int p = 0; p < 4; p++)
            pa[p] = kok ? *(const float4*)(aP[p] + kt) : make_float4(0.f, 0.f, 0.f, 0.f);
#pragma unroll
        for (int p = 0; p < 2; p++)
            pb[p] = (kok && bok[p]) ? *(const float4*)(bP[p] + kt)
                                    : make_float4(0.f, 0.f, 0.f, 0.f);
    };
    auto STS = [&](int buf) {
        char* As = AsB[buf];
        char* Bs = BsB[buf];
#pragma unroll
        for (int p = 0; p < 4; p++) sts_row(As, rowA + 64 * p, kq, pa[p]);
#pragma unroll
        for (int p = 0; p < 2; p++) sts_row(Bs, rowA + 64 * p, kq, pb[p]);
    };
    auto COMP = [&](int buf) {
        const char* As = AsB[buf];
        const char* Bs = BsB[buf];
#pragma unroll
        for (int ks = 0; ks < 32; ks += 16) {
            const int p0 = ((ks >> 3) ^ sw) * 16;
            const int p1 = (((ks >> 3) + 1) ^ sw) * 16;
            unsigned af[4][4], bf[4][2];
#pragma unroll
            for (int mi = 0; mi < 4; mi++) {
                const char* ra = As + (wm * 64 + mi * 16 + lr) * 64;
                af[mi][0] = *(const unsigned*)(ra + p0 + lc4);
                af[mi][1] = *(const unsigned*)(ra + 512 + p0 + lc4);
                af[mi][2] = *(const unsigned*)(ra + p1 + lc4);
                af[mi][3] = *(const unsigned*)(ra + 512 + p1 + lc4);
            }
#pragma unroll
            for (int ni = 0; ni < 4; ni++) {
                const char* rb = Bs + (wn * 32 + ni * 8 + lr) * 64;
                bf[ni][0] = *(const unsigned*)(rb + p0 + lc4);
                bf[ni][1] = *(const unsigned*)(rb + p1 + lc4);
            }
#pragma unroll
            for (int mi = 0; mi < 4; mi++)
#pragma unroll
                for (int ni = 0; ni < 4; ni++)
                    mma_f16(acc[mi][ni][0], acc[mi][ni][1], acc[mi][ni][2], acc[mi][ni][3],
                            af[mi][0], af[mi][1], af[mi][2], af[mi][3],
                            bf[ni][0], bf[ni][1]);
        }
    };

    const int nt = (K + 31) >> 5;
    LDG(0);
    STS(0);
    __syncthreads();
    for (int i = 0; i < nt; i++) {
        if (i + 1 < nt) LDG((i + 1) << 5);
        COMP(i & 1);
        if (i + 1 < nt) STS((i + 1) & 1);
        __syncthreads();
    }

#pragma unroll
    for (int mi = 0; mi < 4; mi++) {
        int m = m0 + wm * 64 + mi * 16 + lr;
#pragma unroll
        for (int ni = 0; ni < 4; ni++) {
            int n = n0 + wn * 32 + ni * 8 + lc * 2;
            if (n + 1 < N) {
                float b0 = bias[n], b1 = bias[n + 1];
                *(float2*)(C + (size_t)m * N + n) =
                    make_float2(acc[mi][ni][0] + b0, acc[mi][ni][1] + b1);
                *(float2*)(C + (size_t)(m + 8) * N + n) =
                    make_float2(acc[mi][ni][2] + b0, acc[mi][ni][3] + b1);
            } else if (n < N) {
                float b0 = bias[n];
                C[(size_t)m * N + n] = acc[mi][ni][0] + b0;
                C[(size_t)(m + 8) * N + n] = acc[mi][ni][2] + b0;
            }
        }
    }
}

// ===========================================================================
// gemm_lstm: fused single-step BiLSTM (i,g,o; f dead at h0=c0=0)
// H[M,2000] = scale*act(X[M,512] @ Wg^T + bg) (+= H)
// block 128x64x3gates, BK=32, 512 threads (16 warps 4m x 4n), warp 32x16x3.
// ===========================================================================
__device__ __forceinline__ int gather_row(int n, int t) {
    int d = (n >= 1000);
    int j = n - d * 1000;
    int toff = (t == 0) ? 0 : (t == 1 ? 2000 : 3000);
    return d * 4000 + toff + j;
}

__global__ __launch_bounds__(512, 1) void gemm_lstm(
    const float* __restrict__ X, const float* __restrict__ W,
    const float* __restrict__ b, float* __restrict__ C,
    int M, float scale, int accum) {
    const int N = 2000, K = 512;
    __shared__ __align__(16) char AsB[2][128 * 64];      // 16KB
    __shared__ __align__(16) char BsB[2][3][64 * 64];    // 24KB

    const int tid = threadIdx.x;
    const int wid = tid >> 5, lane = tid & 31;
    const int wm = wid & 3, wn = wid >> 2;
    const int lr = lane >> 2, lc = lane & 3;
    const int lc4 = lc * 4;
    const int sw = (lr >> 1) & 3;
    const int m0 = blockIdx.y * 128, n0 = blockIdx.x * 64;

    const int rowA = tid >> 3;   // 0..63
    const int kq   = tid & 7;

    const float* aP[2];
    aP[0] = X + (size_t)(m0 + rowA) * K + kq * 4;
    aP[1] = aP[0] + (size_t)64 * K;
    const int nB = n0 + rowA;
    const bool bok = (nB < N);
    const float* bP[3];
#pragma unroll
    for (int t = 0; t < 3; t++)
        bP[t] = W + (size_t)(bok ? gather_row(nB, t) : 0) * K + kq * 4;

    float acc[3][2][2][4];
#pragma unroll
    for (int t = 0; t < 3; t++)
#pragma unroll
        for (int mi = 0; mi < 2; mi++)
#pragma unroll
            for (int ni = 0; ni < 2; ni++)
#pragma unroll
                for (int r = 0; r < 4; r++) acc[t][mi][ni][r] = 0.0f;

    float4 pa[2], pb[3];

    auto LDG = [&](int kt) {
        pa[0] = *(const float4*)(aP[0] + kt);
        pa[1] = *(const float4*)(aP[1] + kt);
#pragma unroll
        for (int t = 0; t < 3; t++)
            pb[t] = bok ? *(const float4*)(bP[t] + kt) : make_float4(0.f, 0.f, 0.f, 0.f);
    };
    auto STS = [&](int buf) {
        sts_row(AsB[buf], rowA, kq, pa[0]);
        sts_row(AsB[buf], rowA + 64, kq, pa[1]);
#pragma unroll
        for (int t = 0; t < 3; t++) sts_row(BsB[buf][t], rowA, kq, pb[t]);
    };
    auto COMP = [&](int buf) {
        const char* As = AsB[buf];
#pragma unroll
        for (int ks = 0; ks < 32; ks += 16) {
            const int p0 = ((ks >> 3) ^ sw) * 16;
            const int p1 = (((ks >> 3) + 1) ^ sw) * 16;
            unsigned af[2][4], bf[3][2][2];
#pragma unroll
            for (int mi = 0; mi < 2; mi++) {
                const char* ra = As + (wm * 32 + mi * 16 + lr) * 64;
                af[mi][0] = *(const unsigned*)(ra + p0 + lc4);
                af[mi][1] = *(const unsigned*)(ra + 512 + p0 + lc4);
                af[mi][2] = *(const unsigned*)(ra + p1 + lc4);
                af[mi][3] = *(const unsigned*)(ra + 512 + p1 + lc4);
            }
#pragma unroll
            for (int t = 0; t < 3; t++) {
                const char* Bs = BsB[buf][t];
#pragma unroll
                for (int ni = 0; ni < 2; ni++) {
                    const char* rb = Bs + (wn * 16 + ni * 8 + lr) * 64;
                    bf[t][ni][0] = *(const unsigned*)(rb + p0 + lc4);
                    bf[t][ni][1] = *(const unsigned*)(rb + p1 + lc4);
                }
            }
#pragma unroll
            for (int t = 0; t < 3; t++)
#pragma unroll
                for (int mi = 0; mi < 2; mi++)
#pragma unroll
                    for (int ni = 0; ni < 2; ni++)
                        mma_f16(acc[t][mi][ni][0], acc[t][mi][ni][1],
                                acc[t][mi][ni][2], acc[t][mi][ni][3],
                                af[mi][0], af[mi][1], af[mi][2], af[mi][3],
                                bf[t][ni][0], bf[t][ni][1]);
        }
    };

    const int nt = K >> 5;   // 16
    LDG(0);
    STS(0);
    __syncthreads();
    for (int i = 0; i < nt; i++) {
        if (i + 1 < nt) LDG((i + 1) << 5);
        COMP(i & 1);
        if (i + 1 < nt) STS((i + 1) & 1);
        __syncthreads();
    }

#pragma unroll
    for (int mi = 0; mi < 2; mi++)
#pragma unroll
        for (int ni = 0; ni < 2; ni++) {
            int mA = m0 + wm * 32 + mi * 16 + lr;
            int nA = n0 + wn * 16 + ni * 8 + lc * 2;
#pragma unroll
            for (int r = 0; r < 4; r++) {
                int mm = mA + ((r >= 2) ? 8 : 0);
                int nn = nA + (r & 1);
                if (nn < N) {
                    int d = (nn >= 1000);
                    int base = d * 4000 + (nn - d * 1000);
                    float gi = acc[0][mi][ni][r] + b[base];
                    float gg = acc[1][mi][ni][r] + b[base + 2000];
                    float go = acc[2][mi][ni][r] + b[base + 3000];
                    float cc = sigf(gi) * tanh_fast(gg);
                    float h = sigf(go) * tanh_fast(cc);
                    float o = scale * h;
                    if (accum) o += C[(size_t)mm * N + nn];
                    C[(size_t)mm * N + nn] = o;
                }
            }
        }
}

// ---------------- neighbor mean: [B,24,E] -> [B,E] --------------------------
__global__ void mean_kernel(const float* __restrict__ Z, float* __restrict__ out) {
    int idx = blockIdx.x * blockDim.x + threadIdx.x;
    if (idx >= BB * EE) return;
    int bI = idx / EE, n = idx % EE;
    float s = 0.f;
#pragma unroll 4
    for (int j = 0; j < 24; j++) s += Z[(size_t)(bI * 24 + j) * EE + n];
    out[idx] = s * (1.0f / 24.0f);
}

// ---------------- 3-way attention combine -----------------------------------
__global__ void attention_kernel(const float* __restrict__ c, const float* __restrict__ u,
                                 const float* __restrict__ p, const float* __restrict__ att,
                                 float* __restrict__ out) {
    int bI = blockIdx.x, tid = threadIdx.x;
    const float* cb = c + (size_t)bI * EE;
    const float* ub = u + (size_t)bI * EE;
    const float* pb = p + (size_t)bI * EE;
    float s0 = 0.f, s1 = 0.f, s2 = 0.f, s3 = 0.f;
    for (int n = tid; n < EE; n += 256) {
        float a0 = att[n], a1 = att[EE + n];
        float cv = cb[n];
        s0 += cv * a0;
        s1 += cv * a1;
        s2 += ub[n] * a1;
        s3 += pb[n] * a1;
    }
    __shared__ float red[4][256];
    red[0][tid] = s0; red[1][tid] = s1; red[2][tid] = s2; red[3][tid] = s3;
    __syncthreads();
    for (int s = 128; s > 0; s >>= 1) {
        if (tid < s) {
#pragma unroll
            for (int q = 0; q < 4; q++) red[q][tid] += red[q][tid + s];
        }
        __syncthreads();
    }
    __shared__ float w[3];
    if (tid == 0) {
        float sc[3];
        sc[0] = red[0][0] + red[1][0];
        sc[1] = red[0][0] + red[2][0];
        sc[2] = red[0][0] + red[3][0];
#pragma unroll
        for (int k = 0; k < 3; k++) sc[k] = sc[k] > 0.f ? sc[k] : 0.01f * sc[k];
        float mx = fmaxf(sc[0], fmaxf(sc[1], sc[2]));
        float e0 = __expf(sc[0] - mx), e1 = __expf(sc[1] - mx), e2 = __expf(sc[2] - mx);
        float inv = 1.0f / (e0 + e1 + e2);
        w[0] = e0 * inv; w[1] = e1 * inv; w[2] = e2 * inv;
    }
    __syncthreads();
    float w0 = w[0], w1 = w[1], w2 = w[2];
    for (int n = tid; n < EE; n += 256)
        out[(size_t)bI * EE + n] = w0 * cb[n] + w1 * ub[n] + w2 * pb[n];
}

// ---------------------------------------------------------------------------
extern "C" void kernel_launch(void* const* d_in, const int* in_sizes, int n_in,
                              void* d_out, int out_size) {
    const float* c_text  = (const float*)d_in[0];
    const float* c_image = (const float*)d_in[1];
    const float* p_text  = (const float*)d_in[2];
    const float* p_image = (const float*)d_in[3];
    const float* u_text  = (const float*)d_in[4];
    const float* u_other = (const float*)d_in[5];
    const float* W_lt = (const float*)d_in[6],  *b_lt = (const float*)d_in[7];
    const float* W_li = (const float*)d_in[8],  *b_li = (const float*)d_in[9];
    const float* W_lo = (const float*)d_in[10], *b_lo = (const float*)d_in[11];
    const float* lstm_t_W = (const float*)d_in[12], *lstm_t_b = (const float*)d_in[13];
    const float* lstm_i_W = (const float*)d_in[14], *lstm_i_b = (const float*)d_in[15];
    const float* lstm_o_W = (const float*)d_in[16], *lstm_o_b = (const float*)d_in[17];
    const float* ua_lin_W = (const float*)d_in[18], *ua_lin_b = (const float*)d_in[19];
    const float* ua_lstm_W = (const float*)d_in[20], *ua_lstm_b = (const float*)d_in[21];
    const float* ua_out_W = (const float*)d_in[22], *ua_out_b = (const float*)d_in[23];
    const float* pa_lin_W = (const float*)d_in[24], *pa_lin_b = (const float*)d_in[25];
    const float* pa_lstm_W = (const float*)d_in[26], *pa_lstm_b = (const float*)d_in[27];
    const float* pa_out_W = (const float*)d_in[28], *pa_out_b = (const float*)d_in[29];
    const float* p_att = (const float*)d_in[30];
    float* out = (float*)d_out;

    float *bufX, *Hc, *Hp, *Hu, *H2, *Hm, *uagg, *pagg;
    cudaGetSymbolAddress((void**)&bufX, g_bufX);
    cudaGetSymbolAddress((void**)&Hc,   g_Hc);
    cudaGetSymbolAddress((void**)&Hp,   g_Hp);
    cudaGetSymbolAddress((void**)&Hu,   g_Hu);
    cudaGetSymbolAddress((void**)&H2,   g_H2);
    cudaGetSymbolAddress((void**)&Hm,   g_Hm);
    cudaGetSymbolAddress((void**)&uagg, g_uagg);
    cudaGetSymbolAddress((void**)&pagg, g_pagg);

    auto L1 = [&](const float* A, const float* W, const float* b, float* C,
                  int M, int N, int K) {
        dim3 g((N + 127) / 128, M / 256);
        gemm_lin<<<g, 512>>>(A, W, b, C, M, N, K);
    };
    auto L2 = [&](const float* X, const float* W, const float* b, float* C,
                  int M, float scale, int accum) {
        dim3 g((EE + 63) / 64, M / 128);
        gemm_lstm<<<g, 512>>>(X, W, b, C, M, scale, accum);
    };

    // ---- per-type input linear + BiLSTM ----
    L1(c_text,  W_lt, b_lt, bufX, BB, 512, 768);    L2(bufX, lstm_t_W, lstm_t_b, Hc, BB, 0.5f, 0);
    L1(c_image, W_li, b_li, bufX, BB, 512, 2048);   L2(bufX, lstm_i_W, lstm_i_b, Hc, BB, 0.5f, 1);
    L1(p_text,  W_lt, b_lt, bufX, MPU, 512, 768);   L2(bufX, lstm_t_W, lstm_t_b, Hp, MPU, 0.5f, 0);
    L1(p_image, W_li, b_li, bufX, MPU, 512, 2048);  L2(bufX, lstm_i_W, lstm_i_b, Hp, MPU, 0.5f, 1);
    L1(u_text,  W_lt, b_lt, bufX, MPU, 512, 768);   L2(bufX, lstm_t_W, lstm_t_b, Hu, MPU, 0.5f, 0);
    L1(u_other, W_lo, b_lo, bufX, MPU, 512, 512);   L2(bufX, lstm_o_W, lstm_o_b, Hu, MPU, 0.5f, 1);

    // ---- user aggregation (mean commuted before the out-linear) ----
    L1(Hu, ua_lin_W, ua_lin_b, bufX, MPU, 512, 2000);
    L2(bufX, ua_lstm_W, ua_lstm_b, H2, MPU, 1.0f, 0);
    mean_kernel<<<(BB * EE + 255) / 256, 256>>>(H2, Hm);
    L1(Hm, ua_out_W, ua_out_b, uagg, BB, 2000, 2000);

    // ---- post aggregation ----
    L1(Hp, pa_lin_W, pa_lin_b, bufX, MPU, 512, 2000);
    L2(bufX, pa_lstm_W, pa_lstm_b, H2, MPU, 1.0f, 0);
    mean_kernel<<<(BB * EE + 255) / 256, 256>>>(H2, Hm);
    L1(Hm, pa_out_W, pa_out_b, pagg, BB, 2000, 2000);

    // ---- attention combine ----
    attention_kernel<<<BB, 256>>>(Hc, uagg, pagg, p_att, out);
}

// round 6
// speedup vs baseline: 3.9039x; 1.2076x over previous
#include <cuda_runtime.h>
#include <cuda_fp16.h>
#include <cstdint>

// ---------------------------------------------------------------------------
// Het_GNN forward — fp16 operands in gmem, cp.async 4-stage, ldmatrix frags.
// ---------------------------------------------------------------------------
#define BB   512
#define MPU  12288
#define EE   2000

// ---------------- scratch (device globals; no allocation allowed) ----------
__device__ __half g_in16 [MPU * 2048];     // converted activations (reused)
__device__ __half g_w16  [27111936];       // all converted weights (offsets below)
__device__ __half g_bufX [MPU * 512];      // projected inputs (fp16)
__device__ float  g_Hc   [BB  * EE];       // center embed (fp32 for attention)
__device__ float  g_Ht32 [MPU * EE];       // fp32 intermediate (pass-1 LSTM)
__device__ __half g_Hp16 [MPU * EE];
__device__ __half g_Hu16 [MPU * EE];
__device__ __half g_H2   [MPU * EE];
__device__ __half g_Hm   [BB  * EE];
__device__ float  g_uagg [BB * EE];
__device__ float  g_pagg [BB * EE];

// weight arena offsets (halves)
#define O_WLT   0
#define O_WLI   393216
#define O_WLO   1441792
#define O_LT    1703936
#define O_LI    4775936
#define O_LO    7847936
#define O_UAL   10919936
#define O_PAL   13991936
#define O_UALIN 17063936
#define O_PALIN 18087936
#define O_UAOUT 19111936
#define O_PAOUT 23111936

// ---------------- helpers ---------------------------------------------------
__device__ __forceinline__ float sigf(float x) { return 1.0f / (1.0f + __expf(-x)); }
__device__ __forceinline__ float tanh_fast(float x) {
    return 2.0f / (1.0f + __expf(-2.0f * x)) - 1.0f;
}
__device__ __forceinline__ void mma_f16(float& d0, float& d1, float& d2, float& d3,
                                        unsigned a0, unsigned a1, unsigned a2, unsigned a3,
                                        unsigned b0, unsigned b1) {
    asm volatile(
        "mma.sync.aligned.m16n8k16.row.col.f32.f16.f16.f32 "
        "{%0,%1,%2,%3}, {%4,%5,%6,%7}, {%8,%9}, {%0,%1,%2,%3};"
        : "+f"(d0), "+f"(d1), "+f"(d2), "+f"(d3)
        : "r"(a0), "r"(a1), "r"(a2), "r"(a3), "r"(b0), "r"(b1));
}
__device__ __forceinline__ void ldsm4(unsigned& r0, unsigned& r1, unsigned& r2,
                                      unsigned& r3, uint32_t a) {
    asm volatile("ldmatrix.sync.aligned.m8n8.x4.shared.b16 {%0,%1,%2,%3}, [%4];"
                 : "=r"(r0), "=r"(r1), "=r"(r2), "=r"(r3) : "r"(a));
}
__device__ __forceinline__ void cpa16(uint32_t dst, const void* src, int srcbytes) {
    asm volatile("cp.async.ca.shared.global [%0], [%1], 16, %2;"
                 :: "r"(dst), "l"(src), "r"(srcbytes) : "memory");
}
__device__ __forceinline__ void cp_commit() {
    asm volatile("cp.async.commit_group;" ::: "memory");
}
template<int N>
__device__ __forceinline__ void cp_wait() {
    asm volatile("cp.async.wait_group %0;" :: "n"(N) : "memory");
}
__device__ __forceinline__ int gather_row(int n, int t) {
    int d = (n >= 1000);
    int toff = (t == 0) ? 0 : (t == 1 ? 2000 : 3000);
    return d * 4000 + toff + (n - d * 1000);
}

// ---------------- conversion kernels ----------------------------------------
__global__ void cvt16(const float* __restrict__ src, __half* __restrict__ dst, int n) {
    int i = (blockIdx.x * blockDim.x + threadIdx.x) * 8;
    if (i >= n) return;
    float4 a = *(const float4*)(src + i);
    float4 b = *(const float4*)(src + i + 4);
    __half2 h[4] = { __floats2half2_rn(a.x, a.y), __floats2half2_rn(a.z, a.w),
                     __floats2half2_rn(b.x, b.y), __floats2half2_rn(b.z, b.w) };
    *(uint4*)(dst + i) = *(uint4*)h;
}
// gather lstm weights [2,4H,512] -> fp16 [3,2000,512] (i,g,o)
__global__ void cvt_lstm(const float* __restrict__ W, __half* __restrict__ dst) {
    int idx = (blockIdx.x * blockDim.x + threadIdx.x) * 8;
    if (idx >= 3 * 2000 * 512) return;
    int k = idx & 511;
    int n = (idx >> 9) % 2000;
    int t = idx / (2000 * 512);
    const float* s = W + (size_t)gather_row(n, t) * 512 + k;
    float4 a = *(const float4*)s;
    float4 b = *(const float4*)(s + 4);
    __half2 h[4] = { __floats2half2_rn(a.x, a.y), __floats2half2_rn(a.z, a.w),
                     __floats2half2_rn(b.x, b.y), __floats2half2_rn(b.z, b.w) };
    *(uint4*)(dst + idx) = *(uint4*)h;
}

// ===========================================================================
// gemm_lin16: C[M,N] = A[M,K] @ W[N,K]^T + bias  (A,W fp16; accum fp32)
// block 256x128, BK=32 halves (64B rows), 512 thr (16 warps 4m x 4n), warp 64x32.
// 4-stage cp.async; chunk-swizzled smem (chunk c of row m at c^((m>>1)&3)).
// ===========================================================================
#define L_TA (256 * 64)
#define L_TB (128 * 64)
#define L_STRIDE (L_TA + L_TB)
#define SMEM_LIN (4 * L_STRIDE)

template<bool OUT16>
__global__ __launch_bounds__(512, 1) void gemm_lin16(
    const __half* __restrict__ A, const __half* __restrict__ W,
    const float* __restrict__ bias, float* __restrict__ Cf, __half* __restrict__ Ch,
    int M, int N, int K) {
    extern __shared__ char sm[];
    const uint32_t smb = (uint32_t)__cvta_generic_to_shared(sm);

    const int tid = threadIdx.x;
    const int wid = tid >> 5, lane = tid & 31;
    const int wm = wid & 3, wn = wid >> 2;
    const int lr = lane >> 2, lc = lane & 3;
    const int m0 = blockIdx.y * 256, n0 = blockIdx.x * 128;

    // producer: slot0/1 = A chunks (rows r, r+128), slot2 = B chunk (row r)
    const int prow = tid >> 2, pc = tid & 3;
    const __half* srcA0 = A + (size_t)(m0 + prow) * K + pc * 8;
    const __half* srcA1 = A + (size_t)(m0 + prow + 128) * K + pc * 8;
    const bool brOK = (n0 + prow) < N;
    const __half* srcB = W + (size_t)(brOK ? (n0 + prow) : 0) * K + pc * 8;
    const uint32_t dA0 = smb + prow * 64 + ((pc ^ ((prow >> 1) & 3)) << 4);
    const uint32_t dA1 = smb + (prow + 128) * 64 + ((pc ^ (((prow + 128) >> 1) & 3)) << 4);
    const uint32_t dB = smb + L_TA + prow * 64 + ((pc ^ ((prow >> 1) & 3)) << 4);

    // consumer per-lane fragment addresses
    const int l15 = lane & 15, hi = lane >> 4;
    uint32_t aOff[4], bOff[2];
    int aSwz[4], bSwz[2];
#pragma unroll
    for (int mi = 0; mi < 4; mi++) {
        int r = wm * 64 + mi * 16 + l15;
        aOff[mi] = r * 64; aSwz[mi] = (r >> 1) & 3;
    }
#pragma unroll
    for (int nj = 0; nj < 2; nj++) {
        int r = wn * 32 + nj * 16 + l15;
        bOff[nj] = L_TA + r * 64; bSwz[nj] = (r >> 1) & 3;
    }

    float acc[4][4][4];
#pragma unroll
    for (int mi = 0; mi < 4; mi++)
#pragma unroll
        for (int ni = 0; ni < 4; ni++)
#pragma unroll
            for (int r = 0; r < 4; r++) acc[mi][ni][r] = 0.0f;

    const int nt = (K + 31) >> 5;
    auto LOAD = [&](int s, int kt) {
        const uint32_t so = s * L_STRIDE;
        const int kb = (kt + pc * 8 + 8 <= K) ? 16 : 0;
        cpa16(dA0 + so, srcA0 + kt, kb);
        cpa16(dA1 + so, srcA1 + kt, kb);
        cpa16(dB + so, srcB + kt, brOK ? kb : 0);
    };

    LOAD(0, 0); cp_commit();
    LOAD(1, 32); cp_commit();
    LOAD(2, 64); cp_commit();

    for (int i = 0; i < nt; i++) {
        cp_wait<2>();
        __syncthreads();
        if (i + 3 < nt) LOAD((i + 3) & 3, (i + 3) << 5);
        cp_commit();

        const uint32_t base = smb + (i & 3) * L_STRIDE;
#pragma unroll
        for (int kc = 0; kc < 4; kc += 2) {     // two k16 steps (chunks kc,kc+1)
            unsigned af[4][4], bq[2][4];
#pragma unroll
            for (int mi = 0; mi < 4; mi++)
                ldsm4(af[mi][0], af[mi][1], af[mi][2], af[mi][3],
                      base + aOff[mi] + (((kc + hi) ^ aSwz[mi]) << 4));
#pragma unroll
            for (int nj = 0; nj < 2; nj++)
                ldsm4(bq[nj][0], bq[nj][1], bq[nj][2], bq[nj][3],
                      base + bOff[nj] + (((kc + hi) ^ bSwz[nj]) << 4));
#pragma unroll
            for (int mi = 0; mi < 4; mi++)
#pragma unroll
                for (int nj = 0; nj < 2; nj++) {
                    mma_f16(acc[mi][2 * nj][0], acc[mi][2 * nj][1],
                            acc[mi][2 * nj][2], acc[mi][2 * nj][3],
                            af[mi][0], af[mi][1], af[mi][2], af[mi][3],
                            bq[nj][0], bq[nj][2]);
                    mma_f16(acc[mi][2 * nj + 1][0], acc[mi][2 * nj + 1][1],
                            acc[mi][2 * nj + 1][2], acc[mi][2 * nj + 1][3],
                            af[mi][0], af[mi][1], af[mi][2], af[mi][3],
                            bq[nj][1], bq[nj][3]);
                }
        }
    }

#pragma unroll
    for (int mi = 0; mi < 4; mi++) {
        int m = m0 + wm * 64 + mi * 16 + lr;
#pragma unroll
        for (int ni = 0; ni < 4; ni++) {
            int n = n0 + wn * 32 + ni * 8 + lc * 2;
            if (n + 1 < N) {
                float b0 = bias[n], b1 = bias[n + 1];
                float v00 = acc[mi][ni][0] + b0, v01 = acc[mi][ni][1] + b1;
                float v10 = acc[mi][ni][2] + b0, v11 = acc[mi][ni][3] + b1;
                if (OUT16) {
                    *(__half2*)(Ch + (size_t)m * N + n) = __floats2half2_rn(v00, v01);
                    *(__half2*)(Ch + (size_t)(m + 8) * N + n) = __floats2half2_rn(v10, v11);
                } else {
                    *(float2*)(Cf + (size_t)m * N + n) = make_float2(v00, v01);
                    *(float2*)(Cf + (size_t)(m + 8) * N + n) = make_float2(v10, v11);
                }
            } else if (n < N) {
                float b0 = bias[n];
                if (OUT16) {
                    Ch[(size_t)m * N + n] = __float2half_rn(acc[mi][ni][0] + b0);
                    Ch[(size_t)(m + 8) * N + n] = __float2half_rn(acc[mi][ni][2] + b0);
                } else {
                    Cf[(size_t)m * N + n] = acc[mi][ni][0] + b0;
                    Cf[(size_t)(m + 8) * N + n] = acc[mi][ni][2] + b0;
                }
            }
        }
    }
}

// ===========================================================================
// gemm_lstm16: fused single-step BiLSTM (gates i,g,o pre-gathered in Wg).
// out = scale * sig(o)*tanh(sig(i)*tanh(g))  [+ Acc];  fp32 or fp16 out.
// block 128x64x3, BK=32, 512 thr (16 warps 4m x 4n), warp 32x16x3. K=512.
// ===========================================================================
#define S_TA (128 * 64)
#define S_TB (192 * 64)
#define S_STRIDE (S_TA + S_TB)
#define SMEM_LSTM (4 * S_STRIDE)

__global__ __launch_bounds__(512, 1) void gemm_lstm16(
    const __half* __restrict__ A, const __half* __restrict__ Wg,
    const float* __restrict__ b, const float* __restrict__ Acc,
    float* __restrict__ Cf, __half* __restrict__ Ch,
    int M, float scale, int accum, int out16) {
    const int N = 2000, K = 512;
    extern __shared__ char sm[];
    const uint32_t smb = (uint32_t)__cvta_generic_to_shared(sm);

    const int tid = threadIdx.x;
    const int wid = tid >> 5, lane = tid & 31;
    const int wm = wid & 3, wn = wid >> 2;
    const int lr = lane >> 2, lc = lane & 3;
    const int m0 = blockIdx.y * 128, n0 = blockIdx.x * 64;

    // producer: slot0 = A chunk tid; slot1 = B chunk tid; slot2 = B chunk 512+tid (tid<256)
    const int pc = tid & 3;
    const int arow = tid >> 2;                       // 0..127
    const __half* srcA = A + (size_t)(m0 + arow) * K + pc * 8;
    const uint32_t dA = smb + arow * 64 + ((pc ^ ((arow >> 1) & 3)) << 4);

    const int b1t = tid >> 8, b1r = (tid & 255) >> 2;     // gate 0/1, row 0..63
    const bool b1ok = (n0 + b1r) < N;
    const __half* srcB1 = Wg + (size_t)(b1t * 2000 + (b1ok ? n0 + b1r : 0)) * K + pc * 8;
    const uint32_t dB1 = smb + S_TA + (b1t * 64 + b1r) * 64 + ((pc ^ ((b1r >> 1) & 3)) << 4);

    const bool has2 = tid < 256;
    const int b2r = tid >> 2;                       // row 0..63, gate 2
    const bool b2ok = has2 && ((n0 + b2r) < N);
    const __half* srcB2 = Wg + (size_t)(2 * 2000 + (b2ok ? n0 + b2r : 0)) * K + pc * 8;
    const uint32_t dB2 = smb + S_TA + (2 * 64 + b2r) * 64 + ((pc ^ ((b2r >> 1) & 3)) << 4);

    // consumer fragment addresses
    const int l15 = lane & 15, hi = lane >> 4;
    uint32_t aOff[2]; int aSwz[2];
#pragma unroll
    for (int mi = 0; mi < 2; mi++) {
        int r = wm * 32 + mi * 16 + l15;
        aOff[mi] = r * 64; aSwz[mi] = (r >> 1) & 3;
    }
    uint32_t bOff[3]; int bSwz;
    {
        int r = wn * 16 + l15;                       // row within gate 0..31
        bSwz = (r >> 1) & 3;
#pragma unroll
        for (int t = 0; t < 3; t++) bOff[t] = S_TA + (t * 64 + r) * 64;
    }

    float acc[3][2][2][4];
#pragma unroll
    for (int t = 0; t < 3; t++)
#pragma unroll
        for (int mi = 0; mi < 2; mi++)
#pragma unroll
            for (int ni = 0; ni < 2; ni++)
#pragma unroll
                for (int r = 0; r < 4; r++) acc[t][mi][ni][r] = 0.0f;

    const int nt = K >> 5;    // 16
    auto LOAD = [&](int s, int kt) {
        const uint32_t so = s * S_STRIDE;
        cpa16(dA + so, srcA + kt, 16);
        cpa16(dB1 + so, srcB1 + kt, b1ok ? 16 : 0);
        if (has2) cpa16(dB2 + so, srcB2 + kt, b2ok ? 16 : 0);
    };

    LOAD(0, 0); cp_commit();
    LOAD(1, 32); cp_commit();
    LOAD(2, 64); cp_commit();

    for (int i = 0; i < nt; i++) {
        cp_wait<2>();
        __syncthreads();
        if (i + 3 < nt) LOAD((i + 3) & 3, (i + 3) << 5);
        cp_commit();

        const uint32_t base = smb + (i & 3) * S_STRIDE;
#pragma unroll
        for (int kc = 0; kc < 4; kc += 2) {
            unsigned af[2][4], bt[3][4];
#pragma unroll
            for (int mi = 0; mi < 2; mi++)
                ldsm4(af[mi][0], af[mi][1], af[mi][2], af[mi][3],
                      base + aOff[mi] + (((kc + hi) ^ aSwz[mi]) << 4));
#pragma unroll
            for (int t = 0; t < 3; t++)
                ldsm4(bt[t][0], bt[t][1], bt[t][2], bt[t][3],
                      base + bOff[t] + (((kc + hi) ^ bSwz) << 4));
#pragma unroll
            for (int t = 0; t < 3; t++)
#pragma unroll
                for (int mi = 0; mi < 2; mi++) {
                    mma_f16(acc[t][mi][0][0], acc[t][mi][0][1],
                            acc[t][mi][0][2], acc[t][mi][0][3],
                            af[mi][0], af[mi][1], af[mi][2], af[mi][3],
                            bt[t][0], bt[t][2]);
                    mma_f16(acc[t][mi][1][0], acc[t][mi][1][1],
                            acc[t][mi][1][2], acc[t][mi][1][3],
                            af[mi][0], af[mi][1], af[mi][2], af[mi][3],
                            bt[t][1], bt[t][3]);
                }
        }
    }

#pragma unroll
    for (int mi = 0; mi < 2; mi++)
#pragma unroll
        for (int ni = 0; ni < 2; ni++) {
            int mA = m0 + wm * 32 + mi * 16 + lr;
            int nA = n0 + wn * 16 + ni * 8 + lc * 2;
#pragma unroll
            for (int r = 0; r < 4; r++) {
                int mm = mA + ((r >= 2) ? 8 : 0);
                int nn = nA + (r & 1);
                if (nn < N) {
                    int d = (nn >= 1000);
                    int base = d * 4000 + (nn - d * 1000);
                    float gi = acc[0][mi][ni][r] + b[base];
                    float gg = acc[1][mi][ni][r] + b[base + 2000];
                    float go = acc[2][mi][ni][r] + b[base + 3000];
                    float cc = sigf(gi) * tanh_fast(gg);
                    float h = sigf(go) * tanh_fast(cc);
                    float o = scale * h;
                    if (accum) o += Acc[(size_t)mm * N + nn];
                    if (out16) Ch[(size_t)mm * N + nn] = __float2half_rn(o);
                    else       Cf[(size_t)mm * N + nn] = o;
                }
            }
        }
}

// ---------------- neighbor mean (fp16 in/out, fp32 accumulate) --------------
__global__ void mean16(const __half* __restrict__ Z, __half* __restrict__ out) {
    int idx = blockIdx.x * blockDim.x + threadIdx.x;
    if (idx >= BB * EE) return;
    int bI = idx / EE, n = idx % EE;
    float s = 0.f;
#pragma unroll 4
    for (int j = 0; j < 24; j++) s += __half2float(Z[(size_t)(bI * 24 + j) * EE + n]);
    out[idx] = __float2half_rn(s * (1.0f / 24.0f));
}

// ---------------- 3-way attention combine -----------------------------------
__global__ void attention_kernel(const float* __restrict__ c, const float* __restrict__ u,
                                 const float* __restrict__ p, const float* __restrict__ att,
                                 float* __restrict__ out) {
    int bI = blockIdx.x, tid = threadIdx.x;
    const float* cb = c + (size_t)bI * EE;
    const float* ub = u + (size_t)bI * EE;
    const float* pb = p + (size_t)bI * EE;
    float s0 = 0.f, s1 = 0.f, s2 = 0.f, s3 = 0.f;
    for (int n = tid; n < EE; n += 256) {
        float a0 = att[n], a1 = att[EE + n];
        float cv = cb[n];
        s0 += cv * a0;
        s1 += cv * a1;
        s2 += ub[n] * a1;
        s3 += pb[n] * a1;
    }
    __shared__ float red[4][256];
    red[0][tid] = s0; red[1][tid] = s1; red[2][tid] = s2; red[3][tid] = s3;
    __syncthreads();
    for (int s = 128; s > 0; s >>= 1) {
        if (tid < s) {
#pragma unroll
            for (int q = 0; q < 4; q++) red[q][tid] += red[q][tid + s];
        }
        __syncthreads();
    }
    __shared__ float w[3];
    if (tid == 0) {
        float sc[3];
        sc[0] = red[0][0] + red[1][0];
        sc[1] = red[0][0] + red[2][0];
        sc[2] = red[0][0] + red[3][0];
#pragma unroll
        for (int k = 0; k < 3; k++) sc[k] = sc[k] > 0.f ? sc[k] : 0.01f * sc[k];
        float mx = fmaxf(sc[0], fmaxf(sc[1], sc[2]));
        float e0 = __expf(sc[0] - mx), e1 = __expf(sc[1] - mx), e2 = __expf(sc[2] - mx);
        float inv = 1.0f / (e0 + e1 + e2);
        w[0] = e0 * inv; w[1] = e1 * inv; w[2] = e2 * inv;
    }
    __syncthreads();
    float w0 = w[0], w1 = w[1], w2 = w[2];
    for (int n = tid; n < EE; n += 256)
        out[(size_t)bI * EE + n] = w0 * cb[n] + w1 * ub[n] + w2 * pb[n];
}

// ---------------------------------------------------------------------------
extern "C" void kernel_launch(void* const* d_in, const int* in_sizes, int n_in,
                              void* d_out, int out_size) {
    const float* c_text  = (const float*)d_in[0];
    const float* c_image = (const float*)d_in[1];
    const float* p_text  = (const float*)d_in[2];
    const float* p_image = (const float*)d_in[3];
    const float* u_text  = (const float*)d_in[4];
    const float* u_other = (const float*)d_in[5];
    const float* W_lt = (const float*)d_in[6],  *b_lt = (const float*)d_in[7];
    const float* W_li = (const float*)d_in[8],  *b_li = (const float*)d_in[9];
    const float* W_lo = (const float*)d_in[10], *b_lo = (const float*)d_in[11];
    const float* lstm_t_W = (const float*)d_in[12], *lstm_t_b = (const float*)d_in[13];
    const float* lstm_i_W = (const float*)d_in[14], *lstm_i_b = (const float*)d_in[15];
    const float* lstm_o_W = (const float*)d_in[16], *lstm_o_b = (const float*)d_in[17];
    const float* ua_lin_W = (const float*)d_in[18], *ua_lin_b = (const float*)d_in[19];
    const float* ua_lstm_W = (const float*)d_in[20], *ua_lstm_b = (const float*)d_in[21];
    const float* ua_out_W = (const float*)d_in[22], *ua_out_b = (const float*)d_in[23];
    const float* pa_lin_W = (const float*)d_in[24], *pa_lin_b = (const float*)d_in[25];
    const float* pa_lstm_W = (const float*)d_in[26], *pa_lstm_b = (const float*)d_in[27];
    const float* pa_out_W = (const float*)d_in[28], *pa_out_b = (const float*)d_in[29];
    const float* p_att = (const float*)d_in[30];
    float* out = (float*)d_out;

    __half *in16, *w16, *bufX, *Hp16, *Hu16, *H2, *Hm;
    float *Hc, *Ht32, *uagg, *pagg;
    cudaGetSymbolAddress((void**)&in16, g_in16);
    cudaGetSymbolAddress((void**)&w16,  g_w16);
    cudaGetSymbolAddress((void**)&bufX, g_bufX);
    cudaGetSymbolAddress((void**)&Hc,   g_Hc);
    cudaGetSymbolAddress((void**)&Ht32, g_Ht32);
    cudaGetSymbolAddress((void**)&Hp16, g_Hp16);
    cudaGetSymbolAddress((void**)&Hu16, g_Hu16);
    cudaGetSymbolAddress((void**)&H2,   g_H2);
    cudaGetSymbolAddress((void**)&Hm,   g_Hm);
    cudaGetSymbolAddress((void**)&uagg, g_uagg);
    cudaGetSymbolAddress((void**)&pagg, g_pagg);

    cudaFuncSetAttribute(gemm_lin16<true>,  cudaFuncAttributeMaxDynamicSharedMemorySize, SMEM_LIN);
    cudaFuncSetAttribute(gemm_lin16<false>, cudaFuncAttributeMaxDynamicSharedMemorySize, SMEM_LIN);
    cudaFuncSetAttribute(gemm_lstm16, cudaFuncAttributeMaxDynamicSharedMemorySize, SMEM_LSTM);

    auto CVT = [&](const float* s, __half* d, int n) {
        cvt16<<<(n / 8 + 255) / 256, 256>>>(s, d, n);
    };
    auto CVTL = [&](const float* W, __half* d) {
        cvt_lstm<<<(3 * 2000 * 512 / 8 + 255) / 256, 256>>>(W, d);
    };
    // GEMM wrappers
    auto LIN16 = [&](const __half* A, const __half* W, const float* b, __half* Ch,
                     int M, int N, int K) {
        dim3 g((N + 127) / 128, M / 256);
        gemm_lin16<true><<<g, 512, SMEM_LIN>>>(A, W, b, nullptr, Ch, M, N, K);
    };
    auto LIN32 = [&](const __half* A, const __half* W, const float* b, float* Cf,
                     int M, int N, int K) {
        dim3 g((N + 127) / 128, M / 256);
        gemm_lin16<false><<<g, 512, SMEM_LIN>>>(A, W, b, Cf, nullptr, M, N, K);
    };
    auto LSTM = [&](const __half* A, const __half* Wg, const float* b,
                    const float* Acc, float* Cf, __half* Ch,
                    int M, float scale, int accum, int out16) {
        dim3 g((EE + 63) / 64, M / 128);
        gemm_lstm16<<<g, 512, SMEM_LSTM>>>(A, Wg, b, Acc, Cf, Ch, M, scale, accum, out16);
    };

    // ---- convert all weights once per call ----
    CVT(W_lt, w16 + O_WLT, 512 * 768);
    CVT(W_li, w16 + O_WLI, 512 * 2048);
    CVT(W_lo, w16 + O_WLO, 512 * 512);
    CVT(ua_lin_W, w16 + O_UALIN, 512 * 2000);
    CVT(pa_lin_W, w16 + O_PALIN, 512 * 2000);
    CVT(ua_out_W, w16 + O_UAOUT, 2000 * 2000);
    CVT(pa_out_W, w16 + O_PAOUT, 2000 * 2000);
    CVTL(lstm_t_W,  w16 + O_LT);
    CVTL(lstm_i_W,  w16 + O_LI);
    CVTL(lstm_o_W,  w16 + O_LO);
    CVTL(ua_lstm_W, w16 + O_UAL);
    CVTL(pa_lstm_W, w16 + O_PAL);

    // ---- center (post) node: Hc fp32 ----
    CVT(c_text, in16, BB * 768);
    LIN16(in16, w16 + O_WLT, b_lt, bufX, BB, 512, 768);
    LSTM(bufX, w16 + O_LT, lstm_t_b, nullptr, Hc, nullptr, BB, 0.5f, 0, 0);
    CVT(c_image, in16, BB * 2048);
    LIN16(in16, w16 + O_WLI, b_li, bufX, BB, 512, 2048);
    LSTM(bufX, w16 + O_LI, lstm_i_b, Hc, Hc, nullptr, BB, 0.5f, 1, 0);

    // ---- post neighbors -> Hp16 ----
    CVT(p_text, in16, MPU * 768);
    LIN16(in16, w16 + O_WLT, b_lt, bufX, MPU, 512, 768);
    LSTM(bufX, w16 + O_LT, lstm_t_b, nullptr, Ht32, nullptr, MPU, 0.5f, 0, 0);
    CVT(p_image, in16, MPU * 2048);
    LIN16(in16, w16 + O_WLI, b_li, bufX, MPU, 512, 2048);
    LSTM(bufX, w16 + O_LI, lstm_i_b, Ht32, nullptr, Hp16, MPU, 0.5f, 1, 1);

    // ---- user neighbors -> Hu16 ----
    CVT(u_text, in16, MPU * 768);
    LIN16(in16, w16 + O_WLT, b_lt, bufX, MPU, 512, 768);
    LSTM(bufX, w16 + O_LT, lstm_t_b, nullptr, Ht32, nullptr, MPU, 0.5f, 0, 0);
    CVT(u_other, in16, MPU * 512);
    LIN16(in16, w16 + O_WLO, b_lo, bufX, MPU, 512, 512);
    LSTM(bufX, w16 + O_LO, lstm_o_b, Ht32, nullptr, Hu16, MPU, 0.5f, 1, 1);

    // ---- user aggregation ----
    LIN16(Hu16, w16 + O_UALIN, ua_lin_b, bufX, MPU, 512, 2000);
    LSTM(bufX, w16 + O_UAL, ua_lstm_b, nullptr, nullptr, H2, MPU, 1.0f, 0, 1);
    mean16<<<(BB * EE + 255) / 256, 256>>>(H2, Hm);
    LIN32(Hm, w16 + O_UAOUT, ua_out_b, uagg, BB, 2000, 2000);

    // ---- post aggregation ----
    LIN16(Hp16, w16 + O_PALIN, pa_lin_b, bufX, MPU, 512, 2000);
    LSTM(bufX, w16 + O_PAL, pa_lstm_b, nullptr, nullptr, H2, MPU, 1.0f, 0, 1);
    mean16<<<(BB * EE + 255) / 256, 256>>>(H2, Hm);
    LIN32(Hm, w16 + O_PAOUT, pa_out_b, pagg, BB, 2000, 2000);

    // ---- attention combine ----
    attention_kernel<<<BB, 256>>>(Hc, uagg, pagg, p_att, out);
}

// round 7
// speedup vs baseline: 4.1868x; 1.0725x over previous
#include <cuda_runtime.h>
#include <cuda_fp16.h>
#include <cstdint>

// ---------------------------------------------------------------------------
// Het_GNN forward — fp16 mma.sync, batched streams + z-paired agg pipelines.
// ---------------------------------------------------------------------------
#define BB   512
#define MPU  12288
#define MT   25088      // text rows: c(512) + p(12288) + u(12288)
#define MI2  12800      // image rows: c(512) + p(12288)
#define EE   2000

// ---------------- scratch (device globals) ----------------------------------
__device__ __half g_in16 [51773440];       // input arena (text|image|other)
__device__ __half g_w16  [27111936];       // converted weights
__device__ __half g_bufX [25690112];       // projection arena
__device__ float  g_Ht32 [MT * EE];        // fp32 LSTM pass arena [25088,2000]
__device__ float  g_Hc   [BB  * EE];
__device__ __half g_Hp16 [MPU * EE];
__device__ __half g_Hu16 [MPU * EE];
__device__ __half g_H2   [2 * MPU * EE];   // paired agg-LSTM out (u|p)
__device__ __half g_Hm   [2 * BB * EE];    // paired neighbor means (u|p)
__device__ float  g_uagg [BB * EE];
__device__ float  g_pagg [BB * EE];

// input arena offsets (halves)
#define I_TEXT 0
#define I_IMG  19267584
#define I_OTH  45481984
// projection arena offsets (halves)
#define X_TEXT 0
#define X_IMG  12845056
#define X_OTH  19398656
// weight arena offsets (halves)
#define O_WLT   0
#define O_WLI   393216
#define O_WLO   1441792
#define O_LT    1703936
#define O_LI    4775936
#define O_LO    7847936
#define O_UAL   10919936
#define O_PAL   13991936
#define O_UALIN 17063936
#define O_PALIN 18087936
#define O_UAOUT 19111936
#define O_PAOUT 23111936

// ---------------- helpers ----------------------------------------------------
__device__ __forceinline__ float sigf(float x) { return 1.0f / (1.0f + __expf(-x)); }
__device__ __forceinline__ float tanh_fast(float x) {
    return 2.0f / (1.0f + __expf(-2.0f * x)) - 1.0f;
}
__device__ __forceinline__ void mma_f16(float& d0, float& d1, float& d2, float& d3,
                                        unsigned a0, unsigned a1, unsigned a2, unsigned a3,
                                        unsigned b0, unsigned b1) {
    asm volatile(
        "mma.sync.aligned.m16n8k16.row.col.f32.f16.f16.f32 "
        "{%0,%1,%2,%3}, {%4,%5,%6,%7}, {%8,%9}, {%0,%1,%2,%3};"
        : "+f"(d0), "+f"(d1), "+f"(d2), "+f"(d3)
        : "r"(a0), "r"(a1), "r"(a2), "r"(a3), "r"(b0), "r"(b1));
}
__device__ __forceinline__ void ldsm4(unsigned& r0, unsigned& r1, unsigned& r2,
                                      unsigned& r3, uint32_t a) {
    asm volatile("ldmatrix.sync.aligned.m8n8.x4.shared.b16 {%0,%1,%2,%3}, [%4];"
                 : "=r"(r0), "=r"(r1), "=r"(r2), "=r"(r3) : "r"(a));
}
__device__ __forceinline__ void cpa16(uint32_t dst, const void* src, int srcbytes) {
    asm volatile("cp.async.ca.shared.global [%0], [%1], 16, %2;"
                 :: "r"(dst), "l"(src), "r"(srcbytes) : "memory");
}
__device__ __forceinline__ void cp_commit() {
    asm volatile("cp.async.commit_group;" ::: "memory");
}
template<int N>
__device__ __forceinline__ void cp_wait() {
    asm volatile("cp.async.wait_group %0;" :: "n"(N) : "memory");
}
__device__ __forceinline__ int gather_row(int n, int t) {
    int d = (n >= 1000);
    int toff = (t == 0) ? 0 : (t == 1 ? 2000 : 3000);
    return d * 4000 + toff + (n - d * 1000);
}

// ---------------- conversion kernels -----------------------------------------
__global__ void cvt16(const float* __restrict__ src, __half* __restrict__ dst, int n) {
    int i = (blockIdx.x * blockDim.x + threadIdx.x) * 8;
    if (i >= n) return;
    float4 a = *(const float4*)(src + i);
    float4 b = *(const float4*)(src + i + 4);
    __half2 h[4] = { __floats2half2_rn(a.x, a.y), __floats2half2_rn(a.z, a.w),
                     __floats2half2_rn(b.x, b.y), __floats2half2_rn(b.z, b.w) };
    *(uint4*)(dst + i) = *(uint4*)h;
}
__global__ void cvt_lstm(const float* __restrict__ W, __half* __restrict__ dst) {
    int idx = (blockIdx.x * blockDim.x + threadIdx.x) * 8;
    if (idx >= 3 * 2000 * 512) return;
    int k = idx & 511;
    int n = (idx >> 9) % 2000;
    int t = idx / (2000 * 512);
    const float* s = W + (size_t)gather_row(n, t) * 512 + k;
    float4 a = *(const float4*)s;
    float4 b = *(const float4*)(s + 4);
    __half2 h[4] = { __floats2half2_rn(a.x, a.y), __floats2half2_rn(a.z, a.w),
                     __floats2half2_rn(b.x, b.y), __floats2half2_rn(b.z, b.w) };
    *(uint4*)(dst + idx) = *(uint4*)h;
}
// split image-pass fp32 rows into Hc (rows<512) / Hp16 (rest)
__global__ void extract_kernel(const float* __restrict__ Ht, float* __restrict__ Hc,
                               __half* __restrict__ Hp) {
    int i = (blockIdx.x * blockDim.x + threadIdx.x) * 4;
    if (i >= MI2 * EE) return;
    float4 v = *(const float4*)(Ht + i);
    int r = i / EE;
    if (r < BB) {
        *(float4*)(Hc + i) = v;
    } else {
        __half2 h[2] = { __floats2half2_rn(v.x, v.y), __floats2half2_rn(v.z, v.w) };
        *(uint2*)(Hp + (i - BB * EE)) = *(uint2*)h;
    }
}

// ---------------- arg structs for z-paired launches ---------------------------
struct LinSet  { const __half* A; const __half* W; const float* bias;
                 float* Cf; __half* Ch; };
struct LstmSet { const __half* A; const __half* Wg; const float* bG;
                 const float* Acc; float* Cf; __half* Ch; };

// ===========================================================================
// gemm_lin16<BM, OUT16>: C[M,N] = A[M,K] @ W[N,K]^T + bias
// BM in {256,128}, BN=128, 512 thr (16 warps 4m x 4n), 4-stage cp.async,
// chunk-swizzle (chunk c of row m at c^((m>>1)&3)), ldmatrix fragments.
// ===========================================================================
template<int BM, bool OUT16>
__global__ __launch_bounds__(512, 1) void gemm_lin16(
    LinSet s0, LinSet s1, int M, int N, int K) {
    constexpr int TA = BM * 64;
    constexpr int TB = 128 * 64;
    constexpr int STRIDE = TA + TB;
    constexpr int MI = BM / 64;          // fragments per warp in m
    constexpr int AP = BM / 128;         // producer A chunks per thread

    const LinSet S = blockIdx.z ? s1 : s0;
    extern __shared__ char sm[];
    const uint32_t smb = (uint32_t)__cvta_generic_to_shared(sm);

    const int tid = threadIdx.x;
    const int wid = tid >> 5, lane = tid & 31;
    const int wm = wid & 3, wn = wid >> 2;
    const int lr = lane >> 2, lc = lane & 3;
    const int m0 = blockIdx.y * BM, n0 = blockIdx.x * 128;

    const int prow = tid >> 2, pc = tid & 3;
    const __half* srcA[AP];
    uint32_t dA[AP];
#pragma unroll
    for (int p = 0; p < AP; p++) {
        int r = prow + 128 * p;
        srcA[p] = S.A + (size_t)(m0 + r) * K + pc * 8;
        dA[p] = smb + r * 64 + ((pc ^ ((r >> 1) & 3)) << 4);
    }
    const bool brOK = (n0 + prow) < N;
    const __half* srcB = S.W + (size_t)(brOK ? (n0 + prow) : 0) * K + pc * 8;
    const uint32_t dB = smb + TA + prow * 64 + ((pc ^ ((prow >> 1) & 3)) << 4);

    const int l15 = lane & 15, hi = lane >> 4;
    uint32_t aOff[MI], bOff[2];
    int aSwz[MI], bSwz[2];
#pragma unroll
    for (int mi = 0; mi < MI; mi++) {
        int r = wm * (BM / 4) + mi * 16 + l15;
        aOff[mi] = r * 64; aSwz[mi] = (r >> 1) & 3;
    }
#pragma unroll
    for (int nj = 0; nj < 2; nj++) {
        int r = wn * 32 + nj * 16 + l15;
        bOff[nj] = TA + r * 64; bSwz[nj] = (r >> 1) & 3;
    }

    float acc[MI][4][4];
#pragma unroll
    for (int mi = 0; mi < MI; mi++)
#pragma unroll
        for (int ni = 0; ni < 4; ni++)
#pragma unroll
            for (int r = 0; r < 4; r++) acc[mi][ni][r] = 0.0f;

    const int nt = (K + 31) >> 5;
    auto LOAD = [&](int s, int kt) {
        const uint32_t so = s * STRIDE;
        const int kb = (kt + pc * 8 + 8 <= K) ? 16 : 0;
#pragma unroll
        for (int p = 0; p < AP; p++) cpa16(dA[p] + so, srcA[p] + kt, kb);
        cpa16(dB + so, srcB + kt, brOK ? kb : 0);
    };

    LOAD(0, 0); cp_commit();
    LOAD(1, 32); cp_commit();
    LOAD(2, 64); cp_commit();

    for (int i = 0; i < nt; i++) {
        cp_wait<2>();
        __syncthreads();
        if (i + 3 < nt) LOAD((i + 3) & 3, (i + 3) << 5);
        cp_commit();

        const uint32_t base = smb + (i & 3) * STRIDE;
#pragma unroll
        for (int kc = 0; kc < 4; kc += 2) {
            unsigned af[MI][4], bq[2][4];
#pragma unroll
            for (int mi = 0; mi < MI; mi++)
                ldsm4(af[mi][0], af[mi][1], af[mi][2], af[mi][3],
                      base + aOff[mi] + (((kc + hi) ^ aSwz[mi]) << 4));
#pragma unroll
            for (int nj = 0; nj < 2; nj++)
                ldsm4(bq[nj][0], bq[nj][1], bq[nj][2], bq[nj][3],
                      base + bOff[nj] + (((kc + hi) ^ bSwz[nj]) << 4));
#pragma unroll
            for (int mi = 0; mi < MI; mi++)
#pragma unroll
                for (int nj = 0; nj < 2; nj++) {
                    mma_f16(acc[mi][2 * nj][0], acc[mi][2 * nj][1],
                            acc[mi][2 * nj][2], acc[mi][2 * nj][3],
                            af[mi][0], af[mi][1], af[mi][2], af[mi][3],
                            bq[nj][0], bq[nj][2]);
                    mma_f16(acc[mi][2 * nj + 1][0], acc[mi][2 * nj + 1][1],
                            acc[mi][2 * nj + 1][2], acc[mi][2 * nj + 1][3],
                            af[mi][0], af[mi][1], af[mi][2], af[mi][3],
                            bq[nj][1], bq[nj][3]);
                }
        }
    }

#pragma unroll
    for (int mi = 0; mi < MI; mi++) {
        int m = m0 + wm * (BM / 4) + mi * 16 + lr;
#pragma unroll
        for (int ni = 0; ni < 4; ni++) {
            int n = n0 + wn * 32 + ni * 8 + lc * 2;
            if (n + 1 < N) {
                float b0 = S.bias[n], b1 = S.bias[n + 1];
                float v00 = acc[mi][ni][0] + b0, v01 = acc[mi][ni][1] + b1;
                float v10 = acc[mi][ni][2] + b0, v11 = acc[mi][ni][3] + b1;
                if (OUT16) {
                    *(__half2*)(S.Ch + (size_t)m * N + n) = __floats2half2_rn(v00, v01);
                    *(__half2*)(S.Ch + (size_t)(m + 8) * N + n) = __floats2half2_rn(v10, v11);
                } else {
                    *(float2*)(S.Cf + (size_t)m * N + n) = make_float2(v00, v01);
                    *(float2*)(S.Cf + (size_t)(m + 8) * N + n) = make_float2(v10, v11);
                }
            } else if (n < N) {
                float b0 = S.bias[n];
                if (OUT16) {
                    S.Ch[(size_t)m * N + n] = __float2half_rn(acc[mi][ni][0] + b0);
                    S.Ch[(size_t)(m + 8) * N + n] = __float2half_rn(acc[mi][ni][2] + b0);
                } else {
                    S.Cf[(size_t)m * N + n] = acc[mi][ni][0] + b0;
                    S.Cf[(size_t)(m + 8) * N + n] = acc[mi][ni][2] + b0;
                }
            }
        }
    }
}
#define SMEM_LIN(BM) (4 * ((BM) + 128) * 64)

// ===========================================================================
// gemm_lstm16: fused single-step BiLSTM (gates pre-gathered in Wg [3,2000,512])
// out = scale * sig(o)*tanh(sig(i)*tanh(g))  [+ Acc];  fp32 or fp16 out.
// block 128x64x3gates, BK=32, 512 thr (16 warps 4m x 4n), 4-stage cp.async.
// ===========================================================================
#define S_TA (128 * 64)
#define S_TB (192 * 64)
#define S_STRIDE (S_TA + S_TB)
#define SMEM_LSTM (4 * S_STRIDE)

__global__ __launch_bounds__(512, 1) void gemm_lstm16(
    LstmSet s0, LstmSet s1, int M, float scale, int accum, int out16) {
    const int N = 2000, K = 512;
    const LstmSet S = blockIdx.z ? s1 : s0;
    extern __shared__ char sm[];
    const uint32_t smb = (uint32_t)__cvta_generic_to_shared(sm);

    const int tid = threadIdx.x;
    const int wid = tid >> 5, lane = tid & 31;
    const int wm = wid & 3, wn = wid >> 2;
    const int lr = lane >> 2, lc = lane & 3;
    const int m0 = blockIdx.y * 128, n0 = blockIdx.x * 64;

    const int pc = tid & 3;
    const int arow = tid >> 2;
    const __half* srcA = S.A + (size_t)(m0 + arow) * K + pc * 8;
    const uint32_t dA = smb + arow * 64 + ((pc ^ ((arow >> 1) & 3)) << 4);

    const int b1t = tid >> 8, b1r = (tid & 255) >> 2;
    const bool b1ok = (n0 + b1r) < N;
    const __half* srcB1 = S.Wg + (size_t)(b1t * 2000 + (b1ok ? n0 + b1r : 0)) * K + pc * 8;
    const uint32_t dB1 = smb + S_TA + (b1t * 64 + b1r) * 64 + ((pc ^ ((b1r >> 1) & 3)) << 4);

    const bool has2 = tid < 256;
    const int b2r = tid >> 2;
    const bool b2ok = has2 && ((n0 + b2r) < N);
    const __half* srcB2 = S.Wg + (size_t)(2 * 2000 + (b2ok ? n0 + b2r : 0)) * K + pc * 8;
    const uint32_t dB2 = smb + S_TA + (2 * 64 + b2r) * 64 + ((pc ^ ((b2r >> 1) & 3)) << 4);

    const int l15 = lane & 15, hi = lane >> 4;
    uint32_t aOff[2]; int aSwz[2];
#pragma unroll
    for (int mi = 0; mi < 2; mi++) {
        int r = wm * 32 + mi * 16 + l15;
        aOff[mi] = r * 64; aSwz[mi] = (r >> 1) & 3;
    }
    uint32_t bOff[3]; int bSwz;
    {
        int r = wn * 16 + l15;
        bSwz = (r >> 1) & 3;
#pragma unroll
        for (int t = 0; t < 3; t++) bOff[t] = S_TA + (t * 64 + r) * 64;
    }

    float acc[3][2][2][4];
#pragma unroll
    for (int t = 0; t < 3; t++)
#pragma unroll
        for (int mi = 0; mi < 2; mi++)
#pragma unroll
            for (int ni = 0; ni < 2; ni++)
#pragma unroll
                for (int r = 0; r < 4; r++) acc[t][mi][ni][r] = 0.0f;

    const int nt = K >> 5;
    auto LOAD = [&](int s, int kt) {
        const uint32_t so = s * S_STRIDE;
        cpa16(dA + so, srcA + kt, 16);
        cpa16(dB1 + so, srcB1 + kt, b1ok ? 16 : 0);
        if (has2) cpa16(dB2 + so, srcB2 + kt, b2ok ? 16 : 0);
    };

    LOAD(0, 0); cp_commit();
    LOAD(1, 32); cp_commit();
    LOAD(2, 64); cp_commit();

    for (int i = 0; i < nt; i++) {
        cp_wait<2>();
        __syncthreads();
        if (i + 3 < nt) LOAD((i + 3) & 3, (i + 3) << 5);
        cp_commit();

        const uint32_t base = smb + (i & 3) * S_STRIDE;
#pragma unroll
        for (int kc = 0; kc < 4; kc += 2) {
            unsigned af[2][4], bt[3][4];
#pragma unroll
            for (int mi = 0; mi < 2; mi++)
                ldsm4(af[mi][0], af[mi][1], af[mi][2], af[mi][3],
                      base + aOff[mi] + (((kc + hi) ^ aSwz[mi]) << 4));
#pragma unroll
            for (int t = 0; t < 3; t++)
                ldsm4(bt[t][0], bt[t][1], bt[t][2], bt[t][3],
                      base + bOff[t] + (((kc + hi) ^ bSwz) << 4));
#pragma unroll
            for (int t = 0; t < 3; t++)
#pragma unroll
                for (int mi = 0; mi < 2; mi++) {
                    mma_f16(acc[t][mi][0][0], acc[t][mi][0][1],
                            acc[t][mi][0][2], acc[t][mi][0][3],
                            af[mi][0], af[mi][1], af[mi][2], af[mi][3],
                            bt[t][0], bt[t][2]);
                    mma_f16(acc[t][mi][1][0], acc[t][mi][1][1],
                            acc[t][mi][1][2], acc[t][mi][1][3],
                            af[mi][0], af[mi][1], af[mi][2], af[mi][3],
                            bt[t][1], bt[t][3]);
                }
        }
    }

#pragma unroll
    for (int mi = 0; mi < 2; mi++)
#pragma unroll
        for (int ni = 0; ni < 2; ni++) {
            int mA = m0 + wm * 32 + mi * 16 + lr;
            int nA = n0 + wn * 16 + ni * 8 + lc * 2;
#pragma unroll
            for (int r = 0; r < 4; r++) {
                int mm = mA + ((r >= 2) ? 8 : 0);
                int nn = nA + (r & 1);
                if (nn < N) {
                    int d = (nn >= 1000);
                    int base = d * 4000 + (nn - d * 1000);
                    float gi = acc[0][mi][ni][r] + S.bG[base];
                    float gg = acc[1][mi][ni][r] + S.bG[base + 2000];
                    float go = acc[2][mi][ni][r] + S.bG[base + 3000];
                    float cc = sigf(gi) * tanh_fast(gg);
                    float h = sigf(go) * tanh_fast(cc);
                    float o = scale * h;
                    if (accum) o += S.Acc[(size_t)mm * N + nn];
                    if (out16) S.Ch[(size_t)mm * N + nn] = __float2half_rn(o);
                    else       S.Cf[(size_t)mm * N + nn] = o;
                }
            }
        }
}

// ---------------- paired neighbor mean: [1024,24,E] -> [1024,E] --------------
__global__ void mean16(const __half* __restrict__ Z, __half* __restrict__ out) {
    int idx = blockIdx.x * blockDim.x + threadIdx.x;
    if (idx >= 2 * BB * EE) return;
    int bI = idx / EE, n = idx % EE;
    float s = 0.f;
#pragma unroll 4
    for (int j = 0; j < 24; j++) s += __half2float(Z[(size_t)(bI * 24 + j) * EE + n]);
    out[idx] = __float2half_rn(s * (1.0f / 24.0f));
}

// ---------------- 3-way attention combine ------------------------------------
__global__ void attention_kernel(const float* __restrict__ c, const float* __restrict__ u,
                                 const float* __restrict__ p, const float* __restrict__ att,
                                 float* __restrict__ out) {
    int bI = blockIdx.x, tid = threadIdx.x;
    const float* cb = c + (size_t)bI * EE;
    const float* ub = u + (size_t)bI * EE;
    const float* pb = p + (size_t)bI * EE;
    float s0 = 0.f, s1 = 0.f, s2 = 0.f, s3 = 0.f;
    for (int n = tid; n < EE; n += 256) {
        float a0 = att[n], a1 = att[EE + n];
        float cv = cb[n];
        s0 += cv * a0;
        s1 += cv * a1;
        s2 += ub[n] * a1;
        s3 += pb[n] * a1;
    }
    __shared__ float red[4][256];
    red[0][tid] = s0; red[1][tid] = s1; red[2][tid] = s2; red[3][tid] = s3;
    __syncthreads();
    for (int s = 128; s > 0; s >>= 1) {
        if (tid < s) {
#pragma unroll
            for (int q = 0; q < 4; q++) red[q][tid] += red[q][tid + s];
        }
        __syncthreads();
    }
    __shared__ float w[3];
    if (tid == 0) {
        float sc[3];
        sc[0] = red[0][0] + red[1][0];
        sc[1] = red[0][0] + red[2][0];
        sc[2] = red[0][0] + red[3][0];
#pragma unroll
        for (int k = 0; k < 3; k++) sc[k] = sc[k] > 0.f ? sc[k] : 0.01f * sc[k];
        float mx = fmaxf(sc[0], fmaxf(sc[1], sc[2]));
        float e0 = __expf(sc[0] - mx), e1 = __expf(sc[1] - mx), e2 = __expf(sc[2] - mx);
        float inv = 1.0f / (e0 + e1 + e2);
        w[0] = e0 * inv; w[1] = e1 * inv; w[2] = e2 * inv;
    }
    __syncthreads();
    float w0 = w[0], w1 = w[1], w2 = w[2];
    for (int n = tid; n < EE; n += 256)
        out[(size_t)bI * EE + n] = w0 * cb[n] + w1 * ub[n] + w2 * pb[n];
}

// ---------------------------------------------------------------------------
extern "C" void kernel_launch(void* const* d_in, const int* in_sizes, int n_in,
                              void* d_out, int out_size) {
    const float* c_text  = (const float*)d_in[0];
    const float* c_image = (const float*)d_in[1];
    const float* p_text  = (const float*)d_in[2];
    const float* p_image = (const float*)d_in[3];
    const float* u_text  = (const float*)d_in[4];
    const float* u_other = (const float*)d_in[5];
    const float* W_lt = (const float*)d_in[6],  *b_lt = (const float*)d_in[7];
    const float* W_li = (const float*)d_in[8],  *b_li = (const float*)d_in[9];
    const float* W_lo = (const float*)d_in[10], *b_lo = (const float*)d_in[11];
    const float* lstm_t_W = (const float*)d_in[12], *lstm_t_b = (const float*)d_in[13];
    const float* lstm_i_W = (const float*)d_in[14], *lstm_i_b = (const float*)d_in[15];
    const float* lstm_o_W = (const float*)d_in[16], *lstm_o_b = (const float*)d_in[17];
    const float* ua_lin_W = (const float*)d_in[18], *ua_lin_b = (const float*)d_in[19];
    const float* ua_lstm_W = (const float*)d_in[20], *ua_lstm_b = (const float*)d_in[21];
    const float* ua_out_W = (const float*)d_in[22], *ua_out_b = (const float*)d_in[23];
    const float* pa_lin_W = (const float*)d_in[24], *pa_lin_b = (const float*)d_in[25];
    const float* pa_lstm_W = (const float*)d_in[26], *pa_lstm_b = (const float*)d_in[27];
    const float* pa_out_W = (const float*)d_in[28], *pa_out_b = (const float*)d_in[29];
    const float* p_att = (const float*)d_in[30];
    float* out = (float*)d_out;

    __half *in16, *w16, *bufX, *Hp16, *Hu16, *H2, *Hm;
    float *Hc, *Ht32, *uagg, *pagg;
    cudaGetSymbolAddress((void**)&in16, g_in16);
    cudaGetSymbolAddress((void**)&w16,  g_w16);
    cudaGetSymbolAddress((void**)&bufX, g_bufX);
    cudaGetSymbolAddress((void**)&Hc,   g_Hc);
    cudaGetSymbolAddress((void**)&Ht32, g_Ht32);
    cudaGetSymbolAddress((void**)&Hp16, g_Hp16);
    cudaGetSymbolAddress((void**)&Hu16, g_Hu16);
    cudaGetSymbolAddress((void**)&H2,   g_H2);
    cudaGetSymbolAddress((void**)&Hm,   g_Hm);
    cudaGetSymbolAddress((void**)&uagg, g_uagg);
    cudaGetSymbolAddress((void**)&pagg, g_pagg);

    cudaFuncSetAttribute(gemm_lin16<256, true>,
                         cudaFuncAttributeMaxDynamicSharedMemorySize, SMEM_LIN(256));
    cudaFuncSetAttribute(gemm_lin16<128, false>,
                         cudaFuncAttributeMaxDynamicSharedMemorySize, SMEM_LIN(128));
    cudaFuncSetAttribute(gemm_lstm16,
                         cudaFuncAttributeMaxDynamicSharedMemorySize, SMEM_LSTM);

    auto CVT = [&](const float* s, __half* d, int n) {
        cvt16<<<(n / 8 + 255) / 256, 256>>>(s, d, n);
    };
    auto CVTL = [&](const float* W, __half* d) {
        cvt_lstm<<<(3 * 2000 * 512 / 8 + 255) / 256, 256>>>(W, d);
    };

    // ---- weight conversion ----
    CVT(W_lt, w16 + O_WLT, 512 * 768);
    CVT(W_li, w16 + O_WLI, 512 * 2048);
    CVT(W_lo, w16 + O_WLO, 512 * 512);
    CVT(ua_lin_W, w16 + O_UALIN, 512 * 2000);
    CVT(pa_lin_W, w16 + O_PALIN, 512 * 2000);
    CVT(ua_out_W, w16 + O_UAOUT, 2000 * 2000);
    CVT(pa_out_W, w16 + O_PAOUT, 2000 * 2000);
    CVTL(lstm_t_W,  w16 + O_LT);
    CVTL(lstm_i_W,  w16 + O_LI);
    CVTL(lstm_o_W,  w16 + O_LO);
    CVTL(ua_lstm_W, w16 + O_UAL);
    CVTL(pa_lstm_W, w16 + O_PAL);

    // ---- input conversion (batched arenas) ----
    CVT(c_text, in16 + I_TEXT, BB * 768);
    CVT(p_text, in16 + I_TEXT + BB * 768, MPU * 768);
    CVT(u_text, in16 + I_TEXT + (BB + MPU) * 768, MPU * 768);
    CVT(c_image, in16 + I_IMG, BB * 2048);
    CVT(p_image, in16 + I_IMG + BB * 2048, MPU * 2048);
    CVT(u_other, in16 + I_OTH, MPU * 512);

    auto LIN = [&](LinSet s, int M, int N, int K) {
        dim3 g((N + 127) / 128, M / 256, 1);
        gemm_lin16<256, true><<<g, 512, SMEM_LIN(256)>>>(s, s, M, N, K);
    };
    auto LIN2 = [&](LinSet a, LinSet b, int M, int N, int K) {
        dim3 g((N + 127) / 128, M / 256, 2);
        gemm_lin16<256, true><<<g, 512, SMEM_LIN(256)>>>(a, b, M, N, K);
    };
    auto OUT2 = [&](LinSet a, LinSet b, int M, int N, int K) {
        dim3 g((N + 127) / 128, M / 128, 2);
        gemm_lin16<128, false><<<g, 512, SMEM_LIN(128)>>>(a, b, M, N, K);
    };
    auto LSTM = [&](LstmSet s, int M, float scale, int accum, int out16) {
        dim3 g((EE + 63) / 64, M / 128, 1);
        gemm_lstm16<<<g, 512, SMEM_LSTM>>>(s, s, M, scale, accum, out16);
    };
    auto LSTM2 = [&](LstmSet a, LstmSet b, int M, float scale, int accum, int out16) {
        dim3 g((EE + 63) / 64, M / 128, 2);
        gemm_lstm16<<<g, 512, SMEM_LSTM>>>(a, b, M, scale, accum, out16);
    };

    // ---- batched per-type stage ----
    LIN({in16 + I_TEXT, w16 + O_WLT, b_lt, nullptr, bufX + X_TEXT}, MT, 512, 768);
    LIN({in16 + I_IMG,  w16 + O_WLI, b_li, nullptr, bufX + X_IMG},  MI2, 512, 2048);
    LIN({in16 + I_OTH,  w16 + O_WLO, b_lo, nullptr, bufX + X_OTH},  MPU, 512, 512);

    LSTM({bufX + X_TEXT, w16 + O_LT, lstm_t_b, nullptr, Ht32, nullptr},
         MT, 0.5f, 0, 0);
    LSTM({bufX + X_IMG, w16 + O_LI, lstm_i_b, Ht32, Ht32, nullptr},
         MI2, 0.5f, 1, 0);
    LSTM({bufX + X_OTH, w16 + O_LO, lstm_o_b, Ht32 + (size_t)MI2 * EE,
          nullptr, Hu16}, MPU, 0.5f, 1, 1);

    extract_kernel<<<(MI2 * EE / 4 + 255) / 256, 256>>>(Ht32, Hc, Hp16);

    // ---- paired u/p aggregation ----
    LIN2({Hu16, w16 + O_UALIN, ua_lin_b, nullptr, bufX},
         {Hp16, w16 + O_PALIN, pa_lin_b, nullptr, bufX + (size_t)MPU * 512},
         MPU, 512, 2000);
    LSTM2({bufX, w16 + O_UAL, ua_lstm_b, nullptr, nullptr, H2},
          {bufX + (size_t)MPU * 512, w16 + O_PAL, pa_lstm_b, nullptr, nullptr,
           H2 + (size_t)MPU * EE},
          MPU, 1.0f, 0, 1);
    mean16<<<(2 * BB * EE + 255) / 256, 256>>>(H2, Hm);
    OUT2({Hm, w16 + O_UAOUT, ua_out_b, uagg, nullptr},
         {Hm + (size_t)BB * EE, w16 + O_PAOUT, pa_out_b, pagg, nullptr},
         BB, 2000, 2000);

    // ---- attention combine ----
    attention_kernel<<<BB, 256>>>(Hc, uagg, pagg, p_att, out);
}

// round 8
// speedup vs baseline: 4.6543x; 1.1117x over previous
#include <cuda_runtime.h>
#include <cuda_fp16.h>
#include <cstdint>

// ---------------------------------------------------------------------------
// Het_GNN forward — fp16 mma.sync, 256-thread CTAs @ 2 CTAs/SM.
// ---------------------------------------------------------------------------
#define BB   512
#define MPU  12288
#define MT   25088      // text rows: c(512) + p(12288) + u(12288)
#define MI2  12800      // image rows: c(512) + p(12288)
#define EE   2000

// ---------------- scratch (device globals) ----------------------------------
__device__ __half g_in16 [51773440];
__device__ __half g_w16  [27111936];
__device__ __half g_bufX [25690112];
__device__ float  g_Ht32 [MT * EE];
__device__ float  g_Hc   [BB  * EE];
__device__ __half g_Hp16 [MPU * EE];
__device__ __half g_Hu16 [MPU * EE];
__device__ __half g_H2   [2 * MPU * EE];
__device__ __half g_Hm   [2 * BB * EE];
__device__ float  g_uagg [BB * EE];
__device__ float  g_pagg [BB * EE];

// arena offsets (halves)
#define I_TEXT 0
#define I_IMG  19267584
#define I_OTH  45481984
#define X_TEXT 0
#define X_IMG  12845056
#define X_OTH  19398656
#define O_WLT   0
#define O_WLI   393216
#define O_WLO   1441792
#define O_LT    1703936
#define O_LI    4775936
#define O_LO    7847936
#define O_UAL   10919936
#define O_PAL   13991936
#define O_UALIN 17063936
#define O_PALIN 18087936
#define O_UAOUT 19111936
#define O_PAOUT 23111936

// ---------------- helpers ----------------------------------------------------
__device__ __forceinline__ float sigf(float x) { return 1.0f / (1.0f + __expf(-x)); }
__device__ __forceinline__ float tanh_fast(float x) {
    return 2.0f / (1.0f + __expf(-2.0f * x)) - 1.0f;
}
__device__ __forceinline__ void mma_f16(float& d0, float& d1, float& d2, float& d3,
                                        unsigned a0, unsigned a1, unsigned a2, unsigned a3,
                                        unsigned b0, unsigned b1) {
    asm volatile(
        "mma.sync.aligned.m16n8k16.row.col.f32.f16.f16.f32 "
        "{%0,%1,%2,%3}, {%4,%5,%6,%7}, {%8,%9}, {%0,%1,%2,%3};"
        : "+f"(d0), "+f"(d1), "+f"(d2), "+f"(d3)
        : "r"(a0), "r"(a1), "r"(a2), "r"(a3), "r"(b0), "r"(b1));
}
__device__ __forceinline__ void ldsm4(unsigned& r0, unsigned& r1, unsigned& r2,
                                      unsigned& r3, uint32_t a) {
    asm volatile("ldmatrix.sync.aligned.m8n8.x4.shared.b16 {%0,%1,%2,%3}, [%4];"
                 : "=r"(r0), "=r"(r1), "=r"(r2), "=r"(r3) : "r"(a));
}
__device__ __forceinline__ void cpa16(uint32_t dst, const void* src, int srcbytes) {
    asm volatile("cp.async.ca.shared.global [%0], [%1], 16, %2;"
                 :: "r"(dst), "l"(src), "r"(srcbytes) : "memory");
}
__device__ __forceinline__ void cp_commit() {
    asm volatile("cp.async.commit_group;" ::: "memory");
}
template<int N>
__device__ __forceinline__ void cp_wait() {
    asm volatile("cp.async.wait_group %0;" :: "n"(N) : "memory");
}
__device__ __forceinline__ int gather_row(int n, int t) {
    int d = (n >= 1000);
    int toff = (t == 0) ? 0 : (t == 1 ? 2000 : 3000);
    return d * 4000 + toff + (n - d * 1000);
}

// ---------------- conversion kernels -----------------------------------------
__global__ void cvt16(const float* __restrict__ src, __half* __restrict__ dst, int n) {
    int i = (blockIdx.x * blockDim.x + threadIdx.x) * 8;
    if (i >= n) return;
    float4 a = *(const float4*)(src + i);
    float4 b = *(const float4*)(src + i + 4);
    __half2 h[4] = { __floats2half2_rn(a.x, a.y), __floats2half2_rn(a.z, a.w),
                     __floats2half2_rn(b.x, b.y), __floats2half2_rn(b.z, b.w) };
    *(uint4*)(dst + i) = *(uint4*)h;
}
__global__ void cvt_lstm(const float* __restrict__ W, __half* __restrict__ dst) {
    int idx = (blockIdx.x * blockDim.x + threadIdx.x) * 8;
    if (idx >= 3 * 2000 * 512) return;
    int k = idx & 511;
    int n = (idx >> 9) % 2000;
    int t = idx / (2000 * 512);
    const float* s = W + (size_t)gather_row(n, t) * 512 + k;
    float4 a = *(const float4*)s;
    float4 b = *(const float4*)(s + 4);
    __half2 h[4] = { __floats2half2_rn(a.x, a.y), __floats2half2_rn(a.z, a.w),
                     __floats2half2_rn(b.x, b.y), __floats2half2_rn(b.z, b.w) };
    *(uint4*)(dst + idx) = *(uint4*)h;
}
__global__ void extract_kernel(const float* __restrict__ Ht, float* __restrict__ Hc,
                               __half* __restrict__ Hp) {
    int i = (blockIdx.x * blockDim.x + threadIdx.x) * 4;
    if (i >= MI2 * EE) return;
    float4 v = *(const float4*)(Ht + i);
    int r = i / EE;
    if (r < BB) {
        *(float4*)(Hc + i) = v;
    } else {
        __half2 h[2] = { __floats2half2_rn(v.x, v.y), __floats2half2_rn(v.z, v.w) };
        *(uint2*)(Hp + (i - BB * EE)) = *(uint2*)h;
    }
}

// ---------------- arg structs for z-paired launches ---------------------------
struct LinSet  { const __half* A; const __half* W; const float* bias;
                 float* Cf; __half* Ch; };
struct LstmSet { const __half* A; const __half* Wg; const float* bG;
                 const float* Acc; float* Cf; __half* Ch; };

// ===========================================================================
// gemm_lin16<OUT16>: C[M,N] = A[M,K] @ W[N,K]^T + bias
// BM=128, BN=128, 256 thr (8 warps 2m x 4n), warp tile 64x32.
// 4-stage cp.async; chunk-swizzle (chunk c of row m at c^((m>>1)&3)); ldmatrix.
// 2 CTAs/SM (regs<=128, smem 64KB).
// ===========================================================================
#define L_TA (128 * 64)
#define L_STRIDE (2 * L_TA)
#define SMEM_LIN (4 * L_STRIDE)

template<bool OUT16>
__global__ __launch_bounds__(256, 2) void gemm_lin16(
    LinSet s0, LinSet s1, int M, int N, int K) {
    const LinSet S = blockIdx.z ? s1 : s0;
    extern __shared__ char sm[];
    const uint32_t smb = (uint32_t)__cvta_generic_to_shared(sm);

    const int tid = threadIdx.x;
    const int wid = tid >> 5, lane = tid & 31;
    const int wm = wid & 1, wn = wid >> 1;          // 2m x 4n
    const int lr = lane >> 2, lc = lane & 3;
    const int m0 = blockIdx.y * 128, n0 = blockIdx.x * 128;

    // producer: 4 slots/thread: p=0,1 -> A rows r, r+64 ; p=2,3 -> B rows r, r+64
    const int prow = tid >> 2, pc = tid & 3;
    const __half* srcA[2];
    uint32_t dA[2];
#pragma unroll
    for (int p = 0; p < 2; p++) {
        int r = prow + 64 * p;
        srcA[p] = S.A + (size_t)(m0 + r) * K + pc * 8;
        dA[p] = smb + r * 64 + ((pc ^ ((r >> 1) & 3)) << 4);
    }
    const __half* srcB[2];
    uint32_t dB[2];
    bool brOK[2];
#pragma unroll
    for (int p = 0; p < 2; p++) {
        int r = prow + 64 * p;
        brOK[p] = (n0 + r) < N;
        srcB[p] = S.W + (size_t)(brOK[p] ? (n0 + r) : 0) * K + pc * 8;
        dB[p] = smb + L_TA + r * 64 + ((pc ^ ((r >> 1) & 3)) << 4);
    }

    const int l15 = lane & 15, hi = lane >> 4;
    uint32_t aOff[4], bOff[2];
    int aSwz[4], bSwz[2];
#pragma unroll
    for (int mi = 0; mi < 4; mi++) {
        int r = wm * 64 + mi * 16 + l15;
        aOff[mi] = r * 64; aSwz[mi] = (r >> 1) & 3;
    }
#pragma unroll
    for (int nj = 0; nj < 2; nj++) {
        int r = wn * 32 + nj * 16 + l15;
        bOff[nj] = L_TA + r * 64; bSwz[nj] = (r >> 1) & 3;
    }

    float acc[4][4][4];
#pragma unroll
    for (int mi = 0; mi < 4; mi++)
#pragma unroll
        for (int ni = 0; ni < 4; ni++)
#pragma unroll
            for (int r = 0; r < 4; r++) acc[mi][ni][r] = 0.0f;

    const int nt = (K + 31) >> 5;
    auto LOAD = [&](int s, int kt) {
        const uint32_t so = s * L_STRIDE;
        const int kb = (kt + pc * 8 + 8 <= K) ? 16 : 0;
#pragma unroll
        for (int p = 0; p < 2; p++) cpa16(dA[p] + so, srcA[p] + kt, kb);
#pragma unroll
        for (int p = 0; p < 2; p++) cpa16(dB[p] + so, srcB[p] + kt, brOK[p] ? kb : 0);
    };

    LOAD(0, 0); cp_commit();
    LOAD(1, 32); cp_commit();
    LOAD(2, 64); cp_commit();

    for (int i = 0; i < nt; i++) {
        cp_wait<2>();
        __syncthreads();
        if (i + 3 < nt) LOAD((i + 3) & 3, (i + 3) << 5);
        cp_commit();

        const uint32_t base = smb + (i & 3) * L_STRIDE;
#pragma unroll
        for (int kc = 0; kc < 4; kc += 2) {
            unsigned af[4][4], bq[2][4];
#pragma unroll
            for (int mi = 0; mi < 4; mi++)
                ldsm4(af[mi][0], af[mi][1], af[mi][2], af[mi][3],
                      base + aOff[mi] + (((kc + hi) ^ aSwz[mi]) << 4));
#pragma unroll
            for (int nj = 0; nj < 2; nj++)
                ldsm4(bq[nj][0], bq[nj][1], bq[nj][2], bq[nj][3],
                      base + bOff[nj] + (((kc + hi) ^ bSwz[nj]) << 4));
#pragma unroll
            for (int mi = 0; mi < 4; mi++)
#pragma unroll
                for (int nj = 0; nj < 2; nj++) {
                    mma_f16(acc[mi][2 * nj][0], acc[mi][2 * nj][1],
                            acc[mi][2 * nj][2], acc[mi][2 * nj][3],
                            af[mi][0], af[mi][1], af[mi][2], af[mi][3],
                            bq[nj][0], bq[nj][2]);
                    mma_f16(acc[mi][2 * nj + 1][0], acc[mi][2 * nj + 1][1],
                            acc[mi][2 * nj + 1][2], acc[mi][2 * nj + 1][3],
                            af[mi][0], af[mi][1], af[mi][2], af[mi][3],
                            bq[nj][1], bq[nj][3]);
                }
        }
    }

#pragma unroll
    for (int mi = 0; mi < 4; mi++) {
        int m = m0 + wm * 64 + mi * 16 + lr;
#pragma unroll
        for (int ni = 0; ni < 4; ni++) {
            int n = n0 + wn * 32 + ni * 8 + lc * 2;
            if (n + 1 < N) {
                float b0 = S.bias[n], b1 = S.bias[n + 1];
                float v00 = acc[mi][ni][0] + b0, v01 = acc[mi][ni][1] + b1;
                float v10 = acc[mi][ni][2] + b0, v11 = acc[mi][ni][3] + b1;
                if (OUT16) {
                    *(__half2*)(S.Ch + (size_t)m * N + n) = __floats2half2_rn(v00, v01);
                    *(__half2*)(S.Ch + (size_t)(m + 8) * N + n) = __floats2half2_rn(v10, v11);
                } else {
                    *(float2*)(S.Cf + (size_t)m * N + n) = make_float2(v00, v01);
                    *(float2*)(S.Cf + (size_t)(m + 8) * N + n) = make_float2(v10, v11);
                }
            } else if (n < N) {
                float b0 = S.bias[n];
                if (OUT16) {
                    S.Ch[(size_t)m * N + n] = __float2half_rn(acc[mi][ni][0] + b0);
                    S.Ch[(size_t)(m + 8) * N + n] = __float2half_rn(acc[mi][ni][2] + b0);
                } else {
                    S.Cf[(size_t)m * N + n] = acc[mi][ni][0] + b0;
                    S.Cf[(size_t)(m + 8) * N + n] = acc[mi][ni][2] + b0;
                }
            }
        }
    }
}

// ===========================================================================
// gemm_lstm16: fused single-step BiLSTM (gates pre-gathered in Wg [3,2000,512])
// out = scale * sig(o)*tanh(sig(i)*tanh(g))  [+ Acc];  fp32 or fp16 out.
// BM=64, BN=64x3 gates, 256 thr (8 warps 2m x 4n), warp 32x16x3. K=512.
// 2 CTAs/SM (regs<=128, smem 64KB).
// ===========================================================================
#define S_TA (64 * 64)
#define S_STRIDE (S_TA + 192 * 64)
#define SMEM_LSTM (4 * S_STRIDE)

__global__ __launch_bounds__(256, 2) void gemm_lstm16(
    LstmSet s0, LstmSet s1, int M, float scale, int accum, int out16) {
    const int N = 2000, K = 512;
    const LstmSet S = blockIdx.z ? s1 : s0;
    extern __shared__ char sm[];
    const uint32_t smb = (uint32_t)__cvta_generic_to_shared(sm);

    const int tid = threadIdx.x;
    const int wid = tid >> 5, lane = tid & 31;
    const int wm = wid & 1, wn = wid >> 1;          // 2m x 4n
    const int lr = lane >> 2, lc = lane & 3;
    const int m0 = blockIdx.y * 64, n0 = blockIdx.x * 64;

    // producer: p=0 -> A row r (0..63); p=1..3 -> gate p-1, row r
    const int prow = tid >> 2, pc = tid & 3;
    const __half* srcA = S.A + (size_t)(m0 + prow) * K + pc * 8;
    const uint32_t dAp = smb + prow * 64 + ((pc ^ ((prow >> 1) & 3)) << 4);
    const bool bOK = (n0 + prow) < N;
    const __half* srcBg[3];
    uint32_t dBg[3];
#pragma unroll
    for (int t = 0; t < 3; t++) {
        srcBg[t] = S.Wg + (size_t)(t * 2000 + (bOK ? n0 + prow : 0)) * K + pc * 8;
        dBg[t] = smb + S_TA + (t * 64 + prow) * 64 + ((pc ^ ((prow >> 1) & 3)) << 4);
    }

    const int l15 = lane & 15, hi = lane >> 4;
    uint32_t aOff[2]; int aSwz[2];
#pragma unroll
    for (int mi = 0; mi < 2; mi++) {
        int r = wm * 32 + mi * 16 + l15;
        aOff[mi] = r * 64; aSwz[mi] = (r >> 1) & 3;
    }
    uint32_t bOff[3]; int bSwz;
    {
        int r = wn * 16 + l15;
        bSwz = (r >> 1) & 3;
#pragma unroll
        for (int t = 0; t < 3; t++) bOff[t] = S_TA + (t * 64 + r) * 64;
    }

    float acc[3][2][2][4];
#pragma unroll
    for (int t = 0; t < 3; t++)
#pragma unroll
        for (int mi = 0; mi < 2; mi++)
#pragma unroll
            for (int ni = 0; ni < 2; ni++)
#pragma unroll
                for (int r = 0; r < 4; r++) acc[t][mi][ni][r] = 0.0f;

    const int nt = K >> 5;
    auto LOAD = [&](int s, int kt) {
        const uint32_t so = s * S_STRIDE;
        cpa16(dAp + so, srcA + kt, 16);
#pragma unroll
        for (int t = 0; t < 3; t++) cpa16(dBg[t] + so, srcBg[t] + kt, bOK ? 16 : 0);
    };

    LOAD(0, 0); cp_commit();
    LOAD(1, 32); cp_commit();
    LOAD(2, 64); cp_commit();

    for (int i = 0; i < nt; i++) {
        cp_wait<2>();
        __syncthreads();
        if (i + 3 < nt) LOAD((i + 3) & 3, (i + 3) << 5);
        cp_commit();

        const uint32_t base = smb + (i & 3) * S_STRIDE;
#pragma unroll
        for (int kc = 0; kc < 4; kc += 2) {
            unsigned af[2][4], bt[3][4];
#pragma unroll
            for (int mi = 0; mi < 2; mi++)
                ldsm4(af[mi][0], af[mi][1], af[mi][2], af[mi][3],
                      base + aOff[mi] + (((kc + hi) ^ aSwz[mi]) << 4));
#pragma unroll
            for (int t = 0; t < 3; t++)
                ldsm4(bt[t][0], bt[t][1], bt[t][2], bt[t][3],
                      base + bOff[t] + (((kc + hi) ^ bSwz) << 4));
#pragma unroll
            for (int t = 0; t < 3; t++)
#pragma unroll
                for (int mi = 0; mi < 2; mi++) {
                    mma_f16(acc[t][mi][0][0], acc[t][mi][0][1],
                            acc[t][mi][0][2], acc[t][mi][0][3],
                            af[mi][0], af[mi][1], af[mi][2], af[mi][3],
                            bt[t][0], bt[t][2]);
                    mma_f16(acc[t][mi][1][0], acc[t][mi][1][1],
                            acc[t][mi][1][2], acc[t][mi][1][3],
                            af[mi][0], af[mi][1], af[mi][2], af[mi][3],
                            bt[t][1], bt[t][3]);
                }
        }
    }

#pragma unroll
    for (int mi = 0; mi < 2; mi++)
#pragma unroll
        for (int ni = 0; ni < 2; ni++) {
            int mA = m0 + wm * 32 + mi * 16 + lr;
            int nA = n0 + wn * 16 + ni * 8 + lc * 2;
#pragma unroll
            for (int r = 0; r < 4; r++) {
                int mm = mA + ((r >= 2) ? 8 : 0);
                int nn = nA + (r & 1);
                if (nn < N) {
                    int d = (nn >= 1000);
                    int base = d * 4000 + (nn - d * 1000);
                    float gi = acc[0][mi][ni][r] + S.bG[base];
                    float gg = acc[1][mi][ni][r] + S.bG[base + 2000];
                    float go = acc[2][mi][ni][r] + S.bG[base + 3000];
                    float cc = sigf(gi) * tanh_fast(gg);
                    float h = sigf(go) * tanh_fast(cc);
                    float o = scale * h;
                    if (accum) o += S.Acc[(size_t)mm * N + nn];
                    if (out16) S.Ch[(size_t)mm * N + nn] = __float2half_rn(o);
                    else       S.Cf[(size_t)mm * N + nn] = o;
                }
            }
        }
}

// ---------------- paired neighbor mean: [1024,24,E] -> [1024,E] --------------
__global__ void mean16(const __half* __restrict__ Z, __half* __restrict__ out) {
    int idx = blockIdx.x * blockDim.x + threadIdx.x;
    if (idx >= 2 * BB * EE) return;
    int bI = idx / EE, n = idx % EE;
    float s = 0.f;
#pragma unroll 4
    for (int j = 0; j < 24; j++) s += __half2float(Z[(size_t)(bI * 24 + j) * EE + n]);
    out[idx] = __float2half_rn(s * (1.0f / 24.0f));
}

// ---------------- 3-way attention combine ------------------------------------
__global__ void attention_kernel(const float* __restrict__ c, const float* __restrict__ u,
                                 const float* __restrict__ p, const float* __restrict__ att,
                                 float* __restrict__ out) {
    int bI = blockIdx.x, tid = threadIdx.x;
    const float* cb = c + (size_t)bI * EE;
    const float* ub = u + (size_t)bI * EE;
    const float* pb = p + (size_t)bI * EE;
    float s0 = 0.f, s1 = 0.f, s2 = 0.f, s3 = 0.f;
    for (int n = tid; n < EE; n += 256) {
        float a0 = att[n], a1 = att[EE + n];
        float cv = cb[n];
        s0 += cv * a0;
        s1 += cv * a1;
        s2 += ub[n] * a1;
        s3 += pb[n] * a1;
    }
    __shared__ float red[4][256];
    red[0][tid] = s0; red[1][tid] = s1; red[2][tid] = s2; red[3][tid] = s3;
    __syncthreads();
    for (int s = 128; s > 0; s >>= 1) {
        if (tid < s) {
#pragma unroll
            for (int q = 0; q < 4; q++) red[q][tid] += red[q][tid + s];
        }
        __syncthreads();
    }
    __shared__ float w[3];
    if (tid == 0) {
        float sc[3];
        sc[0] = red[0][0] + red[1][0];
        sc[1] = red[0][0] + red[2][0];
        sc[2] = red[0][0] + red[3][0];
#pragma unroll
        for (int k = 0; k < 3; k++) sc[k] = sc[k] > 0.f ? sc[k] : 0.01f * sc[k];
        float mx = fmaxf(sc[0], fmaxf(sc[1], sc[2]));
        float e0 = __expf(sc[0] - mx), e1 = __expf(sc[1] - mx), e2 = __expf(sc[2] - mx);
        float inv = 1.0f / (e0 + e1 + e2);
        w[0] = e0 * inv; w[1] = e1 * inv; w[2] = e2 * inv;
    }
    __syncthreads();
    float w0 = w[0], w1 = w[1], w2 = w[2];
    for (int n = tid; n < EE; n += 256)
        out[(size_t)bI * EE + n] = w0 * cb[n] + w1 * ub[n] + w2 * pb[n];
}

// ---------------------------------------------------------------------------
extern "C" void kernel_launch(void* const* d_in, const int* in_sizes, int n_in,
                              void* d_out, int out_size) {
    const float* c_text  = (const float*)d_in[0];
    const float* c_image = (const float*)d_in[1];
    const float* p_text  = (const float*)d_in[2];
    const float* p_image = (const float*)d_in[3];
    const float* u_text  = (const float*)d_in[4];
    const float* u_other = (const float*)d_in[5];
    const float* W_lt = (const float*)d_in[6],  *b_lt = (const float*)d_in[7];
    const float* W_li = (const float*)d_in[8],  *b_li = (const float*)d_in[9];
    const float* W_lo = (const float*)d_in[10], *b_lo = (const float*)d_in[11];
    const float* lstm_t_W = (const float*)d_in[12], *lstm_t_b = (const float*)d_in[13];
    const float* lstm_i_W = (const float*)d_in[14], *lstm_i_b = (const float*)d_in[15];
    const float* lstm_o_W = (const float*)d_in[16], *lstm_o_b = (const float*)d_in[17];
    const float* ua_lin_W = (const float*)d_in[18], *ua_lin_b = (const float*)d_in[19];
    const float* ua_lstm_W = (const float*)d_in[20], *ua_lstm_b = (const float*)d_in[21];
    const float* ua_out_W = (const float*)d_in[22], *ua_out_b = (const float*)d_in[23];
    const float* pa_lin_W = (const float*)d_in[24], *pa_lin_b = (const float*)d_in[25];
    const float* pa_lstm_W = (const float*)d_in[26], *pa_lstm_b = (const float*)d_in[27];
    const float* pa_out_W = (const float*)d_in[28], *pa_out_b = (const float*)d_in[29];
    const float* p_att = (const float*)d_in[30];
    float* out = (float*)d_out;

    __half *in16, *w16, *bufX, *Hp16, *Hu16, *H2, *Hm;
    float *Hc, *Ht32, *uagg, *pagg;
    cudaGetSymbolAddress((void**)&in16, g_in16);
    cudaGetSymbolAddress((void**)&w16,  g_w16);
    cudaGetSymbolAddress((void**)&bufX, g_bufX);
    cudaGetSymbolAddress((void**)&Hc,   g_Hc);
    cudaGetSymbolAddress((void**)&Ht32, g_Ht32);
    cudaGetSymbolAddress((void**)&Hp16, g_Hp16);
    cudaGetSymbolAddress((void**)&Hu16, g_Hu16);
    cudaGetSymbolAddress((void**)&H2,   g_H2);
    cudaGetSymbolAddress((void**)&Hm,   g_Hm);
    cudaGetSymbolAddress((void**)&uagg, g_uagg);
    cudaGetSymbolAddress((void**)&pagg, g_pagg);

    cudaFuncSetAttribute(gemm_lin16<true>,
                         cudaFuncAttributeMaxDynamicSharedMemorySize, SMEM_LIN);
    cudaFuncSetAttribute(gemm_lin16<false>,
                         cudaFuncAttributeMaxDynamicSharedMemorySize, SMEM_LIN);
    cudaFuncSetAttribute(gemm_lstm16,
                         cudaFuncAttributeMaxDynamicSharedMemorySize, SMEM_LSTM);

    auto CVT = [&](const float* s, __half* d, int n) {
        cvt16<<<(n / 8 + 255) / 256, 256>>>(s, d, n);
    };
    auto CVTL = [&](const float* W, __half* d) {
        cvt_lstm<<<(3 * 2000 * 512 / 8 + 255) / 256, 256>>>(W, d);
    };

    // ---- weight conversion ----
    CVT(W_lt, w16 + O_WLT, 512 * 768);
    CVT(W_li, w16 + O_WLI, 512 * 2048);
    CVT(W_lo, w16 + O_WLO, 512 * 512);
    CVT(ua_lin_W, w16 + O_UALIN, 512 * 2000);
    CVT(pa_lin_W, w16 + O_PALIN, 512 * 2000);
    CVT(ua_out_W, w16 + O_UAOUT, 2000 * 2000);
    CVT(pa_out_W, w16 + O_PAOUT, 2000 * 2000);
    CVTL(lstm_t_W,  w16 + O_LT);
    CVTL(lstm_i_W,  w16 + O_LI);
    CVTL(lstm_o_W,  w16 + O_LO);
    CVTL(ua_lstm_W, w16 + O_UAL);
    CVTL(pa_lstm_W, w16 + O_PAL);

    // ---- input conversion (batched arenas) ----
    CVT(c_text, in16 + I_TEXT, BB * 768);
    CVT(p_text, in16 + I_TEXT + BB * 768, MPU * 768);
    CVT(u_text, in16 + I_TEXT + (BB + MPU) * 768, MPU * 768);
    CVT(c_image, in16 + I_IMG, BB * 2048);
    CVT(p_image, in16 + I_IMG + BB * 2048, MPU * 2048);
    CVT(u_other, in16 + I_OTH, MPU * 512);

    auto LIN = [&](LinSet s, int M, int N, int K) {
        dim3 g((N + 127) / 128, M / 128, 1);
        gemm_lin16<true><<<g, 256, SMEM_LIN>>>(s, s, M, N, K);
    };
    auto LIN2 = [&](LinSet a, LinSet b, int M, int N, int K) {
        dim3 g((N + 127) / 128, M / 128, 2);
        gemm_lin16<true><<<g, 256, SMEM_LIN>>>(a, b, M, N, K);
    };
    auto OUT2 = [&](LinSet a, LinSet b, int M, int N, int K) {
        dim3 g((N + 127) / 128, M / 128, 2);
        gemm_lin16<false><<<g, 256, SMEM_LIN>>>(a, b, M, N, K);
    };
    auto LSTM = [&](LstmSet s, int M, float scale, int accum, int out16) {
        dim3 g((EE + 63) / 64, M / 64, 1);
        gemm_lstm16<<<g, 256, SMEM_LSTM>>>(s, s, M, scale, accum, out16);
    };
    auto LSTM2 = [&](LstmSet a, LstmSet b, int M, float scale, int accum, int out16) {
        dim3 g((EE + 63) / 64, M / 64, 2);
        gemm_lstm16<<<g, 256, SMEM_LSTM>>>(a, b, M, scale, accum, out16);
    };

    // ---- batched per-type stage ----
    LIN({in16 + I_TEXT, w16 + O_WLT, b_lt, nullptr, bufX + X_TEXT}, MT, 512, 768);
    LIN({in16 + I_IMG,  w16 + O_WLI, b_li, nullptr, bufX + X_IMG},  MI2, 512, 2048);
    LIN({in16 + I_OTH,  w16 + O_WLO, b_lo, nullptr, bufX + X_OTH},  MPU, 512, 512);

    LSTM({bufX + X_TEXT, w16 + O_LT, lstm_t_b, nullptr, Ht32, nullptr},
         MT, 0.5f, 0, 0);
    LSTM({bufX + X_IMG, w16 + O_LI, lstm_i_b, Ht32, Ht32, nullptr},
         MI2, 0.5f, 1, 0);
    LSTM({bufX + X_OTH, w16 + O_LO, lstm_o_b, Ht32 + (size_t)MI2 * EE,
          nullptr, Hu16}, MPU, 0.5f, 1, 1);

    extract_kernel<<<(MI2 * EE / 4 + 255) / 256, 256>>>(Ht32, Hc, Hp16);

    // ---- paired u/p aggregation ----
    LIN2({Hu16, w16 + O_UALIN, ua_lin_b, nullptr, bufX},
         {Hp16, w16 + O_PALIN, pa_lin_b, nullptr, bufX + (size_t)MPU * 512},
         MPU, 512, 2000);
    LSTM2({bufX, w16 + O_UAL, ua_lstm_b, nullptr, nullptr, H2},
          {bufX + (size_t)MPU * 512, w16 + O_PAL, pa_lstm_b, nullptr, nullptr,
           H2 + (size_t)MPU * EE},
          MPU, 1.0f, 0, 1);
    mean16<<<(2 * BB * EE + 255) / 256, 256>>>(H2, Hm);
    OUT2({Hm, w16 + O_UAOUT, ua_out_b, uagg, nullptr},
         {Hm + (size_t)BB * EE, w16 + O_PAOUT, pa_out_b, pagg, nullptr},
         BB, 2000, 2000);

    // ---- attention combine ----
    attention_kernel<<<BB, 256>>>(Hc, uagg, pagg, p_att, out);
}

// round 9
// speedup vs baseline: 4.9691x; 1.0676x over previous
#include <cuda_runtime.h>
#include <cuda_fp16.h>
#include <cstdint>

// ---------------------------------------------------------------------------
// Het_GNN forward — fp16 mma.sync, BK=64 3-stage pipeline, 2 CTAs/SM,
// fused split-epilogue, collapsed launches (11 total).
// ---------------------------------------------------------------------------
#define BB   512
#define MPU  12288
#define MT   25088      // text rows: c(512) + p(12288) + u(12288)
#define MI2  12800      // image rows: c(512) + p(12288)
#define EE   2000

// ---------------- scratch (device globals) ----------------------------------
__device__ __half g_in16 [51773440];
__device__ __half g_w16  [27111936];
__device__ __half g_bufX [25690112];
__device__ float  g_Ht32 [MT * EE];
__device__ float  g_Hc   [BB  * EE];
__device__ __half g_Hp16 [MPU * EE];
__device__ __half g_Hu16 [MPU * EE];
__device__ __half g_H2   [2 * MPU * EE];
__device__ __half g_Hm   [2 * BB * EE];
__device__ float  g_uagg [BB * EE];
__device__ float  g_pagg [BB * EE];

// arena offsets (halves)
#define I_TEXT 0
#define I_IMG  19267584
#define I_OTH  45481984
#define X_TEXT 0
#define X_IMG  12845056
#define X_OTH  19398656
#define O_WLT   0
#define O_WLI   393216
#define O_WLO   1441792
#define O_LT    1703936      // 5 lstm gathers, stride 3072000
#define O_UALIN 17063936
#define O_PALIN 18087936
#define O_UAOUT 19111936
#define O_PAOUT 23111936

// ---------------- helpers ----------------------------------------------------
__device__ __forceinline__ float sigf(float x) { return 1.0f / (1.0f + __expf(-x)); }
__device__ __forceinline__ float tanh_fast(float x) {
    return 2.0f / (1.0f + __expf(-2.0f * x)) - 1.0f;
}
__device__ __forceinline__ void mma_f16(float& d0, float& d1, float& d2, float& d3,
                                        unsigned a0, unsigned a1, unsigned a2, unsigned a3,
                                        unsigned b0, unsigned b1) {
    asm volatile(
        "mma.sync.aligned.m16n8k16.row.col.f32.f16.f16.f32 "
        "{%0,%1,%2,%3}, {%4,%5,%6,%7}, {%8,%9}, {%0,%1,%2,%3};"
        : "+f"(d0), "+f"(d1), "+f"(d2), "+f"(d3)
        : "r"(a0), "r"(a1), "r"(a2), "r"(a3), "r"(b0), "r"(b1));
}
__device__ __forceinline__ void ldsm4(unsigned& r0, unsigned& r1, unsigned& r2,
                                      unsigned& r3, uint32_t a) {
    asm volatile("ldmatrix.sync.aligned.m8n8.x4.shared.b16 {%0,%1,%2,%3}, [%4];"
                 : "=r"(r0), "=r"(r1), "=r"(r2), "=r"(r3) : "r"(a));
}
__device__ __forceinline__ void cpa16(uint32_t dst, const void* src, int srcbytes) {
    asm volatile("cp.async.ca.shared.global [%0], [%1], 16, %2;"
                 :: "r"(dst), "l"(src), "r"(srcbytes) : "memory");
}
__device__ __forceinline__ void cp_commit() {
    asm volatile("cp.async.commit_group;" ::: "memory");
}
template<int N>
__device__ __forceinline__ void cp_wait() {
    asm volatile("cp.async.wait_group %0;" :: "n"(N) : "memory");
}
__device__ __forceinline__ int gather_row(int n, int t) {
    int d = (n >= 1000);
    int toff = (t == 0) ? 0 : (t == 1 ? 2000 : 3000);
    return d * 4000 + toff + (n - d * 1000);
}

// ---------------- batched conversion kernels ---------------------------------
struct CvtSegs {
    const float* src[8];
    __half* dst[8];
    int n[8];
};
__global__ void cvt_many(CvtSegs cs) {
    const int z = blockIdx.z;
    const float* __restrict__ src = cs.src[z];
    __half* __restrict__ dst = cs.dst[z];
    const int n = cs.n[z];
    const int stride = gridDim.x * blockDim.x * 8;
    for (int i = (blockIdx.x * blockDim.x + threadIdx.x) * 8; i < n; i += stride) {
        float4 a = *(const float4*)(src + i);
        float4 b = *(const float4*)(src + i + 4);
        __half2 h[4] = { __floats2half2_rn(a.x, a.y), __floats2half2_rn(a.z, a.w),
                         __floats2half2_rn(b.x, b.y), __floats2half2_rn(b.z, b.w) };
        *(uint4*)(dst + i) = *(uint4*)h;
    }
}
struct Lstm5 { const float* W[5]; };
__global__ void cvt_lstm5(Lstm5 ws, __half* __restrict__ base) {
    const int z = blockIdx.z;
    const float* __restrict__ W = ws.W[z];
    __half* __restrict__ dst = base + O_LT + (size_t)z * 3072000;
    const int stride = gridDim.x * blockDim.x * 8;
    for (int idx = (blockIdx.x * blockDim.x + threadIdx.x) * 8;
         idx < 3 * 2000 * 512; idx += stride) {
        int k = idx & 511;
        int n = (idx >> 9) % 2000;
        int t = idx / (2000 * 512);
        const float* s = W + (size_t)gather_row(n, t) * 512 + k;
        float4 a = *(const float4*)s;
        float4 b = *(const float4*)(s + 4);
        __half2 h[4] = { __floats2half2_rn(a.x, a.y), __floats2half2_rn(a.z, a.w),
                         __floats2half2_rn(b.x, b.y), __floats2half2_rn(b.z, b.w) };
        *(uint4*)(dst + idx) = *(uint4*)h;
    }
}

// ---------------- arg structs -------------------------------------------------
struct LinSet  { const __half* A; const __half* W; const float* bias;
                 float* Cf; __half* Ch; int M; int K; };
struct LstmSet { const __half* A; const __half* Wg; const float* bG;
                 const float* Acc; float* Cf; __half* Ch;
                 int M; int accum; int out16; };  // out16: 0 fp32, 1 fp16, 2 split@512

// ===========================================================================
// gemm_lin16<OUT16>: C[M,N] = A[M,K] @ W[N,K]^T + bias
// BM=128, BN=128, BK=64 (128B rows, chunk c of row m at c^(m&7)), 256 thr
// (8 warps 2m x 4n), 3-stage cp.async (32KB/stage). 2 CTAs/SM.
// ===========================================================================
#define L_TA 16384                     // 128 rows * 128 B
#define L_STRIDE 32768
#define SMEM_GEMM (3 * 32768)

template<bool OUT16>
__global__ __launch_bounds__(256, 2) void gemm_lin16(
    LinSet s0, LinSet s1, LinSet s2, int N) {
    const LinSet S = (blockIdx.z == 0) ? s0 : (blockIdx.z == 1 ? s1 : s2);
    const int m0 = blockIdx.y * 128, n0 = blockIdx.x * 128;
    if (m0 >= S.M) return;
    const int K = S.K;

    extern __shared__ char sm[];
    const uint32_t smb = (uint32_t)__cvta_generic_to_shared(sm);

    const int tid = threadIdx.x;
    const int wid = tid >> 5, lane = tid & 31;
    const int wm = wid & 1, wn = wid >> 1;
    const int lr = lane >> 2, lc = lane & 3;

    // producer: 8 chunks/thread: rows prow+32p (4 passes A, 4 passes B), chunk pch
    const int prow = tid >> 3, pch = tid & 7;
    const __half* srcA[4];
    uint32_t dA[4];
#pragma unroll
    for (int p = 0; p < 4; p++) {
        int r = prow + 32 * p;
        srcA[p] = S.A + (size_t)(m0 + r) * K + pch * 8;
        dA[p] = smb + r * 128 + ((pch ^ (r & 7)) << 4);
    }
    const __half* srcB[4];
    uint32_t dB[4];
    bool brOK[4];
#pragma unroll
    for (int p = 0; p < 4; p++) {
        int r = prow + 32 * p;
        brOK[p] = (n0 + r) < N;
        srcB[p] = S.W + (size_t)(brOK[p] ? (n0 + r) : 0) * K + pch * 8;
        dB[p] = smb + L_TA + r * 128 + ((pch ^ (r & 7)) << 4);
    }

    const int l15 = lane & 15, hi = lane >> 4;
    uint32_t aOff[4], bOff[2];
    int aSwz[4], bSwz[2];
#pragma unroll
    for (int mi = 0; mi < 4; mi++) {
        int r = wm * 64 + mi * 16 + l15;
        aOff[mi] = r * 128; aSwz[mi] = r & 7;
    }
#pragma unroll
    for (int nj = 0; nj < 2; nj++) {
        int r = wn * 32 + nj * 16 + l15;
        bOff[nj] = L_TA + r * 128; bSwz[nj] = r & 7;
    }

    float acc[4][4][4];
#pragma unroll
    for (int mi = 0; mi < 4; mi++)
#pragma unroll
        for (int ni = 0; ni < 4; ni++)
#pragma unroll
            for (int r = 0; r < 4; r++) acc[mi][ni][r] = 0.0f;

    const int nt = (K + 63) >> 6;
    auto LOAD = [&](int st, int kt) {
        const uint32_t so = st * L_STRIDE;
        const int kb = (kt + pch * 8 + 8 <= K) ? 16 : 0;
#pragma unroll
        for (int p = 0; p < 4; p++) cpa16(dA[p] + so, srcA[p] + kt, kb);
#pragma unroll
        for (int p = 0; p < 4; p++) cpa16(dB[p] + so, srcB[p] + kt, brOK[p] ? kb : 0);
    };

    LOAD(0, 0); cp_commit();
    LOAD(1, 64); cp_commit();

    for (int i = 0; i < nt; i++) {
        cp_wait<1>();
        __syncthreads();
        if (i + 2 < nt) LOAD((i + 2) % 3, (i + 2) << 6);
        cp_commit();

        const uint32_t base = smb + (i % 3) * L_STRIDE;
#pragma unroll
        for (int s = 0; s < 4; s++) {
            const int ch = 2 * s + hi;
            unsigned af[4][4], bq[2][4];
#pragma unroll
            for (int mi = 0; mi < 4; mi++)
                ldsm4(af[mi][0], af[mi][1], af[mi][2], af[mi][3],
                      base + aOff[mi] + ((ch ^ aSwz[mi]) << 4));
#pragma unroll
            for (int nj = 0; nj < 2; nj++)
                ldsm4(bq[nj][0], bq[nj][1], bq[nj][2], bq[nj][3],
                      base + bOff[nj] + ((ch ^ bSwz[nj]) << 4));
#pragma unroll
            for (int mi = 0; mi < 4; mi++)
#pragma unroll
                for (int nj = 0; nj < 2; nj++) {
                    mma_f16(acc[mi][2 * nj][0], acc[mi][2 * nj][1],
                            acc[mi][2 * nj][2], acc[mi][2 * nj][3],
                            af[mi][0], af[mi][1], af[mi][2], af[mi][3],
                            bq[nj][0], bq[nj][2]);
                    mma_f16(acc[mi][2 * nj + 1][0], acc[mi][2 * nj + 1][1],
                            acc[mi][2 * nj + 1][2], acc[mi][2 * nj + 1][3],
                            af[mi][0], af[mi][1], af[mi][2], af[mi][3],
                            bq[nj][1], bq[nj][3]);
                }
        }
    }

#pragma unroll
    for (int mi = 0; mi < 4; mi++) {
        int m = m0 + wm * 64 + mi * 16 + lr;
#pragma unroll
        for (int ni = 0; ni < 4; ni++) {
            int n = n0 + wn * 32 + ni * 8 + lc * 2;
            if (n + 1 < N) {
                float b0 = S.bias[n], b1 = S.bias[n + 1];
                float v00 = acc[mi][ni][0] + b0, v01 = acc[mi][ni][1] + b1;
                float v10 = acc[mi][ni][2] + b0, v11 = acc[mi][ni][3] + b1;
                if (OUT16) {
                    *(__half2*)(S.Ch + (size_t)m * N + n) = __floats2half2_rn(v00, v01);
                    *(__half2*)(S.Ch + (size_t)(m + 8) * N + n) = __floats2half2_rn(v10, v11);
                } else {
                    *(float2*)(S.Cf + (size_t)m * N + n) = make_float2(v00, v01);
                    *(float2*)(S.Cf + (size_t)(m + 8) * N + n) = make_float2(v10, v11);
                }
            } else if (n < N) {
                float b0 = S.bias[n];
                if (OUT16) {
                    S.Ch[(size_t)m * N + n] = __float2half_rn(acc[mi][ni][0] + b0);
                    S.Ch[(size_t)(m + 8) * N + n] = __float2half_rn(acc[mi][ni][2] + b0);
                } else {
                    S.Cf[(size_t)m * N + n] = acc[mi][ni][0] + b0;
                    S.Cf[(size_t)(m + 8) * N + n] = acc[mi][ni][2] + b0;
                }
            }
        }
    }
}

// ===========================================================================
// gemm_lstm16: fused single-step BiLSTM (gates pre-gathered in Wg [3,2000,512])
// out = scale * sig(o)*tanh(sig(i)*tanh(g))  [+ Acc]
// BM=64, BN=64x3 gates, BK=64, 256 thr (8 warps 2m x 4n), 3-stage. K=512.
// out16: 0 fp32, 1 fp16, 2 split (row<512 -> Cf fp32, else Ch fp16 at row-512).
// ===========================================================================
#define S_TA 8192                      // 64 rows * 128 B
#define S_STRIDE 32768

__global__ __launch_bounds__(256, 2) void gemm_lstm16(
    LstmSet s0, LstmSet s1, float scale) {
    const int N = 2000, K = 512;
    const LstmSet S = blockIdx.z ? s1 : s0;
    const int m0 = blockIdx.y * 64, n0 = blockIdx.x * 64;
    if (m0 >= S.M) return;

    extern __shared__ char sm[];
    const uint32_t smb = (uint32_t)__cvta_generic_to_shared(sm);

    const int tid = threadIdx.x;
    const int wid = tid >> 5, lane = tid & 31;
    const int wm = wid & 1, wn = wid >> 1;
    const int lr = lane >> 2, lc = lane & 3;

    // producer: A 64 rows (2 passes), B 192 rows (6 passes); chunk pch
    const int prow = tid >> 3, pch = tid & 7;
    const __half* srcA[2];
    uint32_t dA[2];
#pragma unroll
    for (int p = 0; p < 2; p++) {
        int r = prow + 32 * p;
        srcA[p] = S.A + (size_t)(m0 + r) * K + pch * 8;
        dA[p] = smb + r * 128 + ((pch ^ (r & 7)) << 4);
    }
    const __half* srcB[6];
    uint32_t dB[6];
    bool bOK[6];
#pragma unroll
    for (int p = 0; p < 6; p++) {
        int r = prow + 32 * p;           // 0..191: gate = r/64, row-in-gate = r%64
        int t = r >> 6, rr = r & 63;
        bOK[p] = (n0 + rr) < N;
        srcB[p] = S.Wg + (size_t)(t * 2000 + (bOK[p] ? n0 + rr : 0)) * K + pch * 8;
        dB[p] = smb + S_TA + r * 128 + ((pch ^ (r & 7)) << 4);
    }

    const int l15 = lane & 15, hi = lane >> 4;
    uint32_t aOff[2]; int aSwz[2];
#pragma unroll
    for (int mi = 0; mi < 2; mi++) {
        int r = wm * 32 + mi * 16 + l15;
        aOff[mi] = r * 128; aSwz[mi] = r & 7;
    }
    uint32_t bOff[3]; int bSwz;
    {
        int r = wn * 16 + l15;
        bSwz = r & 7;
#pragma unroll
        for (int t = 0; t < 3; t++) bOff[t] = S_TA + (t * 64 + r) * 128;
    }

    float acc[3][2][2][4];
#pragma unroll
    for (int t = 0; t < 3; t++)
#pragma unroll
        for (int mi = 0; mi < 2; mi++)
#pragma unroll
            for (int ni = 0; ni < 2; ni++)
#pragma unroll
                for (int r = 0; r < 4; r++) acc[t][mi][ni][r] = 0.0f;

    const int nt = K >> 6;               // 8
    auto LOAD = [&](int st, int kt) {
        const uint32_t so = st * S_STRIDE;
#pragma unroll
        for (int p = 0; p < 2; p++) cpa16(dA[p] + so, srcA[p] + kt, 16);
#pragma unroll
        for (int p = 0; p < 6; p++) cpa16(dB[p] + so, srcB[p] + kt, bOK[p] ? 16 : 0);
    };

    LOAD(0, 0); cp_commit();
    LOAD(1, 64); cp_commit();

    for (int i = 0; i < nt; i++) {
        cp_wait<1>();
        __syncthreads();
        if (i + 2 < nt) LOAD((i + 2) % 3, (i + 2) << 6);
        cp_commit();

        const uint32_t base = smb + (i % 3) * S_STRIDE;
#pragma unroll
        for (int s = 0; s < 4; s++) {
            const int ch = 2 * s + hi;
            unsigned af[2][4], bt[3][4];
#pragma unroll
            for (int mi = 0; mi < 2; mi++)
                ldsm4(af[mi][0], af[mi][1], af[mi][2], af[mi][3],
                      base + aOff[mi] + ((ch ^ aSwz[mi]) << 4));
#pragma unroll
            for (int t = 0; t < 3; t++)
                ldsm4(bt[t][0], bt[t][1], bt[t][2], bt[t][3],
                      base + bOff[t] + ((ch ^ bSwz) << 4));
#pragma unroll
            for (int t = 0; t < 3; t++)
#pragma unroll
                for (int mi = 0; mi < 2; mi++) {
                    mma_f16(acc[t][mi][0][0], acc[t][mi][0][1],
                            acc[t][mi][0][2], acc[t][mi][0][3],
                            af[mi][0], af[mi][1], af[mi][2], af[mi][3],
                            bt[t][0], bt[t][2]);
                    mma_f16(acc[t][mi][1][0], acc[t][mi][1][1],
                            acc[t][mi][1][2], acc[t][mi][1][3],
                            af[mi][0], af[mi][1], af[mi][2], af[mi][3],
                            bt[t][1], bt[t][3]);
                }
        }
    }

#pragma unroll
    for (int mi = 0; mi < 2; mi++)
#pragma unroll
        for (int ni = 0; ni < 2; ni++) {
            int mA = m0 + wm * 32 + mi * 16 + lr;
            int nA = n0 + wn * 16 + ni * 8 + lc * 2;
#pragma unroll
            for (int r = 0; r < 4; r++) {
                int mm = mA + ((r >= 2) ? 8 : 0);
                int nn = nA + (r & 1);
                if (nn < N) {
                    int d = (nn >= 1000);
                    int base = d * 4000 + (nn - d * 1000);
                    float gi = acc[0][mi][ni][r] + S.bG[base];
                    float gg = acc[1][mi][ni][r] + S.bG[base + 2000];
                    float go = acc[2][mi][ni][r] + S.bG[base + 3000];
                    float cc = sigf(gi) * tanh_fast(gg);
                    float h = sigf(go) * tanh_fast(cc);
                    float o = scale * h;
                    if (S.accum) o += S.Acc[(size_t)mm * N + nn];
                    if (S.out16 == 0) {
                        S.Cf[(size_t)mm * N + nn] = o;
                    } else if (S.out16 == 1) {
                        S.Ch[(size_t)mm * N + nn] = __float2half_rn(o);
                    } else {
                        if (mm < BB) S.Cf[(size_t)mm * N + nn] = o;
                        else S.Ch[(size_t)(mm - BB) * N + nn] = __float2half_rn(o);
                    }
                }
            }
        }
}

// ---------------- paired neighbor mean: [1024,24,E] -> [1024,E] --------------
__global__ void mean16(const __half* __restrict__ Z, __half* __restrict__ out) {
    int idx = blockIdx.x * blockDim.x + threadIdx.x;
    if (idx >= 2 * BB * EE) return;
    int bI = idx / EE, n = idx % EE;
    float s = 0.f;
#pragma unroll 4
    for (int j = 0; j < 24; j++) s += __half2float(Z[(size_t)(bI * 24 + j) * EE + n]);
    out[idx] = __float2half_rn(s * (1.0f / 24.0f));
}

// ---------------- 3-way attention combine ------------------------------------
__global__ void attention_kernel(const float* __restrict__ c, const float* __restrict__ u,
                                 const float* __restrict__ p, const float* __restrict__ att,
                                 float* __restrict__ out) {
    int bI = blockIdx.x, tid = threadIdx.x;
    const float* cb = c + (size_t)bI * EE;
    const float* ub = u + (size_t)bI * EE;
    const float* pb = p + (size_t)bI * EE;
    float s0 = 0.f, s1 = 0.f, s2 = 0.f, s3 = 0.f;
    for (int n = tid; n < EE; n += 256) {
        float a0 = att[n], a1 = att[EE + n];
        float cv = cb[n];
        s0 += cv * a0;
        s1 += cv * a1;
        s2 += ub[n] * a1;
        s3 += pb[n] * a1;
    }
    __shared__ float red[4][256];
    red[0][tid] = s0; red[1][tid] = s1; red[2][tid] = s2; red[3][tid] = s3;
    __syncthreads();
    for (int s = 128; s > 0; s >>= 1) {
        if (tid < s) {
#pragma unroll
            for (int q = 0; q < 4; q++) red[q][tid] += red[q][tid + s];
        }
        __syncthreads();
    }
    __shared__ float w[3];
    if (tid == 0) {
        float sc[3];
        sc[0] = red[0][0] + red[1][0];
        sc[1] = red[0][0] + red[2][0];
        sc[2] = red[0][0] + red[3][0];
#pragma unroll
        for (int k = 0; k < 3; k++) sc[k] = sc[k] > 0.f ? sc[k] : 0.01f * sc[k];
        float mx = fmaxf(sc[0], fmaxf(sc[1], sc[2]));
        float e0 = __expf(sc[0] - mx), e1 = __expf(sc[1] - mx), e2 = __expf(sc[2] - mx);
        float inv = 1.0f / (e0 + e1 + e2);
        w[0] = e0 * inv; w[1] = e1 * inv; w[2] = e2 * inv;
    }
    __syncthreads();
    float w0 = w[0], w1 = w[1], w2 = w[2];
    for (int n = tid; n < EE; n += 256)
        out[(size_t)bI * EE + n] = w0 * cb[n] + w1 * ub[n] + w2 * pb[n];
}

// ---------------------------------------------------------------------------
extern "C" void kernel_launch(void* const* d_in, const int* in_sizes, int n_in,
                              void* d_out, int out_size) {
    const float* c_text  = (const float*)d_in[0];
    const float* c_image = (const float*)d_in[1];
    const float* p_text  = (const float*)d_in[2];
    const float* p_image = (const float*)d_in[3];
    const float* u_text  = (const float*)d_in[4];
    const float* u_other = (const float*)d_in[5];
    const float* W_lt = (const float*)d_in[6],  *b_lt = (const float*)d_in[7];
    const float* W_li = (const float*)d_in[8],  *b_li = (const float*)d_in[9];
    const float* W_lo = (const float*)d_in[10], *b_lo = (const float*)d_in[11];
    const float* lstm_t_W = (const float*)d_in[12], *lstm_t_b = (const float*)d_in[13];
    const float* lstm_i_W = (const float*)d_in[14], *lstm_i_b = (const float*)d_in[15];
    const float* lstm_o_W = (const float*)d_in[16], *lstm_o_b = (const float*)d_in[17];
    const float* ua_lin_W = (const float*)d_in[18], *ua_lin_b = (const float*)d_in[19];
    const float* ua_lstm_W = (const float*)d_in[20], *ua_lstm_b = (const float*)d_in[21];
    const float* ua_out_W = (const float*)d_in[22], *ua_out_b = (const float*)d_in[23];
    const float* pa_lin_W = (const float*)d_in[24], *pa_lin_b = (const float*)d_in[25];
    const float* pa_lstm_W = (const float*)d_in[26], *pa_lstm_b = (const float*)d_in[27];
    const float* pa_out_W = (const float*)d_in[28], *pa_out_b = (const float*)d_in[29];
    const float* p_att = (const float*)d_in[30];
    float* out = (float*)d_out;

    __half *in16, *w16, *bufX, *Hp16, *Hu16, *H2, *Hm;
    float *Hc, *Ht32, *uagg, *pagg;
    cudaGetSymbolAddress((void**)&in16, g_in16);
    cudaGetSymbolAddress((void**)&w16,  g_w16);
    cudaGetSymbolAddress((void**)&bufX, g_bufX);
    cudaGetSymbolAddress((void**)&Hc,   g_Hc);
    cudaGetSymbolAddress((void**)&Ht32, g_Ht32);
    cudaGetSymbolAddress((void**)&Hp16, g_Hp16);
    cudaGetSymbolAddress((void**)&Hu16, g_Hu16);
    cudaGetSymbolAddress((void**)&H2,   g_H2);
    cudaGetSymbolAddress((void**)&Hm,   g_Hm);
    cudaGetSymbolAddress((void**)&uagg, g_uagg);
    cudaGetSymbolAddress((void**)&pagg, g_pagg);

    cudaFuncSetAttribute(gemm_lin16<true>,
                         cudaFuncAttributeMaxDynamicSharedMemorySize, SMEM_GEMM);
    cudaFuncSetAttribute(gemm_lin16<false>,
                         cudaFuncAttributeMaxDynamicSharedMemorySize, SMEM_GEMM);
    cudaFuncSetAttribute(gemm_lstm16,
                         cudaFuncAttributeMaxDynamicSharedMemorySize, SMEM_GEMM);

    // ---- 1: weight linears (7 segs, one launch) ----
    {
        CvtSegs cs{};
        cs.src[0] = W_lt;     cs.dst[0] = w16 + O_WLT;   cs.n[0] = 512 * 768;
        cs.src[1] = W_li;     cs.dst[1] = w16 + O_WLI;   cs.n[1] = 512 * 2048;
        cs.src[2] = W_lo;     cs.dst[2] = w16 + O_WLO;   cs.n[2] = 512 * 512;
        cs.src[3] = ua_lin_W; cs.dst[3] = w16 + O_UALIN; cs.n[3] = 512 * 2000;
        cs.src[4] = pa_lin_W; cs.dst[4] = w16 + O_PALIN; cs.n[4] = 512 * 2000;
        cs.src[5] = ua_out_W; cs.dst[5] = w16 + O_UAOUT; cs.n[5] = 2000 * 2000;
        cs.src[6] = pa_out_W; cs.dst[6] = w16 + O_PAOUT; cs.n[6] = 2000 * 2000;
        cvt_many<<<dim3(256, 1, 7), 256>>>(cs);
    }
    // ---- 2: lstm weight gathers (5 via z) ----
    {
        Lstm5 ws{ { lstm_t_W, lstm_i_W, lstm_o_W, ua_lstm_W, pa_lstm_W } };
        cvt_lstm5<<<dim3(256, 1, 5), 256>>>(ws, w16);
    }
    // ---- 3: inputs (6 segs) ----
    {
        CvtSegs cs{};
        cs.src[0] = c_text;  cs.dst[0] = in16 + I_TEXT;                    cs.n[0] = BB * 768;
        cs.src[1] = p_text;  cs.dst[1] = in16 + I_TEXT + BB * 768;         cs.n[1] = MPU * 768;
        cs.src[2] = u_text;  cs.dst[2] = in16 + I_TEXT + (BB + MPU) * 768; cs.n[2] = MPU * 768;
        cs.src[3] = c_image; cs.dst[3] = in16 + I_IMG;                     cs.n[3] = BB * 2048;
        cs.src[4] = p_image; cs.dst[4] = in16 + I_IMG + BB * 2048;         cs.n[4] = MPU * 2048;
        cs.src[5] = u_other; cs.dst[5] = in16 + I_OTH;                     cs.n[5] = MPU * 512;
        cvt_many<<<dim3(256, 1, 6), 256>>>(cs);
    }

    // ---- 4: all three input linears, one z=3 launch (N=512) ----
    {
        LinSet a{in16 + I_TEXT, w16 + O_WLT, b_lt, nullptr, bufX + X_TEXT, MT, 768};
        LinSet b{in16 + I_IMG,  w16 + O_WLI, b_li, nullptr, bufX + X_IMG,  MI2, 2048};
        LinSet c{in16 + I_OTH,  w16 + O_WLO, b_lo, nullptr, bufX + X_OTH,  MPU, 512};
        gemm_lin16<true><<<dim3(4, MT / 128, 3), 256, SMEM_GEMM>>>(a, b, c, 512);
    }
    // ---- 5: text LSTM (all rows) -> Ht32 fp32 ----
    {
        LstmSet t{bufX + X_TEXT, w16 + O_LT, lstm_t_b, nullptr, Ht32, nullptr,
                  MT, 0, 0};
        gemm_lstm16<<<dim3(32, MT / 64, 1), 256, SMEM_GEMM>>>(t, t, 0.5f);
    }
    // ---- 6: image LSTM (split Hc/Hp16) + other LSTM (Hu16), z=2 ----
    {
        LstmSet im{bufX + X_IMG, w16 + O_LT + 1 * 3072000, lstm_i_b, Ht32,
                   Hc, Hp16, MI2, 1, 2};
        LstmSet ot{bufX + X_OTH, w16 + O_LT + 2 * 3072000, lstm_o_b,
                   Ht32 + (size_t)MI2 * EE, nullptr, Hu16, MPU, 1, 1};
        gemm_lstm16<<<dim3(32, MI2 / 64, 2), 256, SMEM_GEMM>>>(im, ot, 0.5f);
    }
    // ---- 7: paired agg linears (z=2, N=512, K=2000) ----
    {
        LinSet a{Hu16, w16 + O_UALIN, ua_lin_b, nullptr, bufX, MPU, 2000};
        LinSet b{Hp16, w16 + O_PALIN, pa_lin_b, nullptr, bufX + (size_t)MPU * 512,
                 MPU, 2000};
        gemm_lin16<true><<<dim3(4, MPU / 128, 2), 256, SMEM_GEMM>>>(a, b, b, 512);
    }
    // ---- 8: paired agg LSTMs (z=2) ----
    {
        LstmSet a{bufX, w16 + O_LT + 3 * 3072000, ua_lstm_b, nullptr, nullptr, H2,
                  MPU, 0, 1};
        LstmSet b{bufX + (size_t)MPU * 512, w16 + O_LT + 4 * 3072000, pa_lstm_b,
                  nullptr, nullptr, H2 + (size_t)MPU * EE, MPU, 0, 1};
        gemm_lstm16<<<dim3(32, MPU / 64, 2), 256, SMEM_GEMM>>>(a, b, 1.0f);
    }
    // ---- 9: paired neighbor mean ----
    mean16<<<(2 * BB * EE + 255) / 256, 256>>>(H2, Hm);
    // ---- 10: paired out-linears (z=2, N=2000, K=2000, fp32 out) ----
    {
        LinSet a{Hm, w16 + O_UAOUT, ua_out_b, uagg, nullptr, BB, 2000};
        LinSet b{Hm + (size_t)BB * EE, w16 + O_PAOUT, pa_out_b, pagg, nullptr,
                 BB, 2000};
        gemm_lin16<false><<<dim3(16, BB / 128, 2), 256, SMEM_GEMM>>>(a, b, b, 2000);
    }
    // ---- 11: attention combine ----
    attention_kernel<<<BB, 256>>>(Hc, uagg, pagg, p_att, out);
}

// round 10
// speedup vs baseline: 5.5356x; 1.1140x over previous
#include <cuda_runtime.h>
#include <cuda_fp16.h>
#include <cstdint>

// ---------------------------------------------------------------------------
// Het_GNN forward — fp16 mma.sync, BK=64 3-stage, 2 CTAs/SM, cp.async.cg,
// full-width cvt grids. 11 launches.
// ---------------------------------------------------------------------------
#define BB   512
#define MPU  12288
#define MT   25088
#define MI2  12800
#define EE   2000

__device__ __half g_in16 [51773440];
__device__ __half g_w16  [27111936];
__device__ __half g_bufX [25690112];
__device__ float  g_Ht32 [MT * EE];
__device__ float  g_Hc   [BB  * EE];
__device__ __half g_Hp16 [MPU * EE];
__device__ __half g_Hu16 [MPU * EE];
__device__ __half g_H2   [2 * MPU * EE];
__device__ __half g_Hm   [2 * BB * EE];
__device__ float  g_uagg [BB * EE];
__device__ float  g_pagg [BB * EE];

#define I_TEXT 0
#define I_IMG  19267584
#define I_OTH  45481984
#define X_TEXT 0
#define X_IMG  12845056
#define X_OTH  19398656
#define O_WLT   0
#define O_WLI   393216
#define O_WLO   1441792
#define O_LT    1703936      // 5 lstm gathers, stride 3072000
#define O_UALIN 17063936
#define O_PALIN 18087936
#define O_UAOUT 19111936
#define O_PAOUT 23111936

// ---------------- helpers ----------------------------------------------------
__device__ __forceinline__ float sigf(float x) { return 1.0f / (1.0f + __expf(-x)); }
__device__ __forceinline__ float tanh_fast(float x) {
    return 2.0f / (1.0f + __expf(-2.0f * x)) - 1.0f;
}
__device__ __forceinline__ void mma_f16(float& d0, float& d1, float& d2, float& d3,
                                        unsigned a0, unsigned a1, unsigned a2, unsigned a3,
                                        unsigned b0, unsigned b1) {
    asm volatile(
        "mma.sync.aligned.m16n8k16.row.col.f32.f16.f16.f32 "
        "{%0,%1,%2,%3}, {%4,%5,%6,%7}, {%8,%9}, {%0,%1,%2,%3};"
        : "+f"(d0), "+f"(d1), "+f"(d2), "+f"(d3)
        : "r"(a0), "r"(a1), "r"(a2), "r"(a3), "r"(b0), "r"(b1));
}
__device__ __forceinline__ void ldsm4(unsigned& r0, unsigned& r1, unsigned& r2,
                                      unsigned& r3, uint32_t a) {
    asm volatile("ldmatrix.sync.aligned.m8n8.x4.shared.b16 {%0,%1,%2,%3}, [%4];"
                 : "=r"(r0), "=r"(r1), "=r"(r2), "=r"(r3) : "r"(a));
}
// .cg: 16B global->shared bypassing L1 allocation
__device__ __forceinline__ void cpa16(uint32_t dst, const void* src, int srcbytes) {
    asm volatile("cp.async.cg.shared.global [%0], [%1], 16, %2;"
                 :: "r"(dst), "l"(src), "r"(srcbytes) : "memory");
}
__device__ __forceinline__ void cp_commit() {
    asm volatile("cp.async.commit_group;" ::: "memory");
}
template<int N>
__device__ __forceinline__ void cp_wait() {
    asm volatile("cp.async.wait_group %0;" :: "n"(N) : "memory");
}
__device__ __forceinline__ int gather_row(int n, int t) {
    int d = (n >= 1000);
    int toff = (t == 0) ? 0 : (t == 1 ? 2000 : 3000);
    return d * 4000 + toff + (n - d * 1000);
}

// ---------------- batched conversion kernels (1 group / thread) --------------
struct CvtSegs {
    const float* src[8];
    __half* dst[8];
    int n[8];
};
__global__ void cvt_many(CvtSegs cs) {
    const int z = blockIdx.z;
    const int n = cs.n[z];
    const int i = (blockIdx.x * blockDim.x + threadIdx.x) * 8;
    if (i >= n) return;
    const float* __restrict__ src = cs.src[z];
    __half* __restrict__ dst = cs.dst[z];
    float4 a = *(const float4*)(src + i);
    float4 b = *(const float4*)(src + i + 4);
    __half2 h[4] = { __floats2half2_rn(a.x, a.y), __floats2half2_rn(a.z, a.w),
                     __floats2half2_rn(b.x, b.y), __floats2half2_rn(b.z, b.w) };
    *(uint4*)(dst + i) = *(uint4*)h;
}
struct Lstm5 { const float* W[5]; };
__global__ void cvt_lstm5(Lstm5 ws, __half* __restrict__ base) {
    const int z = blockIdx.z;
    const int idx = (blockIdx.x * blockDim.x + threadIdx.x) * 8;
    if (idx >= 3 * 2000 * 512) return;
    const float* __restrict__ W = ws.W[z];
    __half* __restrict__ dst = base + O_LT + (size_t)z * 3072000;
    int k = idx & 511;
    int n = (idx >> 9) % 2000;
    int t = idx / (2000 * 512);
    const float* s = W + (size_t)gather_row(n, t) * 512 + k;
    float4 a = *(const float4*)s;
    float4 b = *(const float4*)(s + 4);
    __half2 h[4] = { __floats2half2_rn(a.x, a.y), __floats2half2_rn(a.z, a.w),
                     __floats2half2_rn(b.x, b.y), __floats2half2_rn(b.z, b.w) };
    *(uint4*)(dst + idx) = *(uint4*)h;
}

// ---------------- arg structs -------------------------------------------------
struct LinSet  { const __half* A; const __half* W; const float* bias;
                 float* Cf; __half* Ch; int M; int K; };
struct LstmSet { const __half* A; const __half* Wg; const float* bG;
                 const float* Acc; float* Cf; __half* Ch;
                 int M; int accum; int out16; };  // out16: 0 fp32, 1 fp16, 2 split@512

// ===========================================================================
// gemm_lin16<OUT16>: C[M,N] = A[M,K] @ W[N,K]^T + bias
// BM=128, BN=128, BK=64 (128B rows, chunk c of row m at c^(m&7)), 256 thr
// (8 warps 2m x 4n), 3-stage cp.async (32KB/stage). 2 CTAs/SM.
// ===========================================================================
#define L_TA 16384
#define L_STRIDE 32768
#define SMEM_GEMM (3 * 32768)

template<bool OUT16>
__global__ __launch_bounds__(256, 2) void gemm_lin16(
    LinSet s0, LinSet s1, LinSet s2, int N) {
    const LinSet S = (blockIdx.z == 0) ? s0 : (blockIdx.z == 1 ? s1 : s2);
    const int m0 = blockIdx.y * 128, n0 = blockIdx.x * 128;
    if (m0 >= S.M) return;
    const int K = S.K;

    extern __shared__ char sm[];
    const uint32_t smb = (uint32_t)__cvta_generic_to_shared(sm);

    const int tid = threadIdx.x;
    const int wid = tid >> 5, lane = tid & 31;
    const int wm = wid & 1, wn = wid >> 1;
    const int lr = lane >> 2, lc = lane & 3;

    const int prow = tid >> 3, pch = tid & 7;
    const __half* srcA[4];
    uint32_t dA[4];
#pragma unroll
    for (int p = 0; p < 4; p++) {
        int r = prow + 32 * p;
        srcA[p] = S.A + (size_t)(m0 + r) * K + pch * 8;
        dA[p] = smb + r * 128 + ((pch ^ (r & 7)) << 4);
    }
    const __half* srcB[4];
    uint32_t dB[4];
    bool brOK[4];
#pragma unroll
    for (int p = 0; p < 4; p++) {
        int r = prow + 32 * p;
        brOK[p] = (n0 + r) < N;
        srcB[p] = S.W + (size_t)(brOK[p] ? (n0 + r) : 0) * K + pch * 8;
        dB[p] = smb + L_TA + r * 128 + ((pch ^ (r & 7)) << 4);
    }

    const int l15 = lane & 15, hi = lane >> 4;
    uint32_t aOff[4], bOff[2];
    int aSwz[4], bSwz[2];
#pragma unroll
    for (int mi = 0; mi < 4; mi++) {
        int r = wm * 64 + mi * 16 + l15;
        aOff[mi] = r * 128; aSwz[mi] = r & 7;
    }
#pragma unroll
    for (int nj = 0; nj < 2; nj++) {
        int r = wn * 32 + nj * 16 + l15;
        bOff[nj] = L_TA + r * 128; bSwz[nj] = r & 7;
    }

    float acc[4][4][4];
#pragma unroll
    for (int mi = 0; mi < 4; mi++)
#pragma unroll
        for (int ni = 0; ni < 4; ni++)
#pragma unroll
            for (int r = 0; r < 4; r++) acc[mi][ni][r] = 0.0f;

    const int nt = (K + 63) >> 6;
    auto LOAD = [&](int st, int kt) {
        const uint32_t so = st * L_STRIDE;
        const int kb = (kt + pch * 8 + 8 <= K) ? 16 : 0;
#pragma unroll
        for (int p = 0; p < 4; p++) cpa16(dA[p] + so, srcA[p] + kt, kb);
#pragma unroll
        for (int p = 0; p < 4; p++) cpa16(dB[p] + so, srcB[p] + kt, brOK[p] ? kb : 0);
    };

    LOAD(0, 0); cp_commit();
    LOAD(1, 64); cp_commit();

    for (int i = 0; i < nt; i++) {
        cp_wait<1>();
        __syncthreads();
        if (i + 2 < nt) LOAD((i + 2) % 3, (i + 2) << 6);
        cp_commit();

        const uint32_t base = smb + (i % 3) * L_STRIDE;
#pragma unroll
        for (int s = 0; s < 4; s++) {
            const int ch = 2 * s + hi;
            unsigned af[4][4], bq[2][4];
#pragma unroll
            for (int mi = 0; mi < 4; mi++)
                ldsm4(af[mi][0], af[mi][1], af[mi][2], af[mi][3],
                      base + aOff[mi] + ((ch ^ aSwz[mi]) << 4));
#pragma unroll
            for (int nj = 0; nj < 2; nj++)
                ldsm4(bq[nj][0], bq[nj][1], bq[nj][2], bq[nj][3],
                      base + bOff[nj] + ((ch ^ bSwz[nj]) << 4));
#pragma unroll
            for (int mi = 0; mi < 4; mi++)
#pragma unroll
                for (int nj = 0; nj < 2; nj++) {
                    mma_f16(acc[mi][2 * nj][0], acc[mi][2 * nj][1],
                            acc[mi][2 * nj][2], acc[mi][2 * nj][3],
                            af[mi][0], af[mi][1], af[mi][2], af[mi][3],
                            bq[nj][0], bq[nj][2]);
                    mma_f16(acc[mi][2 * nj + 1][0], acc[mi][2 * nj + 1][1],
                            acc[mi][2 * nj + 1][2], acc[mi][2 * nj + 1][3],
                            af[mi][0], af[mi][1], af[mi][2], af[mi][3],
                            bq[nj][1], bq[nj][3]);
                }
        }
    }

#pragma unroll
    for (int mi = 0; mi < 4; mi++) {
        int m = m0 + wm * 64 + mi * 16 + lr;
#pragma unroll
        for (int ni = 0; ni < 4; ni++) {
            int n = n0 + wn * 32 + ni * 8 + lc * 2;
            if (n + 1 < N) {
                float b0 = S.bias[n], b1 = S.bias[n + 1];
                float v00 = acc[mi][ni][0] + b0, v01 = acc[mi][ni][1] + b1;
                float v10 = acc[mi][ni][2] + b0, v11 = acc[mi][ni][3] + b1;
                if (OUT16) {
                    *(__half2*)(S.Ch + (size_t)m * N + n) = __floats2half2_rn(v00, v01);
                    *(__half2*)(S.Ch + (size_t)(m + 8) * N + n) = __floats2half2_rn(v10, v11);
                } else {
                    *(float2*)(S.Cf + (size_t)m * N + n) = make_float2(v00, v01);
                    *(float2*)(S.Cf + (size_t)(m + 8) * N + n) = make_float2(v10, v11);
                }
            } else if (n < N) {
                float b0 = S.bias[n];
                if (OUT16) {
                    S.Ch[(size_t)m * N + n] = __float2half_rn(acc[mi][ni][0] + b0);
                    S.Ch[(size_t)(m + 8) * N + n] = __float2half_rn(acc[mi][ni][2] + b0);
                } else {
                    S.Cf[(size_t)m * N + n] = acc[mi][ni][0] + b0;
                    S.Cf[(size_t)(m + 8) * N + n] = acc[mi][ni][2] + b0;
                }
            }
        }
    }
}

// ===========================================================================
// gemm_lstm16: fused single-step BiLSTM (gates pre-gathered in Wg [3,2000,512])
// BM=64, BN=64x3 gates, BK=64, 256 thr (8 warps 2m x 4n), 3-stage. K=512.
// out16: 0 fp32, 1 fp16, 2 split (row<512 -> Cf fp32, else Ch fp16 at row-512).
// ===========================================================================
#define S_TA 8192
#define S_STRIDE 32768

__global__ __launch_bounds__(256, 2) void gemm_lstm16(
    LstmSet s0, LstmSet s1, float scale) {
    const int N = 2000, K = 512;
    const LstmSet S = blockIdx.z ? s1 : s0;
    const int m0 = blockIdx.y * 64, n0 = blockIdx.x * 64;
    if (m0 >= S.M) return;

    extern __shared__ char sm[];
    const uint32_t smb = (uint32_t)__cvta_generic_to_shared(sm);

    const int tid = threadIdx.x;
    const int wid = tid >> 5, lane = tid & 31;
    const int wm = wid & 1, wn = wid >> 1;
    const int lr = lane >> 2, lc = lane & 3;

    const int prow = tid >> 3, pch = tid & 7;
    const __half* srcA[2];
    uint32_t dA[2];
#pragma unroll
    for (int p = 0; p < 2; p++) {
        int r = prow + 32 * p;
        srcA[p] = S.A + (size_t)(m0 + r) * K + pch * 8;
        dA[p] = smb + r * 128 + ((pch ^ (r & 7)) << 4);
    }
    const __half* srcB[6];
    uint32_t dB[6];
    bool bOK[6];
#pragma unroll
    for (int p = 0; p < 6; p++) {
        int r = prow + 32 * p;
        int t = r >> 6, rr = r & 63;
        bOK[p] = (n0 + rr) < N;
        srcB[p] = S.Wg + (size_t)(t * 2000 + (bOK[p] ? n0 + rr : 0)) * K + pch * 8;
        dB[p] = smb + S_TA + r * 128 + ((pch ^ (r & 7)) << 4);
    }

    const int l15 = lane & 15, hi = lane >> 4;
    uint32_t aOff[2]; int aSwz[2];
#pragma unroll
    for (int mi = 0; mi < 2; mi++) {
        int r = wm * 32 + mi * 16 + l15;
        aOff[mi] = r * 128; aSwz[mi] = r & 7;
    }
    uint32_t bOff[3]; int bSwz;
    {
        int r = wn * 16 + l15;
        bSwz = r & 7;
#pragma unroll
        for (int t = 0; t < 3; t++) bOff[t] = S_TA + (t * 64 + r) * 128;
    }

    float acc[3][2][2][4];
#pragma unroll
    for (int t = 0; t < 3; t++)
#pragma unroll
        for (int mi = 0; mi < 2; mi++)
#pragma unroll
            for (int ni = 0; ni < 2; ni++)
#pragma unroll
                for (int r = 0; r < 4; r++) acc[t][mi][ni][r] = 0.0f;

    const int nt = K >> 6;
    auto LOAD = [&](int st, int kt) {
        const uint32_t so = st * S_STRIDE;
#pragma unroll
        for (int p = 0; p < 2; p++) cpa16(dA[p] + so, srcA[p] + kt, 16);
#pragma unroll
        for (int p = 0; p < 6; p++) cpa16(dB[p] + so, srcB[p] + kt, bOK[p] ? 16 : 0);
    };

    LOAD(0, 0); cp_commit();
    LOAD(1, 64); cp_commit();

    for (int i = 0; i < nt; i++) {
        cp_wait<1>();
        __syncthreads();
        if (i + 2 < nt) LOAD((i + 2) % 3, (i + 2) << 6);
        cp_commit();

        const uint32_t base = smb + (i % 3) * S_STRIDE;
#pragma unroll
        for (int s = 0; s < 4; s++) {
            const int ch = 2 * s + hi;
            unsigned af[2][4], bt[3][4];
#pragma unroll
            for (int mi = 0; mi < 2; mi++)
                ldsm4(af[mi][0], af[mi][1], af[mi][2], af[mi][3],
                      base + aOff[mi] + ((ch ^ aSwz[mi]) << 4));
#pragma unroll
            for (int t = 0; t < 3; t++)
                ldsm4(bt[t][0], bt[t][1], bt[t][2], bt[t][3],
                      base + bOff[t] + ((ch ^ bSwz) << 4));
#pragma unroll
            for (int t = 0; t < 3; t++)
#pragma unroll
                for (int mi = 0; mi < 2; mi++) {
                    mma_f16(acc[t][mi][0][0], acc[t][mi][0][1],
                            acc[t][mi][0][2], acc[t][mi][0][3],
                            af[mi][0], af[mi][1], af[mi][2], af[mi][3],
                            bt[t][0], bt[t][2]);
                    mma_f16(acc[t][mi][1][0], acc[t][mi][1][1],
                            acc[t][mi][1][2], acc[t][mi][1][3],
                            af[mi][0], af[mi][1], af[mi][2], af[mi][3],
                            bt[t][1], bt[t][3]);
                }
        }
    }

#pragma unroll
    for (int mi = 0; mi < 2; mi++)
#pragma unroll
        for (int ni = 0; ni < 2; ni++) {
            int mA = m0 + wm * 32 + mi * 16 + lr;
            int nA = n0 + wn * 16 + ni * 8 + lc * 2;
#pragma unroll
            for (int r = 0; r < 4; r++) {
                int mm = mA + ((r >= 2) ? 8 : 0);
                int nn = nA + (r & 1);
                if (nn < N) {
                    int d = (nn >= 1000);
                    int base = d * 4000 + (nn - d * 1000);
                    float gi = acc[0][mi][ni][r] + S.bG[base];
                    float gg = acc[1][mi][ni][r] + S.bG[base + 2000];
                    float go = acc[2][mi][ni][r] + S.bG[base + 3000];
                    float cc = sigf(gi) * tanh_fast(gg);
                    float h = sigf(go) * tanh_fast(cc);
                    float o = scale * h;
                    if (S.accum) o += S.Acc[(size_t)mm * N + nn];
                    if (S.out16 == 0) {
                        S.Cf[(size_t)mm * N + nn] = o;
                    } else if (S.out16 == 1) {
                        S.Ch[(size_t)mm * N + nn] = __float2half_rn(o);
                    } else {
                        if (mm < BB) S.Cf[(size_t)mm * N + nn] = o;
                        else S.Ch[(size_t)(mm - BB) * N + nn] = __float2half_rn(o);
                    }
                }
            }
        }
}

// ---------------- paired neighbor mean: [1024,24,E] -> [1024,E] --------------
__global__ void mean16(const __half* __restrict__ Z, __half* __restrict__ out) {
    int idx = blockIdx.x * blockDim.x + threadIdx.x;
    if (idx >= 2 * BB * EE) return;
    int bI = idx / EE, n = idx % EE;
    float s = 0.f;
#pragma unroll 4
    for (int j = 0; j < 24; j++) s += __half2float(Z[(size_t)(bI * 24 + j) * EE + n]);
    out[idx] = __float2half_rn(s * (1.0f / 24.0f));
}

// ---------------- 3-way attention combine ------------------------------------
__global__ void attention_kernel(const float* __restrict__ c, const float* __restrict__ u,
                                 const float* __restrict__ p, const float* __restrict__ att,
                                 float* __restrict__ out) {
    int bI = blockIdx.x, tid = threadIdx.x;
    const float* cb = c + (size_t)bI * EE;
    const float* ub = u + (size_t)bI * EE;
    const float* pb = p + (size_t)bI * EE;
    float s0 = 0.f, s1 = 0.f, s2 = 0.f, s3 = 0.f;
    for (int n = tid; n < EE; n += 256) {
        float a0 = att[n], a1 = att[EE + n];
        float cv = cb[n];
        s0 += cv * a0;
        s1 += cv * a1;
        s2 += ub[n] * a1;
        s3 += pb[n] * a1;
    }
    __shared__ float red[4][256];
    red[0][tid] = s0; red[1][tid] = s1; red[2][tid] = s2; red[3][tid] = s3;
    __syncthreads();
    for (int s = 128; s > 0; s >>= 1) {
        if (tid < s) {
#pragma unroll
            for (int q = 0; q < 4; q++) red[q][tid] += red[q][tid + s];
        }
        __syncthreads();
    }
    __shared__ float w[3];
    if (tid == 0) {
        float sc[3];
        sc[0] = red[0][0] + red[1][0];
        sc[1] = red[0][0] + red[2][0];
        sc[2] = red[0][0] + red[3][0];
#pragma unroll
        for (int k = 0; k < 3; k++) sc[k] = sc[k] > 0.f ? sc[k] : 0.01f * sc[k];
        float mx = fmaxf(sc[0], fmaxf(sc[1], sc[2]));
        float e0 = __expf(sc[0] - mx), e1 = __expf(sc[1] - mx), e2 = __expf(sc[2] - mx);
        float inv = 1.0f / (e0 + e1 + e2);
        w[0] = e0 * inv; w[1] = e1 * inv; w[2] = e2 * inv;
    }
    __syncthreads();
    float w0 = w[0], w1 = w[1], w2 = w[2];
    for (int n = tid; n < EE; n += 256)
        out[(size_t)bI * EE + n] = w0 * cb[n] + w1 * ub[n] + w2 * pb[n];
}

// ---------------------------------------------------------------------------
extern "C" void kernel_launch(void* const* d_in, const int* in_sizes, int n_in,
                              void* d_out, int out_size) {
    const float* c_text  = (const float*)d_in[0];
    const float* c_image = (const float*)d_in[1];
    const float* p_text  = (const float*)d_in[2];
    const float* p_image = (const float*)d_in[3];
    const float* u_text  = (const float*)d_in[4];
    const float* u_other = (const float*)d_in[5];
    const float* W_lt = (const float*)d_in[6],  *b_lt = (const float*)d_in[7];
    const float* W_li = (const float*)d_in[8],  *b_li = (const float*)d_in[9];
    const float* W_lo = (const float*)d_in[10], *b_lo = (const float*)d_in[11];
    const float* lstm_t_W = (const float*)d_in[12], *lstm_t_b = (const float*)d_in[13];
    const float* lstm_i_W = (const float*)d_in[14], *lstm_i_b = (const float*)d_in[15];
    const float* lstm_o_W = (const float*)d_in[16], *lstm_o_b = (const float*)d_in[17];
    const float* ua_lin_W = (const float*)d_in[18], *ua_lin_b = (const float*)d_in[19];
    const float* ua_lstm_W = (const float*)d_in[20], *ua_lstm_b = (const float*)d_in[21];
    const float* ua_out_W = (const float*)d_in[22], *ua_out_b = (const float*)d_in[23];
    const float* pa_lin_W = (const float*)d_in[24], *pa_lin_b = (const float*)d_in[25];
    const float* pa_lstm_W = (const float*)d_in[26], *pa_lstm_b = (const float*)d_in[27];
    const float* pa_out_W = (const float*)d_in[28], *pa_out_b = (const float*)d_in[29];
    const float* p_att = (const float*)d_in[30];
    float* out = (float*)d_out;

    __half *in16, *w16, *bufX, *Hp16, *Hu16, *H2, *Hm;
    float *Hc, *Ht32, *uagg, *pagg;
    cudaGetSymbolAddress((void**)&in16, g_in16);
    cudaGetSymbolAddress((void**)&w16,  g_w16);
    cudaGetSymbolAddress((void**)&bufX, g_bufX);
    cudaGetSymbolAddress((void**)&Hc,   g_Hc);
    cudaGetSymbolAddress((void**)&Ht32, g_Ht32);
    cudaGetSymbolAddress((void**)&Hp16, g_Hp16);
    cudaGetSymbolAddress((void**)&Hu16, g_Hu16);
    cudaGetSymbolAddress((void**)&H2,   g_H2);
    cudaGetSymbolAddress((void**)&Hm,   g_Hm);
    cudaGetSymbolAddress((void**)&uagg, g_uagg);
    cudaGetSymbolAddress((void**)&pagg, g_pagg);

    cudaFuncSetAttribute(gemm_lin16<true>,
                         cudaFuncAttributeMaxDynamicSharedMemorySize, SMEM_GEMM);
    cudaFuncSetAttribute(gemm_lin16<false>,
                         cudaFuncAttributeMaxDynamicSharedMemorySize, SMEM_GEMM);
    cudaFuncSetAttribute(gemm_lstm16,
                         cudaFuncAttributeMaxDynamicSharedMemorySize, SMEM_GEMM);

    // ---- 1: weight linears (7 segs; grid sized to largest = 4M elems) ----
    {
        CvtSegs cs{};
        cs.src[0] = W_lt;     cs.dst[0] = w16 + O_WLT;   cs.n[0] = 512 * 768;
        cs.src[1] = W_li;     cs.dst[1] = w16 + O_WLI;   cs.n[1] = 512 * 2048;
        cs.src[2] = W_lo;     cs.dst[2] = w16 + O_WLO;   cs.n[2] = 512 * 512;
        cs.src[3] = ua_lin_W; cs.dst[3] = w16 + O_UALIN; cs.n[3] = 512 * 2000;
        cs.src[4] = pa_lin_W; cs.dst[4] = w16 + O_PALIN; cs.n[4] = 512 * 2000;
        cs.src[5] = ua_out_W; cs.dst[5] = w16 + O_UAOUT; cs.n[5] = 2000 * 2000;
        cs.src[6] = pa_out_W; cs.dst[6] = w16 + O_PAOUT; cs.n[6] = 2000 * 2000;
        int gx = (2000 * 2000 / 8 + 255) / 256;
        cvt_many<<<dim3(gx, 1, 7), 256>>>(cs);
    }
    // ---- 2: lstm weight gathers (5 via z, full grid) ----
    {
        Lstm5 ws{ { lstm_t_W, lstm_i_W, lstm_o_W, ua_lstm_W, pa_lstm_W } };
        int gx = (3 * 2000 * 512 / 8 + 255) / 256;
        cvt_lstm5<<<dim3(gx, 1, 5), 256>>>(ws, w16);
    }
    // ---- 3: inputs (6 segs; grid sized to largest = 25.2M elems) ----
    {
        CvtSegs cs{};
        cs.src[0] = c_text;  cs.dst[0] = in16 + I_TEXT;                    cs.n[0] = BB * 768;
        cs.src[1] = p_text;  cs.dst[1] = in16 + I_TEXT + BB * 768;         cs.n[1] = MPU * 768;
        cs.src[2] = u_text;  cs.dst[2] = in16 + I_TEXT + (BB + MPU) * 768; cs.n[2] = MPU * 768;
        cs.src[3] = c_image; cs.dst[3] = in16 + I_IMG;                     cs.n[3] = BB * 2048;
        cs.src[4] = p_image; cs.dst[4] = in16 + I_IMG + BB * 2048;         cs.n[4] = MPU * 2048;
        cs.src[5] = u_other; cs.dst[5] = in16 + I_OTH;                     cs.n[5] = MPU * 512;
        int gx = (MPU * 2048 / 8 + 255) / 256;
        cvt_many<<<dim3(gx, 1, 6), 256>>>(cs);
    }

    // ---- 4: all three input linears, one z=3 launch (N=512) ----
    {
        LinSet a{in16 + I_TEXT, w16 + O_WLT, b_lt, nullptr, bufX + X_TEXT, MT, 768};
        LinSet b{in16 + I_IMG,  w16 + O_WLI, b_li, nullptr, bufX + X_IMG,  MI2, 2048};
        LinSet c{in16 + I_OTH,  w16 + O_WLO, b_lo, nullptr, bufX + X_OTH,  MPU, 512};
        gemm_lin16<true><<<dim3(4, MT / 128, 3), 256, SMEM_GEMM>>>(a, b, c, 512);
    }
    // ---- 5: text LSTM -> Ht32 fp32 ----
    {
        LstmSet t{bufX + X_TEXT, w16 + O_LT, lstm_t_b, nullptr, Ht32, nullptr,
                  MT, 0, 0};
        gemm_lstm16<<<dim3(32, MT / 64, 1), 256, SMEM_GEMM>>>(t, t, 0.5f);
    }
    // ---- 6: image LSTM (split Hc/Hp16) + other LSTM (Hu16), z=2 ----
    {
        LstmSet im{bufX + X_IMG, w16 + O_LT + 1 * 3072000, lstm_i_b, Ht32,
                   Hc, Hp16, MI2, 1, 2};
        LstmSet ot{bufX + X_OTH, w16 + O_LT + 2 * 3072000, lstm_o_b,
                   Ht32 + (size_t)MI2 * EE, nullptr, Hu16, MPU, 1, 1};
        gemm_lstm16<<<dim3(32, MI2 / 64, 2), 256, SMEM_GEMM>>>(im, ot, 0.5f);
    }
    // ---- 7: paired agg linears (z=2, N=512, K=2000) ----
    {
        LinSet a{Hu16, w16 + O_UALIN, ua_lin_b, nullptr, bufX, MPU, 2000};
        LinSet b{Hp16, w16 + O_PALIN, pa_lin_b, nullptr, bufX + (size_t)MPU * 512,
                 MPU, 2000};
        gemm_lin16<true><<<dim3(4, MPU / 128, 2), 256, SMEM_GEMM>>>(a, b, b, 512);
    }
    // ---- 8: paired agg LSTMs (z=2) ----
    {
        LstmSet a{bufX, w16 + O_LT + 3 * 3072000, ua_lstm_b, nullptr, nullptr, H2,
                  MPU, 0, 1};
        LstmSet b{bufX + (size_t)MPU * 512, w16 + O_LT + 4 * 3072000, pa_lstm_b,
                  nullptr, nullptr, H2 + (size_t)MPU * EE, MPU, 0, 1};
        gemm_lstm16<<<dim3(32, MPU / 64, 2), 256, SMEM_GEMM>>>(a, b, 1.0f);
    }
    // ---- 9: paired neighbor mean ----
    mean16<<<(2 * BB * EE + 255) / 256, 256>>>(H2, Hm);
    // ---- 10: paired out-linears (z=2, N=2000, fp32 out) ----
    {
        LinSet a{Hm, w16 + O_UAOUT, ua_out_b, uagg, nullptr, BB, 2000};
        LinSet b{Hm + (size_t)BB * EE, w16 + O_PAOUT, pa_out_b, pagg, nullptr,
                 BB, 2000};
        gemm_lin16<false><<<dim3(16, BB / 128, 2), 256, SMEM_GEMM>>>(a, b, b, 2000);
    }
    // ---- 11: attention combine ----
    attention_kernel<<<BB, 256>>>(Hc, uagg, pagg, p_att, out);
}

// round 11
// speedup vs baseline: 7.0617x; 1.2757x over previous
#include <cuda_runtime.h>
#include <cuda_fp16.h>
#include <cstdint>

// ---------------------------------------------------------------------------
// Het_GNN forward — fp16 mma.sync, BK=64 3-stage, 2 CTAs/SM, cp.async.cg,
// hardware-tanh LSTM epilogue. 11 launches.
// ---------------------------------------------------------------------------
#define BB   512
#define MPU  12288
#define MT   25088
#define MI2  12800
#define EE   2000

__device__ __half g_in16 [51773440];
__device__ __half g_w16  [27111936];
__device__ __half g_bufX [25690112];
__device__ float  g_Ht32 [MT * EE];
__device__ float  g_Hc   [BB  * EE];
__device__ __half g_Hp16 [MPU * EE];
__device__ __half g_Hu16 [MPU * EE];
__device__ __half g_H2   [2 * MPU * EE];
__device__ __half g_Hm   [2 * BB * EE];
__device__ float  g_uagg [BB * EE];
__device__ float  g_pagg [BB * EE];

#define I_TEXT 0
#define I_IMG  19267584
#define I_OTH  45481984
#define X_TEXT 0
#define X_IMG  12845056
#define X_OTH  19398656
#define O_WLT   0
#define O_WLI   393216
#define O_WLO   1441792
#define O_LT    1703936      // 5 lstm gathers, stride 3072000
#define O_UALIN 17063936
#define O_PALIN 18087936
#define O_UAOUT 19111936
#define O_PAOUT 23111936

// ---------------- helpers ----------------------------------------------------
__device__ __forceinline__ float tanh_hw(float x) {
    float r;
    asm("tanh.approx.f32 %0, %1;" : "=f"(r) : "f"(x));
    return r;
}
__device__ __forceinline__ float sig_hw(float x) {
    return fmaf(0.5f, tanh_hw(0.5f * x), 0.5f);
}
__device__ __forceinline__ void mma_f16(float& d0, float& d1, float& d2, float& d3,
                                        unsigned a0, unsigned a1, unsigned a2, unsigned a3,
                                        unsigned b0, unsigned b1) {
    asm volatile(
        "mma.sync.aligned.m16n8k16.row.col.f32.f16.f16.f32 "
        "{%0,%1,%2,%3}, {%4,%5,%6,%7}, {%8,%9}, {%0,%1,%2,%3};"
        : "+f"(d0), "+f"(d1), "+f"(d2), "+f"(d3)
        : "r"(a0), "r"(a1), "r"(a2), "r"(a3), "r"(b0), "r"(b1));
}
__device__ __forceinline__ void ldsm4(unsigned& r0, unsigned& r1, unsigned& r2,
                                      unsigned& r3, uint32_t a) {
    asm volatile("ldmatrix.sync.aligned.m8n8.x4.shared.b16 {%0,%1,%2,%3}, [%4];"
                 : "=r"(r0), "=r"(r1), "=r"(r2), "=r"(r3) : "r"(a));
}
__device__ __forceinline__ void cpa16(uint32_t dst, const void* src, int srcbytes) {
    asm volatile("cp.async.cg.shared.global [%0], [%1], 16, %2;"
                 :: "r"(dst), "l"(src), "r"(srcbytes) : "memory");
}
__device__ __forceinline__ void cp_commit() {
    asm volatile("cp.async.commit_group;" ::: "memory");
}
template<int N>
__device__ __forceinline__ void cp_wait() {
    asm volatile("cp.async.wait_group %0;" :: "n"(N) : "memory");
}
__device__ __forceinline__ int gather_row(int n, int t) {
    int d = (n >= 1000);
    int toff = (t == 0) ? 0 : (t == 1 ? 2000 : 3000);
    return d * 4000 + toff + (n - d * 1000);
}

// ---------------- batched conversion kernels (1 group / thread) --------------
struct CvtSegs {
    const float* src[8];
    __half* dst[8];
    int n[8];
};
__global__ void cvt_many(CvtSegs cs) {
    const int z = blockIdx.z;
    const int n = cs.n[z];
    const int i = (blockIdx.x * blockDim.x + threadIdx.x) * 8;
    if (i >= n) return;
    const float* __restrict__ src = cs.src[z];
    __half* __restrict__ dst = cs.dst[z];
    float4 a = *(const float4*)(src + i);
    float4 b = *(const float4*)(src + i + 4);
    __half2 h[4] = { __floats2half2_rn(a.x, a.y), __floats2half2_rn(a.z, a.w),
                     __floats2half2_rn(b.x, b.y), __floats2half2_rn(b.z, b.w) };
    *(uint4*)(dst + i) = *(uint4*)h;
}
struct Lstm5 { const float* W[5]; };
__global__ void cvt_lstm5(Lstm5 ws, __half* __restrict__ base) {
    const int z = blockIdx.z;
    const int idx = (blockIdx.x * blockDim.x + threadIdx.x) * 8;
    if (idx >= 3 * 2000 * 512) return;
    const float* __restrict__ W = ws.W[z];
    __half* __restrict__ dst = base + O_LT + (size_t)z * 3072000;
    int k = idx & 511;
    int n = (idx >> 9) % 2000;
    int t = idx / (2000 * 512);
    const float* s = W + (size_t)gather_row(n, t) * 512 + k;
    float4 a = *(const float4*)s;
    float4 b = *(const float4*)(s + 4);
    __half2 h[4] = { __floats2half2_rn(a.x, a.y), __floats2half2_rn(a.z, a.w),
                     __floats2half2_rn(b.x, b.y), __floats2half2_rn(b.z, b.w) };
    *(uint4*)(dst + idx) = *(uint4*)h;
}

// ---------------- arg structs -------------------------------------------------
struct LinSet  { const __half* A; const __half* W; const float* bias;
                 float* Cf; __half* Ch; int M; int K; };
struct LstmSet { const __half* A; const __half* Wg; const float* bG;
                 const float* Acc; float* Cf; __half* Ch;
                 int M; int accum; int out16; };  // out16: 0 fp32, 1 fp16, 2 split@512

// ===========================================================================
// gemm_lin16<OUT16>: C[M,N] = A[M,K] @ W[N,K]^T + bias
// BM=128, BN=128, BK=64 (128B rows, chunk c of row m at c^(m&7)), 256 thr
// (8 warps 2m x 4n), 3-stage cp.async (32KB/stage). 2 CTAs/SM.
// ===========================================================================
#define L_TA 16384
#define L_STRIDE 32768
#define SMEM_GEMM (3 * 32768)

template<bool OUT16>
__global__ __launch_bounds__(256, 2) void gemm_lin16(
    LinSet s0, LinSet s1, LinSet s2, int N) {
    const LinSet S = (blockIdx.z == 0) ? s0 : (blockIdx.z == 1 ? s1 : s2);
    const int m0 = blockIdx.y * 128, n0 = blockIdx.x * 128;
    if (m0 >= S.M) return;
    const int K = S.K;

    extern __shared__ char sm[];
    const uint32_t smb = (uint32_t)__cvta_generic_to_shared(sm);

    const int tid = threadIdx.x;
    const int wid = tid >> 5, lane = tid & 31;
    const int wm = wid & 1, wn = wid >> 1;
    const int lr = lane >> 2, lc = lane & 3;

    const int prow = tid >> 3, pch = tid & 7;
    const __half* srcA[4];
    uint32_t dA[4];
#pragma unroll
    for (int p = 0; p < 4; p++) {
        int r = prow + 32 * p;
        srcA[p] = S.A + (size_t)(m0 + r) * K + pch * 8;
        dA[p] = smb + r * 128 + ((pch ^ (r & 7)) << 4);
    }
    const __half* srcB[4];
    uint32_t dB[4];
    bool brOK[4];
#pragma unroll
    for (int p = 0; p < 4; p++) {
        int r = prow + 32 * p;
        brOK[p] = (n0 + r) < N;
        srcB[p] = S.W + (size_t)(brOK[p] ? (n0 + r) : 0) * K + pch * 8;
        dB[p] = smb + L_TA + r * 128 + ((pch ^ (r & 7)) << 4);
    }

    const int l15 = lane & 15, hi = lane >> 4;
    uint32_t aOff[4], bOff[2];
    int aSwz[4], bSwz[2];
#pragma unroll
    for (int mi = 0; mi < 4; mi++) {
        int r = wm * 64 + mi * 16 + l15;
        aOff[mi] = r * 128; aSwz[mi] = r & 7;
    }
#pragma unroll
    for (int nj = 0; nj < 2; nj++) {
        int r = wn * 32 + nj * 16 + l15;
        bOff[nj] = L_TA + r * 128; bSwz[nj] = r & 7;
    }

    float acc[4][4][4];
#pragma unroll
    for (int mi = 0; mi < 4; mi++)
#pragma unroll
        for (int ni = 0; ni < 4; ni++)
#pragma unroll
            for (int r = 0; r < 4; r++) acc[mi][ni][r] = 0.0f;

    const int nt = (K + 63) >> 6;
    auto LOAD = [&](int st, int kt) {
        const uint32_t so = st * L_STRIDE;
        const int kb = (kt + pch * 8 + 8 <= K) ? 16 : 0;
#pragma unroll
        for (int p = 0; p < 4; p++) cpa16(dA[p] + so, srcA[p] + kt, kb);
#pragma unroll
        for (int p = 0; p < 4; p++) cpa16(dB[p] + so, srcB[p] + kt, brOK[p] ? kb : 0);
    };

    LOAD(0, 0); cp_commit();
    LOAD(1, 64); cp_commit();

    for (int i = 0; i < nt; i++) {
        cp_wait<1>();
        __syncthreads();
        if (i + 2 < nt) LOAD((i + 2) % 3, (i + 2) << 6);
        cp_commit();

        const uint32_t base = smb + (i % 3) * L_STRIDE;
#pragma unroll
        for (int s = 0; s < 4; s++) {
            const int ch = 2 * s + hi;
            unsigned af[4][4], bq[2][4];
#pragma unroll
            for (int mi = 0; mi < 4; mi++)
                ldsm4(af[mi][0], af[mi][1], af[mi][2], af[mi][3],
                      base + aOff[mi] + ((ch ^ aSwz[mi]) << 4));
#pragma unroll
            for (int nj = 0; nj < 2; nj++)
                ldsm4(bq[nj][0], bq[nj][1], bq[nj][2], bq[nj][3],
                      base + bOff[nj] + ((ch ^ bSwz[nj]) << 4));
#pragma unroll
            for (int mi = 0; mi < 4; mi++)
#pragma unroll
                for (int nj = 0; nj < 2; nj++) {
                    mma_f16(acc[mi][2 * nj][0], acc[mi][2 * nj][1],
                            acc[mi][2 * nj][2], acc[mi][2 * nj][3],
                            af[mi][0], af[mi][1], af[mi][2], af[mi][3],
                            bq[nj][0], bq[nj][2]);
                    mma_f16(acc[mi][2 * nj + 1][0], acc[mi][2 * nj + 1][1],
                            acc[mi][2 * nj + 1][2], acc[mi][2 * nj + 1][3],
                            af[mi][0], af[mi][1], af[mi][2], af[mi][3],
                            bq[nj][1], bq[nj][3]);
                }
        }
    }

#pragma unroll
    for (int mi = 0; mi < 4; mi++) {
        int m = m0 + wm * 64 + mi * 16 + lr;
#pragma unroll
        for (int ni = 0; ni < 4; ni++) {
            int n = n0 + wn * 32 + ni * 8 + lc * 2;
            if (n + 1 < N) {
                float b0 = S.bias[n], b1 = S.bias[n + 1];
                float v00 = acc[mi][ni][0] + b0, v01 = acc[mi][ni][1] + b1;
                float v10 = acc[mi][ni][2] + b0, v11 = acc[mi][ni][3] + b1;
                if (OUT16) {
                    *(__half2*)(S.Ch + (size_t)m * N + n) = __floats2half2_rn(v00, v01);
                    *(__half2*)(S.Ch + (size_t)(m + 8) * N + n) = __floats2half2_rn(v10, v11);
                } else {
                    *(float2*)(S.Cf + (size_t)m * N + n) = make_float2(v00, v01);
                    *(float2*)(S.Cf + (size_t)(m + 8) * N + n) = make_float2(v10, v11);
                }
            } else if (n < N) {
                float b0 = S.bias[n];
                if (OUT16) {
                    S.Ch[(size_t)m * N + n] = __float2half_rn(acc[mi][ni][0] + b0);
                    S.Ch[(size_t)(m + 8) * N + n] = __float2half_rn(acc[mi][ni][2] + b0);
                } else {
                    S.Cf[(size_t)m * N + n] = acc[mi][ni][0] + b0;
                    S.Cf[(size_t)(m + 8) * N + n] = acc[mi][ni][2] + b0;
                }
            }
        }
    }
}

// ===========================================================================
// gemm_lstm16: fused single-step BiLSTM (gates pre-gathered in Wg [3,2000,512])
// out = scale * sig(o)*tanh(sig(i)*tanh(g))  [+ Acc] — hardware tanh epilogue.
// BM=64, BN=64x3 gates, BK=64, 256 thr (8 warps 2m x 4n), 3-stage. K=512.
// out16: 0 fp32, 1 fp16, 2 split (row<512 -> Cf fp32, else Ch fp16 at row-512).
// ===========================================================================
#define S_TA 8192
#define S_STRIDE 32768

__global__ __launch_bounds__(256, 2) void gemm_lstm16(
    LstmSet s0, LstmSet s1, float scale) {
    const int N = 2000, K = 512;
    const LstmSet S = blockIdx.z ? s1 : s0;
    const int m0 = blockIdx.y * 64, n0 = blockIdx.x * 64;
    if (m0 >= S.M) return;

    extern __shared__ char sm[];
    const uint32_t smb = (uint32_t)__cvta_generic_to_shared(sm);

    const int tid = threadIdx.x;
    const int wid = tid >> 5, lane = tid & 31;
    const int wm = wid & 1, wn = wid >> 1;
    const int lr = lane >> 2, lc = lane & 3;

    const int prow = tid >> 3, pch = tid & 7;
    const __half* srcA[2];
    uint32_t dA[2];
#pragma unroll
    for (int p = 0; p < 2; p++) {
        int r = prow + 32 * p;
        srcA[p] = S.A + (size_t)(m0 + r) * K + pch * 8;
        dA[p] = smb + r * 128 + ((pch ^ (r & 7)) << 4);
    }
    const __half* srcB[6];
    uint32_t dB[6];
    bool bOK[6];
#pragma unroll
    for (int p = 0; p < 6; p++) {
        int r = prow + 32 * p;
        int t = r >> 6, rr = r & 63;
        bOK[p] = (n0 + rr) < N;
        srcB[p] = S.Wg + (size_t)(t * 2000 + (bOK[p] ? n0 + rr : 0)) * K + pch * 8;
        dB[p] = smb + S_TA + r * 128 + ((pch ^ (r & 7)) << 4);
    }

    const int l15 = lane & 15, hi = lane >> 4;
    uint32_t aOff[2]; int aSwz[2];
#pragma unroll
    for (int mi = 0; mi < 2; mi++) {
        int r = wm * 32 + mi * 16 + l15;
        aOff[mi] = r * 128; aSwz[mi] = r & 7;
    }
    uint32_t bOff[3]; int bSwz;
    {
        int r = wn * 16 + l15;
        bSwz = r & 7;
#pragma unroll
        for (int t = 0; t < 3; t++) bOff[t] = S_TA + (t * 64 + r) * 128;
    }

    float acc[3][2][2][4];
#pragma unroll
    for (int t = 0; t < 3; t++)
#pragma unroll
        for (int mi = 0; mi < 2; mi++)
#pragma unroll
            for (int ni = 0; ni < 2; ni++)
#pragma unroll
                for (int r = 0; r < 4; r++) acc[t][mi][ni][r] = 0.0f;

    const int nt = K >> 6;
    auto LOAD = [&](int st, int kt) {
        const uint32_t so = st * S_STRIDE;
#pragma unroll
        for (int p = 0; p < 2; p++) cpa16(dA[p] + so, srcA[p] + kt, 16);
#pragma unroll
        for (int p = 0; p < 6; p++) cpa16(dB[p] + so, srcB[p] + kt, bOK[p] ? 16 : 0);
    };

    LOAD(0, 0); cp_commit();
    LOAD(1, 64); cp_commit();

    for (int i = 0; i < nt; i++) {
        cp_wait<1>();
        __syncthreads();
        if (i + 2 < nt) LOAD((i + 2) % 3, (i + 2) << 6);
        cp_commit();

        const uint32_t base = smb + (i % 3) * S_STRIDE;
#pragma unroll
        for (int s = 0; s < 4; s++) {
            const int ch = 2 * s + hi;
            unsigned af[2][4], bt[3][4];
#pragma unroll
            for (int mi = 0; mi < 2; mi++)
                ldsm4(af[mi][0], af[mi][1], af[mi][2], af[mi][3],
                      base + aOff[mi] + ((ch ^ aSwz[mi]) << 4));
#pragma unroll
            for (int t = 0; t < 3; t++)
                ldsm4(bt[t][0], bt[t][1], bt[t][2], bt[t][3],
                      base + bOff[t] + ((ch ^ bSwz) << 4));
#pragma unroll
            for (int t = 0; t < 3; t++)
#pragma unroll
                for (int mi = 0; mi < 2; mi++) {
                    mma_f16(acc[t][mi][0][0], acc[t][mi][0][1],
                            acc[t][mi][0][2], acc[t][mi][0][3],
                            af[mi][0], af[mi][1], af[mi][2], af[mi][3],
                            bt[t][0], bt[t][2]);
                    mma_f16(acc[t][mi][1][0], acc[t][mi][1][1],
                            acc[t][mi][1][2], acc[t][mi][1][3],
                            af[mi][0], af[mi][1], af[mi][2], af[mi][3],
                            bt[t][1], bt[t][3]);
                }
        }
    }

    // ---- hardware-tanh epilogue, vectorized pair stores ----------------------
#pragma unroll
    for (int mi = 0; mi < 2; mi++)
#pragma unroll
        for (int ni = 0; ni < 2; ni++) {
            int mA = m0 + wm * 32 + mi * 16 + lr;
            int nA = n0 + wn * 16 + ni * 8 + lc * 2;
#pragma unroll
            for (int half = 0; half < 2; half++) {     // r pair (0,1) then (2,3)
                int mm = mA + half * 8;
                float o[2];
#pragma unroll
                for (int q = 0; q < 2; q++) {
                    int r = half * 2 + q;
                    int nn = nA + q;
                    int d = (nn >= 1000);
                    int base = d * 4000 + (nn - d * 1000);
                    float gi = acc[0][mi][ni][r] + S.bG[base];
                    float gg = acc[1][mi][ni][r] + S.bG[base + 2000];
                    float go = acc[2][mi][ni][r] + S.bG[base + 3000];
                    float cc = sig_hw(gi) * tanh_hw(gg);
                    o[q] = scale * sig_hw(go) * tanh_hw(cc);
                }
                if (nA + 1 < N) {
                    if (S.accum) {
                        float2 av = *(const float2*)(S.Acc + (size_t)mm * N + nA);
                        o[0] += av.x; o[1] += av.y;
                    }
                    if (S.out16 == 0) {
                        *(float2*)(S.Cf + (size_t)mm * N + nA) = make_float2(o[0], o[1]);
                    } else if (S.out16 == 1) {
                        *(__half2*)(S.Ch + (size_t)mm * N + nA) = __floats2half2_rn(o[0], o[1]);
                    } else {
                        if (mm < BB)
                            *(float2*)(S.Cf + (size_t)mm * N + nA) = make_float2(o[0], o[1]);
                        else
                            *(__half2*)(S.Ch + (size_t)(mm - BB) * N + nA) =
                                __floats2half2_rn(o[0], o[1]);
                    }
                } else if (nA < N) {
                    float v = o[0];
                    if (S.accum) v += S.Acc[(size_t)mm * N + nA];
                    if (S.out16 == 0) S.Cf[(size_t)mm * N + nA] = v;
                    else if (S.out16 == 1) S.Ch[(size_t)mm * N + nA] = __float2half_rn(v);
                    else {
                        if (mm < BB) S.Cf[(size_t)mm * N + nA] = v;
                        else S.Ch[(size_t)(mm - BB) * N + nA] = __float2half_rn(v);
                    }
                }
            }
        }
}

// ---------------- paired neighbor mean: [1024,24,E] -> [1024,E] --------------
__global__ void mean16(const __half* __restrict__ Z, __half* __restrict__ out) {
    int idx = blockIdx.x * blockDim.x + threadIdx.x;
    if (idx >= 2 * BB * EE) return;
    int bI = idx / EE, n = idx % EE;
    float s = 0.f;
#pragma unroll 4
    for (int j = 0; j < 24; j++) s += __half2float(Z[(size_t)(bI * 24 + j) * EE + n]);
    out[idx] = __float2half_rn(s * (1.0f / 24.0f));
}

// ---------------- 3-way attention combine ------------------------------------
__global__ void attention_kernel(const float* __restrict__ c, const float* __restrict__ u,
                                 const float* __restrict__ p, const float* __restrict__ att,
                                 float* __restrict__ out) {
    int bI = blockIdx.x, tid = threadIdx.x;
    const float* cb = c + (size_t)bI * EE;
    const float* ub = u + (size_t)bI * EE;
    const float* pb = p + (size_t)bI * EE;
    float s0 = 0.f, s1 = 0.f, s2 = 0.f, s3 = 0.f;
    for (int n = tid; n < EE; n += 256) {
        float a0 = att[n], a1 = att[EE + n];
        float cv = cb[n];
        s0 += cv * a0;
        s1 += cv * a1;
        s2 += ub[n] * a1;
        s3 += pb[n] * a1;
    }
    __shared__ float red[4][256];
    red[0][tid] = s0; red[1][tid] = s1; red[2][tid] = s2; red[3][tid] = s3;
    __syncthreads();
    for (int s = 128; s > 0; s >>= 1) {
        if (tid < s) {
#pragma unroll
            for (int q = 0; q < 4; q++) red[q][tid] += red[q][tid + s];
        }
        __syncthreads();
    }
    __shared__ float w[3];
    if (tid == 0) {
        float sc[3];
        sc[0] = red[0][0] + red[1][0];
        sc[1] = red[0][0] + red[2][0];
        sc[2] = red[0][0] + red[3][0];
#pragma unroll
        for (int k = 0; k < 3; k++) sc[k] = sc[k] > 0.f ? sc[k] : 0.01f * sc[k];
        float mx = fmaxf(sc[0], fmaxf(sc[1], sc[2]));
        float e0 = __expf(sc[0] - mx), e1 = __expf(sc[1] - mx), e2 = __expf(sc[2] - mx);
        float inv = 1.0f / (e0 + e1 + e2);
        w[0] = e0 * inv; w[1] = e1 * inv; w[2] = e2 * inv;
    }
    __syncthreads();
    float w0 = w[0], w1 = w[1], w2 = w[2];
    for (int n = tid; n < EE; n += 256)
        out[(size_t)bI * EE + n] = w0 * cb[n] + w1 * ub[n] + w2 * pb[n];
}

// ---------------------------------------------------------------------------
extern "C" void kernel_launch(void* const* d_in, const int* in_sizes, int n_in,
                              void* d_out, int out_size) {
    const float* c_text  = (const float*)d_in[0];
    const float* c_image = (const float*)d_in[1];
    const float* p_text  = (const float*)d_in[2];
    const float* p_image = (const float*)d_in[3];
    const float* u_text  = (const float*)d_in[4];
    const float* u_other = (const float*)d_in[5];
    const float* W_lt = (const float*)d_in[6],  *b_lt = (const float*)d_in[7];
    const float* W_li = (const float*)d_in[8],  *b_li = (const float*)d_in[9];
    const float* W_lo = (const float*)d_in[10], *b_lo = (const float*)d_in[11];
    const float* lstm_t_W = (const float*)d_in[12], *lstm_t_b = (const float*)d_in[13];
    const float* lstm_i_W = (const float*)d_in[14], *lstm_i_b = (const float*)d_in[15];
    const float* lstm_o_W = (const float*)d_in[16], *lstm_o_b = (const float*)d_in[17];
    const float* ua_lin_W = (const float*)d_in[18], *ua_lin_b = (const float*)d_in[19];
    const float* ua_lstm_W = (const float*)d_in[20], *ua_lstm_b = (const float*)d_in[21];
    const float* ua_out_W = (const float*)d_in[22], *ua_out_b = (const float*)d_in[23];
    const float* pa_lin_W = (const float*)d_in[24], *pa_lin_b = (const float*)d_in[25];
    const float* pa_lstm_W = (const float*)d_in[26], *pa_lstm_b = (const float*)d_in[27];
    const float* pa_out_W = (const float*)d_in[28], *pa_out_b = (const float*)d_in[29];
    const float* p_att = (const float*)d_in[30];
    float* out = (float*)d_out;

    __half *in16, *w16, *bufX, *Hp16, *Hu16, *H2, *Hm;
    float *Hc, *Ht32, *uagg, *pagg;
    cudaGetSymbolAddress((void**)&in16, g_in16);
    cudaGetSymbolAddress((void**)&w16,  g_w16);
    cudaGetSymbolAddress((void**)&bufX, g_bufX);
    cudaGetSymbolAddress((void**)&Hc,   g_Hc);
    cudaGetSymbolAddress((void**)&Ht32, g_Ht32);
    cudaGetSymbolAddress((void**)&Hp16, g_Hp16);
    cudaGetSymbolAddress((void**)&Hu16, g_Hu16);
    cudaGetSymbolAddress((void**)&H2,   g_H2);
    cudaGetSymbolAddress((void**)&Hm,   g_Hm);
    cudaGetSymbolAddress((void**)&uagg, g_uagg);
    cudaGetSymbolAddress((void**)&pagg, g_pagg);

    cudaFuncSetAttribute(gemm_lin16<true>,
                         cudaFuncAttributeMaxDynamicSharedMemorySize, SMEM_GEMM);
    cudaFuncSetAttribute(gemm_lin16<false>,
                         cudaFuncAttributeMaxDynamicSharedMemorySize, SMEM_GEMM);
    cudaFuncSetAttribute(gemm_lstm16,
                         cudaFuncAttributeMaxDynamicSharedMemorySize, SMEM_GEMM);

    // ---- 1: weight linears (7 segs) ----
    {
        CvtSegs cs{};
        cs.src[0] = W_lt;     cs.dst[0] = w16 + O_WLT;   cs.n[0] = 512 * 768;
        cs.src[1] = W_li;     cs.dst[1] = w16 + O_WLI;   cs.n[1] = 512 * 2048;
        cs.src[2] = W_lo;     cs.dst[2] = w16 + O_WLO;   cs.n[2] = 512 * 512;
        cs.src[3] = ua_lin_W; cs.dst[3] = w16 + O_UALIN; cs.n[3] = 512 * 2000;
        cs.src[4] = pa_lin_W; cs.dst[4] = w16 + O_PALIN; cs.n[4] = 512 * 2000;
        cs.src[5] = ua_out_W; cs.dst[5] = w16 + O_UAOUT; cs.n[5] = 2000 * 2000;
        cs.src[6] = pa_out_W; cs.dst[6] = w16 + O_PAOUT; cs.n[6] = 2000 * 2000;
        int gx = (2000 * 2000 / 8 + 255) / 256;
        cvt_many<<<dim3(gx, 1, 7), 256>>>(cs);
    }
    // ---- 2: lstm weight gathers (5 via z) ----
    {
        Lstm5 ws{ { lstm_t_W, lstm_i_W, lstm_o_W, ua_lstm_W, pa_lstm_W } };
        int gx = (3 * 2000 * 512 / 8 + 255) / 256;
        cvt_lstm5<<<dim3(gx, 1, 5), 256>>>(ws, w16);
    }
    // ---- 3: inputs (6 segs) ----
    {
        CvtSegs cs{};
        cs.src[0] = c_text;  cs.dst[0] = in16 + I_TEXT;                    cs.n[0] = BB * 768;
        cs.src[1] = p_text;  cs.dst[1] = in16 + I_TEXT + BB * 768;         cs.n[1] = MPU * 768;
        cs.src[2] = u_text;  cs.dst[2] = in16 + I_TEXT + (BB + MPU) * 768; cs.n[2] = MPU * 768;
        cs.src[3] = c_image; cs.dst[3] = in16 + I_IMG;                     cs.n[3] = BB * 2048;
        cs.src[4] = p_image; cs.dst[4] = in16 + I_IMG + BB * 2048;         cs.n[4] = MPU * 2048;
        cs.src[5] = u_other; cs.dst[5] = in16 + I_OTH;                     cs.n[5] = MPU * 512;
        int gx = (MPU * 2048 / 8 + 255) / 256;
        cvt_many<<<dim3(gx, 1, 6), 256>>>(cs);
    }

    // ---- 4: all three input linears, one z=3 launch (N=512) ----
    {
        LinSet a{in16 + I_TEXT, w16 + O_WLT, b_lt, nullptr, bufX + X_TEXT, MT, 768};
        LinSet b{in16 + I_IMG,  w16 + O_WLI, b_li, nullptr, bufX + X_IMG,  MI2, 2048};
        LinSet c{in16 + I_OTH,  w16 + O_WLO, b_lo, nullptr, bufX + X_OTH,  MPU, 512};
        gemm_lin16<true><<<dim3(4, MT / 128, 3), 256, SMEM_GEMM>>>(a, b, c, 512);
    }
    // ---- 5: text LSTM -> Ht32 fp32 ----
    {
        LstmSet t{bufX + X_TEXT, w16 + O_LT, lstm_t_b, nullptr, Ht32, nullptr,
                  MT, 0, 0};
        gemm_lstm16<<<dim3(32, MT / 64, 1), 256, SMEM_GEMM>>>(t, t, 0.5f);
    }
    // ---- 6: image LSTM (split Hc/Hp16) + other LSTM (Hu16), z=2 ----
    {
        LstmSet im{bufX + X_IMG, w16 + O_LT + 1 * 3072000, lstm_i_b, Ht32,
                   Hc, Hp16, MI2, 1, 2};
        LstmSet ot{bufX + X_OTH, w16 + O_LT + 2 * 3072000, lstm_o_b,
                   Ht32 + (size_t)MI2 * EE, nullptr, Hu16, MPU, 1, 1};
        gemm_lstm16<<<dim3(32, MI2 / 64, 2), 256, SMEM_GEMM>>>(im, ot, 0.5f);
    }
    // ---- 7: paired agg linears (z=2, N=512, K=2000) ----
    {
        LinSet a{Hu16, w16 + O_UALIN, ua_lin_b, nullptr, bufX, MPU, 2000};
        LinSet b{Hp16, w16 + O_PALIN, pa_lin_b, nullptr, bufX + (size_t)MPU * 512,
                 MPU, 2000};
        gemm_lin16<true><<<dim3(4, MPU / 128, 2), 256, SMEM_GEMM>>>(a, b, b, 512);
    }
    // ---- 8: paired agg LSTMs (z=2) ----
    {
        LstmSet a{bufX, w16 + O_LT + 3 * 3072000, ua_lstm_b, nullptr, nullptr, H2,
                  MPU, 0, 1};
        LstmSet b{bufX + (size_t)MPU * 512, w16 + O_LT + 4 * 3072000, pa_lstm_b,
                  nullptr, nullptr, H2 + (size_t)MPU * EE, MPU, 0, 1};
        gemm_lstm16<<<dim3(32, MPU / 64, 2), 256, SMEM_GEMM>>>(a, b, 1.0f);
    }
    // ---- 9: paired neighbor mean ----
    mean16<<<(2 * BB * EE + 255) / 256, 256>>>(H2, Hm);
    // ---- 10: paired out-linears (z=2, N=2000, fp32 out) ----
    {
        LinSet a{Hm, w16 + O_UAOUT, ua_out_b, uagg, nullptr, BB, 2000};
        LinSet b{Hm + (size_t)BB * EE, w16 + O_PAOUT, pa_out_b, pagg, nullptr,
                 BB, 2000};
        gemm_lin16<false><<<dim3(16, BB / 128, 2), 256, SMEM_GEMM>>>(a, b, b, 2000);
    }
    // ---- 11: attention combine ----
    attention_kernel<<<BB, 256>>>(Hc, uagg, pagg, p_att, out);
}

// round 12
// speedup vs baseline: 7.2676x; 1.0292x over previous
#include <cuda_runtime.h>
#include <cuda_fp16.h>
#include <cstdint>

// ---------------------------------------------------------------------------
// Het_GNN forward — fp16 mma.sync, BK=64 3-stage, 2 CTAs/SM, cp.async.cg,
// hw-tanh epilogue, fp16 intermediates, vectorized mean. 11 launches.
// ---------------------------------------------------------------------------
#define BB   512
#define MPU  12288
#define MT   25088
#define MI2  12800
#define EE   2000

__device__ __half g_in16 [51773440];
__device__ __half g_w16  [27111936];
__device__ __half g_bufX [25690112];
__device__ __half g_Ht16 [MT * EE];        // fp16 LSTM pass-1 arena
__device__ float  g_Hc   [BB  * EE];
__device__ __half g_Hp16 [MPU * EE];
__device__ __half g_Hu16 [MPU * EE];
__device__ __half g_H2   [2 * MPU * EE];
__device__ __half g_Hm   [2 * BB * EE];
__device__ float  g_uagg [BB * EE];
__device__ float  g_pagg [BB * EE];

#define I_TEXT 0
#define I_IMG  19267584
#define I_OTH  45481984
#define X_TEXT 0
#define X_IMG  12845056
#define X_OTH  19398656
#define O_WLT   0
#define O_WLI   393216
#define O_WLO   1441792
#define O_LT    1703936      // 5 lstm gathers, stride 3072000
#define O_UALIN 17063936
#define O_PALIN 18087936
#define O_UAOUT 19111936
#define O_PAOUT 23111936

// ---------------- helpers ----------------------------------------------------
__device__ __forceinline__ float tanh_hw(float x) {
    float r;
    asm("tanh.approx.f32 %0, %1;" : "=f"(r) : "f"(x));
    return r;
}
__device__ __forceinline__ float sig_hw(float x) {
    return fmaf(0.5f, tanh_hw(0.5f * x), 0.5f);
}
__device__ __forceinline__ void mma_f16(float& d0, float& d1, float& d2, float& d3,
                                        unsigned a0, unsigned a1, unsigned a2, unsigned a3,
                                        unsigned b0, unsigned b1) {
    asm volatile(
        "mma.sync.aligned.m16n8k16.row.col.f32.f16.f16.f32 "
        "{%0,%1,%2,%3}, {%4,%5,%6,%7}, {%8,%9}, {%0,%1,%2,%3};"
        : "+f"(d0), "+f"(d1), "+f"(d2), "+f"(d3)
        : "r"(a0), "r"(a1), "r"(a2), "r"(a3), "r"(b0), "r"(b1));
}
__device__ __forceinline__ void ldsm4(unsigned& r0, unsigned& r1, unsigned& r2,
                                      unsigned& r3, uint32_t a) {
    asm volatile("ldmatrix.sync.aligned.m8n8.x4.shared.b16 {%0,%1,%2,%3}, [%4];"
                 : "=r"(r0), "=r"(r1), "=r"(r2), "=r"(r3) : "r"(a));
}
__device__ __forceinline__ void cpa16(uint32_t dst, const void* src, int srcbytes) {
    asm volatile("cp.async.cg.shared.global [%0], [%1], 16, %2;"
                 :: "r"(dst), "l"(src), "r"(srcbytes) : "memory");
}
__device__ __forceinline__ void cp_commit() {
    asm volatile("cp.async.commit_group;" ::: "memory");
}
template<int N>
__device__ __forceinline__ void cp_wait() {
    asm volatile("cp.async.wait_group %0;" :: "n"(N) : "memory");
}
__device__ __forceinline__ int gather_row(int n, int t) {
    int d = (n >= 1000);
    int toff = (t == 0) ? 0 : (t == 1 ? 2000 : 3000);
    return d * 4000 + toff + (n - d * 1000);
}

// ---------------- batched conversion kernels (1 group / thread) --------------
struct CvtSegs {
    const float* src[8];
    __half* dst[8];
    int n[8];
};
__global__ void cvt_many(CvtSegs cs) {
    const int z = blockIdx.z;
    const int n = cs.n[z];
    const int i = (blockIdx.x * blockDim.x + threadIdx.x) * 8;
    if (i >= n) return;
    const float* __restrict__ src = cs.src[z];
    __half* __restrict__ dst = cs.dst[z];
    float4 a = *(const float4*)(src + i);
    float4 b = *(const float4*)(src + i + 4);
    __half2 h[4] = { __floats2half2_rn(a.x, a.y), __floats2half2_rn(a.z, a.w),
                     __floats2half2_rn(b.x, b.y), __floats2half2_rn(b.z, b.w) };
    *(uint4*)(dst + i) = *(uint4*)h;
}
struct Lstm5 { const float* W[5]; };
__global__ void cvt_lstm5(Lstm5 ws, __half* __restrict__ base) {
    const int z = blockIdx.z;
    const int idx = (blockIdx.x * blockDim.x + threadIdx.x) * 8;
    if (idx >= 3 * 2000 * 512) return;
    const float* __restrict__ W = ws.W[z];
    __half* __restrict__ dst = base + O_LT + (size_t)z * 3072000;
    int k = idx & 511;
    int n = (idx >> 9) % 2000;
    int t = idx / (2000 * 512);
    const float* s = W + (size_t)gather_row(n, t) * 512 + k;
    float4 a = *(const float4*)s;
    float4 b = *(const float4*)(s + 4);
    __half2 h[4] = { __floats2half2_rn(a.x, a.y), __floats2half2_rn(a.z, a.w),
                     __floats2half2_rn(b.x, b.y), __floats2half2_rn(b.z, b.w) };
    *(uint4*)(dst + idx) = *(uint4*)h;
}

// ---------------- arg structs -------------------------------------------------
struct LinSet  { const __half* A; const __half* W; const float* bias;
                 float* Cf; __half* Ch; int M; int K; };
struct LstmSet { const __half* A; const __half* Wg; const float* bG;
                 const __half* Acc; float* Cf; __half* Ch;
                 int M; int splitM; };  // rows < splitM -> Cf fp32; rest -> Ch fp16

// ===========================================================================
// gemm_lin16<OUT16>: C[M,N] = A[M,K] @ W[N,K]^T + bias
// BM=128, BN=128, BK=64 (128B rows, chunk c of row m at c^(m&7)), 256 thr
// (8 warps 2m x 4n), 3-stage cp.async (32KB/stage). 2 CTAs/SM.
// ===========================================================================
#define L_TA 16384
#define L_STRIDE 32768
#define SMEM_GEMM (3 * 32768)

template<bool OUT16>
__global__ __launch_bounds__(256, 2) void gemm_lin16(
    LinSet s0, LinSet s1, LinSet s2, int N) {
    const LinSet S = (blockIdx.z == 0) ? s0 : (blockIdx.z == 1 ? s1 : s2);
    const int m0 = blockIdx.y * 128, n0 = blockIdx.x * 128;
    if (m0 >= S.M) return;
    const int K = S.K;

    extern __shared__ char sm[];
    const uint32_t smb = (uint32_t)__cvta_generic_to_shared(sm);

    const int tid = threadIdx.x;
    const int wid = tid >> 5, lane = tid & 31;
    const int wm = wid & 1, wn = wid >> 1;
    const int lr = lane >> 2, lc = lane & 3;

    const int prow = tid >> 3, pch = tid & 7;
    const __half* srcA[4];
    uint32_t dA[4];
#pragma unroll
    for (int p = 0; p < 4; p++) {
        int r = prow + 32 * p;
        srcA[p] = S.A + (size_t)(m0 + r) * K + pch * 8;
        dA[p] = smb + r * 128 + ((pch ^ (r & 7)) << 4);
    }
    const __half* srcB[4];
    uint32_t dB[4];
    bool brOK[4];
#pragma unroll
    for (int p = 0; p < 4; p++) {
        int r = prow + 32 * p;
        brOK[p] = (n0 + r) < N;
        srcB[p] = S.W + (size_t)(brOK[p] ? (n0 + r) : 0) * K + pch * 8;
        dB[p] = smb + L_TA + r * 128 + ((pch ^ (r & 7)) << 4);
    }

    const int l15 = lane & 15, hi = lane >> 4;
    uint32_t aOff[4], bOff[2];
    int aSwz[4], bSwz[2];
#pragma unroll
    for (int mi = 0; mi < 4; mi++) {
        int r = wm * 64 + mi * 16 + l15;
        aOff[mi] = r * 128; aSwz[mi] = r & 7;
    }
#pragma unroll
    for (int nj = 0; nj < 2; nj++) {
        int r = wn * 32 + nj * 16 + l15;
        bOff[nj] = L_TA + r * 128; bSwz[nj] = r & 7;
    }

    float acc[4][4][4];
#pragma unroll
    for (int mi = 0; mi < 4; mi++)
#pragma unroll
        for (int ni = 0; ni < 4; ni++)
#pragma unroll
            for (int r = 0; r < 4; r++) acc[mi][ni][r] = 0.0f;

    const int nt = (K + 63) >> 6;
    auto LOAD = [&](int st, int kt) {
        const uint32_t so = st * L_STRIDE;
        const int kb = (kt + pch * 8 + 8 <= K) ? 16 : 0;
#pragma unroll
        for (int p = 0; p < 4; p++) cpa16(dA[p] + so, srcA[p] + kt, kb);
#pragma unroll
        for (int p = 0; p < 4; p++) cpa16(dB[p] + so, srcB[p] + kt, brOK[p] ? kb : 0);
    };

    LOAD(0, 0); cp_commit();
    LOAD(1, 64); cp_commit();

    for (int i = 0; i < nt; i++) {
        cp_wait<1>();
        __syncthreads();
        if (i + 2 < nt) LOAD((i + 2) % 3, (i + 2) << 6);
        cp_commit();

        const uint32_t base = smb + (i % 3) * L_STRIDE;
#pragma unroll
        for (int s = 0; s < 4; s++) {
            const int ch = 2 * s + hi;
            unsigned af[4][4], bq[2][4];
#pragma unroll
            for (int mi = 0; mi < 4; mi++)
                ldsm4(af[mi][0], af[mi][1], af[mi][2], af[mi][3],
                      base + aOff[mi] + ((ch ^ aSwz[mi]) << 4));
#pragma unroll
            for (int nj = 0; nj < 2; nj++)
                ldsm4(bq[nj][0], bq[nj][1], bq[nj][2], bq[nj][3],
                      base + bOff[nj] + ((ch ^ bSwz[nj]) << 4));
#pragma unroll
            for (int mi = 0; mi < 4; mi++)
#pragma unroll
                for (int nj = 0; nj < 2; nj++) {
                    mma_f16(acc[mi][2 * nj][0], acc[mi][2 * nj][1],
                            acc[mi][2 * nj][2], acc[mi][2 * nj][3],
                            af[mi][0], af[mi][1], af[mi][2], af[mi][3],
                            bq[nj][0], bq[nj][2]);
                    mma_f16(acc[mi][2 * nj + 1][0], acc[mi][2 * nj + 1][1],
                            acc[mi][2 * nj + 1][2], acc[mi][2 * nj + 1][3],
                            af[mi][0], af[mi][1], af[mi][2], af[mi][3],
                            bq[nj][1], bq[nj][3]);
                }
        }
    }

#pragma unroll
    for (int mi = 0; mi < 4; mi++) {
        int m = m0 + wm * 64 + mi * 16 + lr;
#pragma unroll
        for (int ni = 0; ni < 4; ni++) {
            int n = n0 + wn * 32 + ni * 8 + lc * 2;
            if (n + 1 < N) {
                float b0 = S.bias[n], b1 = S.bias[n + 1];
                float v00 = acc[mi][ni][0] + b0, v01 = acc[mi][ni][1] + b1;
                float v10 = acc[mi][ni][2] + b0, v11 = acc[mi][ni][3] + b1;
                if (OUT16) {
                    *(__half2*)(S.Ch + (size_t)m * N + n) = __floats2half2_rn(v00, v01);
                    *(__half2*)(S.Ch + (size_t)(m + 8) * N + n) = __floats2half2_rn(v10, v11);
                } else {
                    *(float2*)(S.Cf + (size_t)m * N + n) = make_float2(v00, v01);
                    *(float2*)(S.Cf + (size_t)(m + 8) * N + n) = make_float2(v10, v11);
                }
            } else if (n < N) {
                float b0 = S.bias[n];
                if (OUT16) {
                    S.Ch[(size_t)m * N + n] = __float2half_rn(acc[mi][ni][0] + b0);
                    S.Ch[(size_t)(m + 8) * N + n] = __float2half_rn(acc[mi][ni][2] + b0);
                } else {
                    S.Cf[(size_t)m * N + n] = acc[mi][ni][0] + b0;
                    S.Cf[(size_t)(m + 8) * N + n] = acc[mi][ni][2] + b0;
                }
            }
        }
    }
}

// ===========================================================================
// gemm_lstm16<ACC>: fused single-step BiLSTM (gates pre-gathered, Wg [3,2000,512])
// out = scale * sig(o)*tanh(sig(i)*tanh(g))  [+ fp16 Acc if ACC]
// rows < splitM -> Cf fp32 ; rows >= splitM -> Ch fp16 at (row - splitM).
// BM=64, BN=64x3 gates, BK=64, 256 thr (8 warps 2m x 4n), 3-stage. K=512.
// ===========================================================================
#define S_TA 8192
#define S_STRIDE 32768

template<bool ACC>
__global__ __launch_bounds__(256, 2) void gemm_lstm16(
    LstmSet s0, LstmSet s1, float scale) {
    const int N = 2000, K = 512;
    const LstmSet S = blockIdx.z ? s1 : s0;
    const int m0 = blockIdx.y * 64, n0 = blockIdx.x * 64;
    if (m0 >= S.M) return;

    extern __shared__ char sm[];
    const uint32_t smb = (uint32_t)__cvta_generic_to_shared(sm);

    const int tid = threadIdx.x;
    const int wid = tid >> 5, lane = tid & 31;
    const int wm = wid & 1, wn = wid >> 1;
    const int lr = lane >> 2, lc = lane & 3;

    const int prow = tid >> 3, pch = tid & 7;
    const __half* srcA[2];
    uint32_t dA[2];
#pragma unroll
    for (int p = 0; p < 2; p++) {
        int r = prow + 32 * p;
        srcA[p] = S.A + (size_t)(m0 + r) * K + pch * 8;
        dA[p] = smb + r * 128 + ((pch ^ (r & 7)) << 4);
    }
    const __half* srcB[6];
    uint32_t dB[6];
    bool bOK[6];
#pragma unroll
    for (int p = 0; p < 6; p++) {
        int r = prow + 32 * p;
        int t = r >> 6, rr = r & 63;
        bOK[p] = (n0 + rr) < N;
        srcB[p] = S.Wg + (size_t)(t * 2000 + (bOK[p] ? n0 + rr : 0)) * K + pch * 8;
        dB[p] = smb + S_TA + r * 128 + ((pch ^ (r & 7)) << 4);
    }

    const int l15 = lane & 15, hi = lane >> 4;
    uint32_t aOff[2]; int aSwz[2];
#pragma unroll
    for (int mi = 0; mi < 2; mi++) {
        int r = wm * 32 + mi * 16 + l15;
        aOff[mi] = r * 128; aSwz[mi] = r & 7;
    }
    uint32_t bOff[3]; int bSwz;
    {
        int r = wn * 16 + l15;
        bSwz = r & 7;
#pragma unroll
        for (int t = 0; t < 3; t++) bOff[t] = S_TA + (t * 64 + r) * 128;
    }

    float acc[3][2][2][4];
#pragma unroll
    for (int t = 0; t < 3; t++)
#pragma unroll
        for (int mi = 0; mi < 2; mi++)
#pragma unroll
            for (int ni = 0; ni < 2; ni++)
#pragma unroll
                for (int r = 0; r < 4; r++) acc[t][mi][ni][r] = 0.0f;

    const int nt = K >> 6;
    auto LOAD = [&](int st, int kt) {
        const uint32_t so = st * S_STRIDE;
#pragma unroll
        for (int p = 0; p < 2; p++) cpa16(dA[p] + so, srcA[p] + kt, 16);
#pragma unroll
        for (int p = 0; p < 6; p++) cpa16(dB[p] + so, srcB[p] + kt, bOK[p] ? 16 : 0);
    };

    LOAD(0, 0); cp_commit();
    LOAD(1, 64); cp_commit();

    for (int i = 0; i < nt; i++) {
        cp_wait<1>();
        __syncthreads();
        if (i + 2 < nt) LOAD((i + 2) % 3, (i + 2) << 6);
        cp_commit();

        const uint32_t base = smb + (i % 3) * S_STRIDE;
#pragma unroll
        for (int s = 0; s < 4; s++) {
            const int ch = 2 * s + hi;
            unsigned af[2][4], bt[3][4];
#pragma unroll
            for (int mi = 0; mi < 2; mi++)
                ldsm4(af[mi][0], af[mi][1], af[mi][2], af[mi][3],
                      base + aOff[mi] + ((ch ^ aSwz[mi]) << 4));
#pragma unroll
            for (int t = 0; t < 3; t++)
                ldsm4(bt[t][0], bt[t][1], bt[t][2], bt[t][3],
                      base + bOff[t] + ((ch ^ bSwz) << 4));
#pragma unroll
            for (int t = 0; t < 3; t++)
#pragma unroll
                for (int mi = 0; mi < 2; mi++) {
                    mma_f16(acc[t][mi][0][0], acc[t][mi][0][1],
                            acc[t][mi][0][2], acc[t][mi][0][3],
                            af[mi][0], af[mi][1], af[mi][2], af[mi][3],
                            bt[t][0], bt[t][2]);
                    mma_f16(acc[t][mi][1][0], acc[t][mi][1][1],
                            acc[t][mi][1][2], acc[t][mi][1][3],
                            af[mi][0], af[mi][1], af[mi][2], af[mi][3],
                            bt[t][1], bt[t][3]);
                }
        }
    }

    // ---- hw-tanh epilogue, fp16 accum, split stores --------------------------
#pragma unroll
    for (int mi = 0; mi < 2; mi++)
#pragma unroll
        for (int ni = 0; ni < 2; ni++) {
            int mA = m0 + wm * 32 + mi * 16 + lr;
            int nA = n0 + wn * 16 + ni * 8 + lc * 2;
#pragma unroll
            for (int half = 0; half < 2; half++) {
                int mm = mA + half * 8;
                float o[2];
#pragma unroll
                for (int q = 0; q < 2; q++) {
                    int r = half * 2 + q;
                    int nn = nA + q;
                    int d = (nn >= 1000);
                    int base = d * 4000 + (nn - d * 1000);
                    float gi = acc[0][mi][ni][r] + S.bG[base];
                    float gg = acc[1][mi][ni][r] + S.bG[base + 2000];
                    float go = acc[2][mi][ni][r] + S.bG[base + 3000];
                    float cc = sig_hw(gi) * tanh_hw(gg);
                    o[q] = scale * sig_hw(go) * tanh_hw(cc);
                }
                if (nA + 1 < N) {
                    if (ACC) {
                        float2 av = __half22float2(
                            *(const __half2*)(S.Acc + (size_t)mm * N + nA));
                        o[0] += av.x; o[1] += av.y;
                    }
                    if (mm < S.splitM)
                        *(float2*)(S.Cf + (size_t)mm * N + nA) = make_float2(o[0], o[1]);
                    else
                        *(__half2*)(S.Ch + (size_t)(mm - S.splitM) * N + nA) =
                            __floats2half2_rn(o[0], o[1]);
                } else if (nA < N) {
                    float v = o[0];
                    if (ACC) v += __half2float(S.Acc[(size_t)mm * N + nA]);
                    if (mm < S.splitM) S.Cf[(size_t)mm * N + nA] = v;
                    else S.Ch[(size_t)(mm - S.splitM) * N + nA] = __float2half_rn(v);
                }
            }
        }
}

// ---------------- paired neighbor mean: [1024,24,E] -> [1024,E], vectorized --
__global__ void mean16(const __half* __restrict__ Z, __half* __restrict__ out) {
    int idx = (blockIdx.x * blockDim.x + threadIdx.x) * 8;
    if (idx >= 2 * BB * EE) return;
    int bI = idx / EE, n = idx % EE;            // EE % 8 == 0, so n is 8-aligned
    float s[8];
#pragma unroll
    for (int q = 0; q < 8; q++) s[q] = 0.f;
    const __half* base = Z + (size_t)bI * 24 * EE + n;
    for (int j = 0; j < 24; j++) {
        uint4 v = *(const uint4*)(base + (size_t)j * EE);
        const __half2* h = (const __half2*)&v;
#pragma unroll
        for (int q = 0; q < 4; q++) {
            float2 f = __half22float2(h[q]);
            s[2 * q] += f.x; s[2 * q + 1] += f.y;
        }
    }
    __half2 r[4];
#pragma unroll
    for (int q = 0; q < 4; q++)
        r[q] = __floats2half2_rn(s[2 * q] * (1.0f / 24.0f), s[2 * q + 1] * (1.0f / 24.0f));
    *(uint4*)(out + idx) = *(uint4*)r;
}

// ---------------- 3-way attention combine ------------------------------------
__global__ void attention_kernel(const float* __restrict__ c, const float* __restrict__ u,
                                 const float* __restrict__ p, const float* __restrict__ att,
                                 float* __restrict__ out) {
    int bI = blockIdx.x, tid = threadIdx.x;
    const float* cb = c + (size_t)bI * EE;
    const float* ub = u + (size_t)bI * EE;
    const float* pb = p + (size_t)bI * EE;
    float s0 = 0.f, s1 = 0.f, s2 = 0.f, s3 = 0.f;
    for (int n = tid; n < EE; n += 256) {
        float a0 = att[n], a1 = att[EE + n];
        float cv = cb[n];
        s0 += cv * a0;
        s1 += cv * a1;
        s2 += ub[n] * a1;
        s3 += pb[n] * a1;
    }
    __shared__ float red[4][256];
    red[0][tid] = s0; red[1][tid] = s1; red[2][tid] = s2; red[3][tid] = s3;
    __syncthreads();
    for (int s = 128; s > 0; s >>= 1) {
        if (tid < s) {
#pragma unroll
            for (int q = 0; q < 4; q++) red[q][tid] += red[q][tid + s];
        }
        __syncthreads();
    }
    __shared__ float w[3];
    if (tid == 0) {
        float sc[3];
        sc[0] = red[0][0] + red[1][0];
        sc[1] = red[0][0] + red[2][0];
        sc[2] = red[0][0] + red[3][0];
#pragma unroll
        for (int k = 0; k < 3; k++) sc[k] = sc[k] > 0.f ? sc[k] : 0.01f * sc[k];
        float mx = fmaxf(sc[0], fmaxf(sc[1], sc[2]));
        float e0 = __expf(sc[0] - mx), e1 = __expf(sc[1] - mx), e2 = __expf(sc[2] - mx);
        float inv = 1.0f / (e0 + e1 + e2);
        w[0] = e0 * inv; w[1] = e1 * inv; w[2] = e2 * inv;
    }
    __syncthreads();
    float w0 = w[0], w1 = w[1], w2 = w[2];
    for (int n = tid; n < EE; n += 256)
        out[(size_t)bI * EE + n] = w0 * cb[n] + w1 * ub[n] + w2 * pb[n];
}

// ---------------------------------------------------------------------------
extern "C" void kernel_launch(void* const* d_in, const int* in_sizes, int n_in,
                              void* d_out, int out_size) {
    const float* c_text  = (const float*)d_in[0];
    const float* c_image = (const float*)d_in[1];
    const float* p_text  = (const float*)d_in[2];
    const float* p_image = (const float*)d_in[3];
    const float* u_text  = (const float*)d_in[4];
    const float* u_other = (const float*)d_in[5];
    const float* W_lt = (const float*)d_in[6],  *b_lt = (const float*)d_in[7];
    const float* W_li = (const float*)d_in[8],  *b_li = (const float*)d_in[9];
    const float* W_lo = (const float*)d_in[10], *b_lo = (const float*)d_in[11];
    const float* lstm_t_W = (const float*)d_in[12], *lstm_t_b = (const float*)d_in[13];
    const float* lstm_i_W = (const float*)d_in[14], *lstm_i_b = (const float*)d_in[15];
    const float* lstm_o_W = (const float*)d_in[16], *lstm_o_b = (const float*)d_in[17];
    const float* ua_lin_W = (const float*)d_in[18], *ua_lin_b = (const float*)d_in[19];
    const float* ua_lstm_W = (const float*)d_in[20], *ua_lstm_b = (const float*)d_in[21];
    const float* ua_out_W = (const float*)d_in[22], *ua_out_b = (const float*)d_in[23];
    const float* pa_lin_W = (const float*)d_in[24], *pa_lin_b = (const float*)d_in[25];
    const float* pa_lstm_W = (const float*)d_in[26], *pa_lstm_b = (const float*)d_in[27];
    const float* pa_out_W = (const float*)d_in[28], *pa_out_b = (const float*)d_in[29];
    const float* p_att = (const float*)d_in[30];
    float* out = (float*)d_out;

    __half *in16, *w16, *bufX, *Ht16, *Hp16, *Hu16, *H2, *Hm;
    float *Hc, *uagg, *pagg;
    cudaGetSymbolAddress((void**)&in16, g_in16);
    cudaGetSymbolAddress((void**)&w16,  g_w16);
    cudaGetSymbolAddress((void**)&bufX, g_bufX);
    cudaGetSymbolAddress((void**)&Hc,   g_Hc);
    cudaGetSymbolAddress((void**)&Ht16, g_Ht16);
    cudaGetSymbolAddress((void**)&Hp16, g_Hp16);
    cudaGetSymbolAddress((void**)&Hu16, g_Hu16);
    cudaGetSymbolAddress((void**)&H2,   g_H2);
    cudaGetSymbolAddress((void**)&Hm,   g_Hm);
    cudaGetSymbolAddress((void**)&uagg, g_uagg);
    cudaGetSymbolAddress((void**)&pagg, g_pagg);

    cudaFuncSetAttribute(gemm_lin16<true>,
                         cudaFuncAttributeMaxDynamicSharedMemorySize, SMEM_GEMM);
    cudaFuncSetAttribute(gemm_lin16<false>,
                         cudaFuncAttributeMaxDynamicSharedMemorySize, SMEM_GEMM);
    cudaFuncSetAttribute(gemm_lstm16<false>,
                         cudaFuncAttributeMaxDynamicSharedMemorySize, SMEM_GEMM);
    cudaFuncSetAttribute(gemm_lstm16<true>,
                         cudaFuncAttributeMaxDynamicSharedMemorySize, SMEM_GEMM);

    // ---- 1: weight linears (7 segs) ----
    {
        CvtSegs cs{};
        cs.src[0] = W_lt;     cs.dst[0] = w16 + O_WLT;   cs.n[0] = 512 * 768;
        cs.src[1] = W_li;     cs.dst[1] = w16 + O_WLI;   cs.n[1] = 512 * 2048;
        cs.src[2] = W_lo;     cs.dst[2] = w16 + O_WLO;   cs.n[2] = 512 * 512;
        cs.src[3] = ua_lin_W; cs.dst[3] = w16 + O_UALIN; cs.n[3] = 512 * 2000;
        cs.src[4] = pa_lin_W; cs.dst[4] = w16 + O_PALIN; cs.n[4] = 512 * 2000;
        cs.src[5] = ua_out_W; cs.dst[5] = w16 + O_UAOUT; cs.n[5] = 2000 * 2000;
        cs.src[6] = pa_out_W; cs.dst[6] = w16 + O_PAOUT; cs.n[6] = 2000 * 2000;
        int gx = (2000 * 2000 / 8 + 255) / 256;
        cvt_many<<<dim3(gx, 1, 7), 256>>>(cs);
    }
    // ---- 2: lstm weight gathers (5 via z) ----
    {
        Lstm5 ws{ { lstm_t_W, lstm_i_W, lstm_o_W, ua_lstm_W, pa_lstm_W } };
        int gx = (3 * 2000 * 512 / 8 + 255) / 256;
        cvt_lstm5<<<dim3(gx, 1, 5), 256>>>(ws, w16);
    }
    // ---- 3: inputs (6 segs) ----
    {
        CvtSegs cs{};
        cs.src[0] = c_text;  cs.dst[0] = in16 + I_TEXT;                    cs.n[0] = BB * 768;
        cs.src[1] = p_text;  cs.dst[1] = in16 + I_TEXT + BB * 768;         cs.n[1] = MPU * 768;
        cs.src[2] = u_text;  cs.dst[2] = in16 + I_TEXT + (BB + MPU) * 768; cs.n[2] = MPU * 768;
        cs.src[3] = c_image; cs.dst[3] = in16 + I_IMG;                     cs.n[3] = BB * 2048;
        cs.src[4] = p_image; cs.dst[4] = in16 + I_IMG + BB * 2048;         cs.n[4] = MPU * 2048;
        cs.src[5] = u_other; cs.dst[5] = in16 + I_OTH;                     cs.n[5] = MPU * 512;
        int gx = (MPU * 2048 / 8 + 255) / 256;
        cvt_many<<<dim3(gx, 1, 6), 256>>>(cs);
    }

    // ---- 4: all three input linears, one z=3 launch (N=512) ----
    {
        LinSet a{in16 + I_TEXT, w16 + O_WLT, b_lt, nullptr, bufX + X_TEXT, MT, 768};
        LinSet b{in16 + I_IMG,  w16 + O_WLI, b_li, nullptr, bufX + X_IMG,  MI2, 2048};
        LinSet c{in16 + I_OTH,  w16 + O_WLO, b_lo, nullptr, bufX + X_OTH,  MPU, 512};
        gemm_lin16<true><<<dim3(4, MT / 128, 3), 256, SMEM_GEMM>>>(a, b, c, 512);
    }
    // ---- 5: text LSTM -> Ht16 fp16 ----
    {
        LstmSet t{bufX + X_TEXT, w16 + O_LT, lstm_t_b, nullptr, nullptr, Ht16,
                  MT, 0};
        gemm_lstm16<false><<<dim3(32, MT / 64, 1), 256, SMEM_GEMM>>>(t, t, 0.5f);
    }
    // ---- 6: image LSTM (split Hc/Hp16) + other LSTM (Hu16), z=2, fp16 accum --
    {
        LstmSet im{bufX + X_IMG, w16 + O_LT + 1 * 3072000, lstm_i_b, Ht16,
                   Hc, Hp16, MI2, BB};
        LstmSet ot{bufX + X_OTH, w16 + O_LT + 2 * 3072000, lstm_o_b,
                   Ht16 + (size_t)MI2 * EE, nullptr, Hu16, MPU, 0};
        gemm_lstm16<true><<<dim3(32, MI2 / 64, 2), 256, SMEM_GEMM>>>(im, ot, 0.5f);
    }
    // ---- 7: paired agg linears (z=2, N=512, K=2000) ----
    {
        LinSet a{Hu16, w16 + O_UALIN, ua_lin_b, nullptr, bufX, MPU, 2000};
        LinSet b{Hp16, w16 + O_PALIN, pa_lin_b, nullptr, bufX + (size_t)MPU * 512,
                 MPU, 2000};
        gemm_lin16<true><<<dim3(4, MPU / 128, 2), 256, SMEM_GEMM>>>(a, b, b, 512);
    }
    // ---- 8: paired agg LSTMs (z=2) ----
    {
        LstmSet a{bufX, w16 + O_LT + 3 * 3072000, ua_lstm_b, nullptr, nullptr, H2,
                  MPU, 0};
        LstmSet b{bufX + (size_t)MPU * 512, w16 + O_LT + 4 * 3072000, pa_lstm_b,
                  nullptr, nullptr, H2 + (size_t)MPU * EE, MPU, 0};
        gemm_lstm16<false><<<dim3(32, MPU / 64, 2), 256, SMEM_GEMM>>>(a, b, 1.0f);
    }
    // ---- 9: paired neighbor mean (vectorized) ----
    mean16<<<(2 * BB * EE / 8 + 255) / 256, 256>>>(H2, Hm);
    // ---- 10: paired out-linears (z=2, N=2000, fp32 out) ----
    {
        LinSet a{Hm, w16 + O_UAOUT, ua_out_b, uagg, nullptr, BB, 2000};
        LinSet b{Hm + (size_t)BB * EE, w16 + O_PAOUT, pa_out_b, pagg, nullptr,
                 BB, 2000};
        gemm_lin16<false><<<dim3(16, BB / 128, 2), 256, SMEM_GEMM>>>(a, b, b, 2000);
    }
    // ---- 11: attention combine ----
    attention_kernel<<<BB, 256>>>(Hc, uagg, pagg, p_att, out);
}

// round 13
// speedup vs baseline: 7.3080x; 1.0055x over previous
#include <cuda_runtime.h>
#include <cuda_fp16.h>
#include <cstdint>

// ---------------------------------------------------------------------------
// Het_GNN forward — fp16 mma.sync, BK=64 3-stage, 2 CTAs/SM, cp.async.cg,
// hw-tanh epilogue, fp16 intermediates, software-pipelined LSTM fragments.
// ---------------------------------------------------------------------------
#define BB   512
#define MPU  12288
#define MT   25088
#define MI2  12800
#define EE   2000

__device__ __half g_in16 [51773440];
__device__ __half g_w16  [27111936];
__device__ __half g_bufX [25690112];
__device__ __half g_Ht16 [MT * EE];
__device__ float  g_Hc   [BB  * EE];
__device__ __half g_Hp16 [MPU * EE];
__device__ __half g_Hu16 [MPU * EE];
__device__ __half g_H2   [2 * MPU * EE];
__device__ __half g_Hm   [2 * BB * EE];
__device__ float  g_uagg [BB * EE];
__device__ float  g_pagg [BB * EE];

#define I_TEXT 0
#define I_IMG  19267584
#define I_OTH  45481984
#define X_TEXT 0
#define X_IMG  12845056
#define X_OTH  19398656
#define O_WLT   0
#define O_WLI   393216
#define O_WLO   1441792
#define O_LT    1703936      // 5 lstm gathers, stride 3072000
#define O_UALIN 17063936
#define O_PALIN 18087936
#define O_UAOUT 19111936
#define O_PAOUT 23111936

// ---------------- helpers ----------------------------------------------------
__device__ __forceinline__ float tanh_hw(float x) {
    float r;
    asm("tanh.approx.f32 %0, %1;" : "=f"(r) : "f"(x));
    return r;
}
__device__ __forceinline__ float sig_hw(float x) {
    return fmaf(0.5f, tanh_hw(0.5f * x), 0.5f);
}
__device__ __forceinline__ void mma_f16(float& d0, float& d1, float& d2, float& d3,
                                        unsigned a0, unsigned a1, unsigned a2, unsigned a3,
                                        unsigned b0, unsigned b1) {
    asm volatile(
        "mma.sync.aligned.m16n8k16.row.col.f32.f16.f16.f32 "
        "{%0,%1,%2,%3}, {%4,%5,%6,%7}, {%8,%9}, {%0,%1,%2,%3};"
        : "+f"(d0), "+f"(d1), "+f"(d2), "+f"(d3)
        : "r"(a0), "r"(a1), "r"(a2), "r"(a3), "r"(b0), "r"(b1));
}
__device__ __forceinline__ void ldsm4(unsigned& r0, unsigned& r1, unsigned& r2,
                                      unsigned& r3, uint32_t a) {
    asm volatile("ldmatrix.sync.aligned.m8n8.x4.shared.b16 {%0,%1,%2,%3}, [%4];"
                 : "=r"(r0), "=r"(r1), "=r"(r2), "=r"(r3) : "r"(a));
}
__device__ __forceinline__ void cpa16(uint32_t dst, const void* src, int srcbytes) {
    asm volatile("cp.async.cg.shared.global [%0], [%1], 16, %2;"
                 :: "r"(dst), "l"(src), "r"(srcbytes) : "memory");
}
__device__ __forceinline__ void cp_commit() {
    asm volatile("cp.async.commit_group;" ::: "memory");
}
template<int N>
__device__ __forceinline__ void cp_wait() {
    asm volatile("cp.async.wait_group %0;" :: "n"(N) : "memory");
}
__device__ __forceinline__ int gather_row(int n, int t) {
    int d = (n >= 1000);
    int toff = (t == 0) ? 0 : (t == 1 ? 2000 : 3000);
    return d * 4000 + toff + (n - d * 1000);
}

// ---------------- batched conversion kernels (1 group / thread) --------------
struct CvtSegs {
    const float* src[8];
    __half* dst[8];
    int n[8];
};
__global__ void cvt_many(CvtSegs cs) {
    const int z = blockIdx.z;
    const int n = cs.n[z];
    const int i = (blockIdx.x * blockDim.x + threadIdx.x) * 8;
    if (i >= n) return;
    const float* __restrict__ src = cs.src[z];
    __half* __restrict__ dst = cs.dst[z];
    float4 a = *(const float4*)(src + i);
    float4 b = *(const float4*)(src + i + 4);
    __half2 h[4] = { __floats2half2_rn(a.x, a.y), __floats2half2_rn(a.z, a.w),
                     __floats2half2_rn(b.x, b.y), __floats2half2_rn(b.z, b.w) };
    *(uint4*)(dst + i) = *(uint4*)h;
}
struct Lstm5 { const float* W[5]; };
__global__ void cvt_lstm5(Lstm5 ws, __half* __restrict__ base) {
    const int z = blockIdx.z;
    const int idx = (blockIdx.x * blockDim.x + threadIdx.x) * 8;
    if (idx >= 3 * 2000 * 512) return;
    const float* __restrict__ W = ws.W[z];
    __half* __restrict__ dst = base + O_LT + (size_t)z * 3072000;
    int k = idx & 511;
    int n = (idx >> 9) % 2000;
    int t = idx / (2000 * 512);
    const float* s = W + (size_t)gather_row(n, t) * 512 + k;
    float4 a = *(const float4*)s;
    float4 b = *(const float4*)(s + 4);
    __half2 h[4] = { __floats2half2_rn(a.x, a.y), __floats2half2_rn(a.z, a.w),
                     __floats2half2_rn(b.x, b.y), __floats2half2_rn(b.z, b.w) };
    *(uint4*)(dst + idx) = *(uint4*)h;
}

// ---------------- arg structs -------------------------------------------------
struct LinSet  { const __half* A; const __half* W; const float* bias;
                 float* Cf; __half* Ch; int M; int K; };
struct LstmSet { const __half* A; const __half* Wg; const float* bG;
                 const __half* Acc; float* Cf; __half* Ch;
                 int M; int splitM; };

// ===========================================================================
// gemm_lin16<OUT16>: C[M,N] = A[M,K] @ W[N,K]^T + bias
// BM=128, BN=128, BK=64, 256 thr (8 warps 2m x 4n), 3-stage. 2 CTAs/SM.
// ===========================================================================
#define L_TA 16384
#define L_STRIDE 32768
#define SMEM_GEMM (3 * 32768)

template<bool OUT16>
__global__ __launch_bounds__(256, 2) void gemm_lin16(
    LinSet s0, LinSet s1, LinSet s2, int N) {
    const LinSet S = (blockIdx.z == 0) ? s0 : (blockIdx.z == 1 ? s1 : s2);
    const int m0 = blockIdx.y * 128, n0 = blockIdx.x * 128;
    if (m0 >= S.M) return;
    const int K = S.K;

    extern __shared__ char sm[];
    const uint32_t smb = (uint32_t)__cvta_generic_to_shared(sm);

    const int tid = threadIdx.x;
    const int wid = tid >> 5, lane = tid & 31;
    const int wm = wid & 1, wn = wid >> 1;
    const int lr = lane >> 2, lc = lane & 3;

    const int prow = tid >> 3, pch = tid & 7;
    const __half* srcA[4];
    uint32_t dA[4];
#pragma unroll
    for (int p = 0; p < 4; p++) {
        int r = prow + 32 * p;
        srcA[p] = S.A + (size_t)(m0 + r) * K + pch * 8;
        dA[p] = smb + r * 128 + ((pch ^ (r & 7)) << 4);
    }
    const __half* srcB[4];
    uint32_t dB[4];
    bool brOK[4];
#pragma unroll
    for (int p = 0; p < 4; p++) {
        int r = prow + 32 * p;
        brOK[p] = (n0 + r) < N;
        srcB[p] = S.W + (size_t)(brOK[p] ? (n0 + r) : 0) * K + pch * 8;
        dB[p] = smb + L_TA + r * 128 + ((pch ^ (r & 7)) << 4);
    }

    const int l15 = lane & 15, hi = lane >> 4;
    uint32_t aOff[4], bOff[2];
    int aSwz[4], bSwz[2];
#pragma unroll
    for (int mi = 0; mi < 4; mi++) {
        int r = wm * 64 + mi * 16 + l15;
        aOff[mi] = r * 128; aSwz[mi] = r & 7;
    }
#pragma unroll
    for (int nj = 0; nj < 2; nj++) {
        int r = wn * 32 + nj * 16 + l15;
        bOff[nj] = L_TA + r * 128; bSwz[nj] = r & 7;
    }

    float acc[4][4][4];
#pragma unroll
    for (int mi = 0; mi < 4; mi++)
#pragma unroll
        for (int ni = 0; ni < 4; ni++)
#pragma unroll
            for (int r = 0; r < 4; r++) acc[mi][ni][r] = 0.0f;

    const int nt = (K + 63) >> 6;
    auto LOAD = [&](int st, int kt) {
        const uint32_t so = st * L_STRIDE;
        const int kb = (kt + pch * 8 + 8 <= K) ? 16 : 0;
#pragma unroll
        for (int p = 0; p < 4; p++) cpa16(dA[p] + so, srcA[p] + kt, kb);
#pragma unroll
        for (int p = 0; p < 4; p++) cpa16(dB[p] + so, srcB[p] + kt, brOK[p] ? kb : 0);
    };

    LOAD(0, 0); cp_commit();
    LOAD(1, 64); cp_commit();

    for (int i = 0; i < nt; i++) {
        cp_wait<1>();
        __syncthreads();
        if (i + 2 < nt) LOAD((i + 2) % 3, (i + 2) << 6);
        cp_commit();

        const uint32_t base = smb + (i % 3) * L_STRIDE;
#pragma unroll
        for (int s = 0; s < 4; s++) {
            const int ch = 2 * s + hi;
            unsigned af[4][4], bq[2][4];
#pragma unroll
            for (int mi = 0; mi < 4; mi++)
                ldsm4(af[mi][0], af[mi][1], af[mi][2], af[mi][3],
                      base + aOff[mi] + ((ch ^ aSwz[mi]) << 4));
#pragma unroll
            for (int nj = 0; nj < 2; nj++)
                ldsm4(bq[nj][0], bq[nj][1], bq[nj][2], bq[nj][3],
                      base + bOff[nj] + ((ch ^ bSwz[nj]) << 4));
#pragma unroll
            for (int mi = 0; mi < 4; mi++)
#pragma unroll
                for (int nj = 0; nj < 2; nj++) {
                    mma_f16(acc[mi][2 * nj][0], acc[mi][2 * nj][1],
                            acc[mi][2 * nj][2], acc[mi][2 * nj][3],
                            af[mi][0], af[mi][1], af[mi][2], af[mi][3],
                            bq[nj][0], bq[nj][2]);
                    mma_f16(acc[mi][2 * nj + 1][0], acc[mi][2 * nj + 1][1],
                            acc[mi][2 * nj + 1][2], acc[mi][2 * nj + 1][3],
                            af[mi][0], af[mi][1], af[mi][2], af[mi][3],
                            bq[nj][1], bq[nj][3]);
                }
        }
    }

#pragma unroll
    for (int mi = 0; mi < 4; mi++) {
        int m = m0 + wm * 64 + mi * 16 + lr;
#pragma unroll
        for (int ni = 0; ni < 4; ni++) {
            int n = n0 + wn * 32 + ni * 8 + lc * 2;
            if (n + 1 < N) {
                float b0 = S.bias[n], b1 = S.bias[n + 1];
                float v00 = acc[mi][ni][0] + b0, v01 = acc[mi][ni][1] + b1;
                float v10 = acc[mi][ni][2] + b0, v11 = acc[mi][ni][3] + b1;
                if (OUT16) {
                    *(__half2*)(S.Ch + (size_t)m * N + n) = __floats2half2_rn(v00, v01);
                    *(__half2*)(S.Ch + (size_t)(m + 8) * N + n) = __floats2half2_rn(v10, v11);
                } else {
                    *(float2*)(S.Cf + (size_t)m * N + n) = make_float2(v00, v01);
                    *(float2*)(S.Cf + (size_t)(m + 8) * N + n) = make_float2(v10, v11);
                }
            } else if (n < N) {
                float b0 = S.bias[n];
                if (OUT16) {
                    S.Ch[(size_t)m * N + n] = __float2half_rn(acc[mi][ni][0] + b0);
                    S.Ch[(size_t)(m + 8) * N + n] = __float2half_rn(acc[mi][ni][2] + b0);
                } else {
                    S.Cf[(size_t)m * N + n] = acc[mi][ni][0] + b0;
                    S.Cf[(size_t)(m + 8) * N + n] = acc[mi][ni][2] + b0;
                }
            }
        }
    }
}

// ===========================================================================
// gemm_lstm16<ACC>: fused single-step BiLSTM, software-pipelined fragments.
// BM=64, BN=64x3 gates, BK=64, 256 thr (8 warps 2m x 4n), 3-stage. K=512.
// ===========================================================================
#define S_TA 8192
#define S_STRIDE 32768

template<bool ACC>
__global__ __launch_bounds__(256, 2) void gemm_lstm16(
    LstmSet s0, LstmSet s1, float scale) {
    const int N = 2000, K = 512;
    const LstmSet S = blockIdx.z ? s1 : s0;
    const int m0 = blockIdx.y * 64, n0 = blockIdx.x * 64;
    if (m0 >= S.M) return;

    extern __shared__ char sm[];
    const uint32_t smb = (uint32_t)__cvta_generic_to_shared(sm);

    const int tid = threadIdx.x;
    const int wid = tid >> 5, lane = tid & 31;
    const int wm = wid & 1, wn = wid >> 1;
    const int lr = lane >> 2, lc = lane & 3;

    const int prow = tid >> 3, pch = tid & 7;
    const __half* srcA[2];
    uint32_t dA[2];
#pragma unroll
    for (int p = 0; p < 2; p++) {
        int r = prow + 32 * p;
        srcA[p] = S.A + (size_t)(m0 + r) * K + pch * 8;
        dA[p] = smb + r * 128 + ((pch ^ (r & 7)) << 4);
    }
    const __half* srcB[6];
    uint32_t dB[6];
    bool bOK[6];
#pragma unroll
    for (int p = 0; p < 6; p++) {
        int r = prow + 32 * p;
        int t = r >> 6, rr = r & 63;
        bOK[p] = (n0 + rr) < N;
        srcB[p] = S.Wg + (size_t)(t * 2000 + (bOK[p] ? n0 + rr : 0)) * K + pch * 8;
        dB[p] = smb + S_TA + r * 128 + ((pch ^ (r & 7)) << 4);
    }

    const int l15 = lane & 15, hi = lane >> 4;
    uint32_t aOff[2]; int aSwz[2];
#pragma unroll
    for (int mi = 0; mi < 2; mi++) {
        int r = wm * 32 + mi * 16 + l15;
        aOff[mi] = r * 128; aSwz[mi] = r & 7;
    }
    uint32_t bOff[3]; int bSwz;
    {
        int r = wn * 16 + l15;
        bSwz = r & 7;
#pragma unroll
        for (int t = 0; t < 3; t++) bOff[t] = S_TA + (t * 64 + r) * 128;
    }

    float acc[3][2][2][4];
#pragma unroll
    for (int t = 0; t < 3; t++)
#pragma unroll
        for (int mi = 0; mi < 2; mi++)
#pragma unroll
            for (int ni = 0; ni < 2; ni++)
#pragma unroll
                for (int r = 0; r < 4; r++) acc[t][mi][ni][r] = 0.0f;

    const int nt = K >> 6;
    auto LOAD = [&](int st, int kt) {
        const uint32_t so = st * S_STRIDE;
#pragma unroll
        for (int p = 0; p < 2; p++) cpa16(dA[p] + so, srcA[p] + kt, 16);
#pragma unroll
        for (int p = 0; p < 6; p++) cpa16(dB[p] + so, srcB[p] + kt, bOK[p] ? 16 : 0);
    };

    LOAD(0, 0); cp_commit();
    LOAD(1, 64); cp_commit();

    // double-buffered fragments: load chunk s+1 before issuing MMAs of chunk s
    unsigned af[2][2][4], bt[2][3][4];

    for (int i = 0; i < nt; i++) {
        cp_wait<1>();
        __syncthreads();
        if (i + 2 < nt) LOAD((i + 2) % 3, (i + 2) << 6);
        cp_commit();

        const uint32_t base = smb + (i % 3) * S_STRIDE;
        // prologue: fragments for s=0
        {
            const int ch = hi;
#pragma unroll
            for (int mi = 0; mi < 2; mi++)
                ldsm4(af[0][mi][0], af[0][mi][1], af[0][mi][2], af[0][mi][3],
                      base + aOff[mi] + ((ch ^ aSwz[mi]) << 4));
#pragma unroll
            for (int t = 0; t < 3; t++)
                ldsm4(bt[0][t][0], bt[0][t][1], bt[0][t][2], bt[0][t][3],
                      base + bOff[t] + ((ch ^ bSwz) << 4));
        }
#pragma unroll
        for (int s = 0; s < 4; s++) {
            const int cur = s & 1, nxt = cur ^ 1;
            if (s < 3) {
                const int ch = 2 * (s + 1) + hi;
#pragma unroll
                for (int mi = 0; mi < 2; mi++)
                    ldsm4(af[nxt][mi][0], af[nxt][mi][1], af[nxt][mi][2], af[nxt][mi][3],
                          base + aOff[mi] + ((ch ^ aSwz[mi]) << 4));
#pragma unroll
                for (int t = 0; t < 3; t++)
                    ldsm4(bt[nxt][t][0], bt[nxt][t][1], bt[nxt][t][2], bt[nxt][t][3],
                          base + bOff[t] + ((ch ^ bSwz) << 4));
            }
#pragma unroll
            for (int t = 0; t < 3; t++)
#pragma unroll
                for (int mi = 0; mi < 2; mi++) {
                    mma_f16(acc[t][mi][0][0], acc[t][mi][0][1],
                            acc[t][mi][0][2], acc[t][mi][0][3],
                            af[cur][mi][0], af[cur][mi][1], af[cur][mi][2], af[cur][mi][3],
                            bt[cur][t][0], bt[cur][t][2]);
                    mma_f16(acc[t][mi][1][0], acc[t][mi][1][1],
                            acc[t][mi][1][2], acc[t][mi][1][3],
                            af[cur][mi][0], af[cur][mi][1], af[cur][mi][2], af[cur][mi][3],
                            bt[cur][t][1], bt[cur][t][3]);
                }
        }
    }

    // ---- hw-tanh epilogue, fp16 accum, split stores --------------------------
#pragma unroll
    for (int mi = 0; mi < 2; mi++)
#pragma unroll
        for (int ni = 0; ni < 2; ni++) {
            int mA = m0 + wm * 32 + mi * 16 + lr;
            int nA = n0 + wn * 16 + ni * 8 + lc * 2;
#pragma unroll
            for (int half = 0; half < 2; half++) {
                int mm = mA + half * 8;
                float o[2];
#pragma unroll
                for (int q = 0; q < 2; q++) {
                    int r = half * 2 + q;
                    int nn = nA + q;
                    int d = (nn >= 1000);
                    int base = d * 4000 + (nn - d * 1000);
                    float gi = acc[0][mi][ni][r] + S.bG[base];
                    float gg = acc[1][mi][ni][r] + S.bG[base + 2000];
                    float go = acc[2][mi][ni][r] + S.bG[base + 3000];
                    float cc = sig_hw(gi) * tanh_hw(gg);
                    o[q] = scale * sig_hw(go) * tanh_hw(cc);
                }
                if (nA + 1 < N) {
                    if (ACC) {
                        float2 av = __half22float2(
                            *(const __half2*)(S.Acc + (size_t)mm * N + nA));
                        o[0] += av.x; o[1] += av.y;
                    }
                    if (mm < S.splitM)
                        *(float2*)(S.Cf + (size_t)mm * N + nA) = make_float2(o[0], o[1]);
                    else
                        *(__half2*)(S.Ch + (size_t)(mm - S.splitM) * N + nA) =
                            __floats2half2_rn(o[0], o[1]);
                } else if (nA < N) {
                    float v = o[0];
                    if (ACC) v += __half2float(S.Acc[(size_t)mm * N + nA]);
                    if (mm < S.splitM) S.Cf[(size_t)mm * N + nA] = v;
                    else S.Ch[(size_t)(mm - S.splitM) * N + nA] = __float2half_rn(v);
                }
            }
        }
}

// ---------------- paired neighbor mean: vectorized ---------------------------
__global__ void mean16(const __half* __restrict__ Z, __half* __restrict__ out) {
    int idx = (blockIdx.x * blockDim.x + threadIdx.x) * 8;
    if (idx >= 2 * BB * EE) return;
    int bI = idx / EE, n = idx % EE;
    float s[8];
#pragma unroll
    for (int q = 0; q < 8; q++) s[q] = 0.f;
    const __half* base = Z + (size_t)bI * 24 * EE + n;
    for (int j = 0; j < 24; j++) {
        uint4 v = *(const uint4*)(base + (size_t)j * EE);
        const __half2* h = (const __half2*)&v;
#pragma unroll
        for (int q = 0; q < 4; q++) {
            float2 f = __half22float2(h[q]);
            s[2 * q] += f.x; s[2 * q + 1] += f.y;
        }
    }
    __half2 r[4];
#pragma unroll
    for (int q = 0; q < 4; q++)
        r[q] = __floats2half2_rn(s[2 * q] * (1.0f / 24.0f), s[2 * q + 1] * (1.0f / 24.0f));
    *(uint4*)(out + idx) = *(uint4*)r;
}

// ---------------- 3-way attention combine ------------------------------------
__global__ void attention_kernel(const float* __restrict__ c, const float* __restrict__ u,
                                 const float* __restrict__ p, const float* __restrict__ att,
                                 float* __restrict__ out) {
    int bI = blockIdx.x, tid = threadIdx.x;
    const float* cb = c + (size_t)bI * EE;
    const float* ub = u + (size_t)bI * EE;
    const float* pb = p + (size_t)bI * EE;
    float s0 = 0.f, s1 = 0.f, s2 = 0.f, s3 = 0.f;
    for (int n = tid; n < EE; n += 256) {
        float a0 = att[n], a1 = att[EE + n];
        float cv = cb[n];
        s0 += cv * a0;
        s1 += cv * a1;
        s2 += ub[n] * a1;
        s3 += pb[n] * a1;
    }
    __shared__ float red[4][256];
    red[0][tid] = s0; red[1][tid] = s1; red[2][tid] = s2; red[3][tid] = s3;
    __syncthreads();
    for (int s = 128; s > 0; s >>= 1) {
        if (tid < s) {
#pragma unroll
            for (int q = 0; q < 4; q++) red[q][tid] += red[q][tid + s];
        }
        __syncthreads();
    }
    __shared__ float w[3];
    if (tid == 0) {
        float sc[3];
        sc[0] = red[0][0] + red[1][0];
        sc[1] = red[0][0] + red[2][0];
        sc[2] = red[0][0] + red[3][0];
#pragma unroll
        for (int k = 0; k < 3; k++) sc[k] = sc[k] > 0.f ? sc[k] : 0.01f * sc[k];
        float mx = fmaxf(sc[0], fmaxf(sc[1], sc[2]));
        float e0 = __expf(sc[0] - mx), e1 = __expf(sc[1] - mx), e2 = __expf(sc[2] - mx);
        float inv = 1.0f / (e0 + e1 + e2);
        w[0] = e0 * inv; w[1] = e1 * inv; w[2] = e2 * inv;
    }
    __syncthreads();
    float w0 = w[0], w1 = w[1], w2 = w[2];
    for (int n = tid; n < EE; n += 256)
        out[(size_t)bI * EE + n] = w0 * cb[n] + w1 * ub[n] + w2 * pb[n];
}

// ---------------------------------------------------------------------------
extern "C" void kernel_launch(void* const* d_in, const int* in_sizes, int n_in,
                              void* d_out, int out_size) {
    const float* c_text  = (const float*)d_in[0];
    const float* c_image = (const float*)d_in[1];
    const float* p_text  = (const float*)d_in[2];
    const float* p_image = (const float*)d_in[3];
    const float* u_text  = (const float*)d_in[4];
    const float* u_other = (const float*)d_in[5];
    const float* W_lt = (const float*)d_in[6],  *b_lt = (const float*)d_in[7];
    const float* W_li = (const float*)d_in[8],  *b_li = (const float*)d_in[9];
    const float* W_lo = (const float*)d_in[10], *b_lo = (const float*)d_in[11];
    const float* lstm_t_W = (const float*)d_in[12], *lstm_t_b = (const float*)d_in[13];
    const float* lstm_i_W = (const float*)d_in[14], *lstm_i_b = (const float*)d_in[15];
    const float* lstm_o_W = (const float*)d_in[16], *lstm_o_b = (const float*)d_in[17];
    const float* ua_lin_W = (const float*)d_in[18], *ua_lin_b = (const float*)d_in[19];
    const float* ua_lstm_W = (const float*)d_in[20], *ua_lstm_b = (const float*)d_in[21];
    const float* ua_out_W = (const float*)d_in[22], *ua_out_b = (const float*)d_in[23];
    const float* pa_lin_W = (const float*)d_in[24], *pa_lin_b = (const float*)d_in[25];
    const float* pa_lstm_W = (const float*)d_in[26], *pa_lstm_b = (const float*)d_in[27];
    const float* pa_out_W = (const float*)d_in[28], *pa_out_b = (const float*)d_in[29];
    const float* p_att = (const float*)d_in[30];
    float* out = (float*)d_out;

    __half *in16, *w16, *bufX, *Ht16, *Hp16, *Hu16, *H2, *Hm;
    float *Hc, *uagg, *pagg;
    cudaGetSymbolAddress((void**)&in16, g_in16);
    cudaGetSymbolAddress((void**)&w16,  g_w16);
    cudaGetSymbolAddress((void**)&bufX, g_bufX);
    cudaGetSymbolAddress((void**)&Hc,   g_Hc);
    cudaGetSymbolAddress((void**)&Ht16, g_Ht16);
    cudaGetSymbolAddress((void**)&Hp16, g_Hp16);
    cudaGetSymbolAddress((void**)&Hu16, g_Hu16);
    cudaGetSymbolAddress((void**)&H2,   g_H2);
    cudaGetSymbolAddress((void**)&Hm,   g_Hm);
    cudaGetSymbolAddress((void**)&uagg, g_uagg);
    cudaGetSymbolAddress((void**)&pagg, g_pagg);

    cudaFuncSetAttribute(gemm_lin16<true>,
                         cudaFuncAttributeMaxDynamicSharedMemorySize, SMEM_GEMM);
    cudaFuncSetAttribute(gemm_lin16<false>,
                         cudaFuncAttributeMaxDynamicSharedMemorySize, SMEM_GEMM);
    cudaFuncSetAttribute(gemm_lstm16<false>,
                         cudaFuncAttributeMaxDynamicSharedMemorySize, SMEM_GEMM);
    cudaFuncSetAttribute(gemm_lstm16<true>,
                         cudaFuncAttributeMaxDynamicSharedMemorySize, SMEM_GEMM);

    // ---- 1: weight linears (7 segs) ----
    {
        CvtSegs cs{};
        cs.src[0] = W_lt;     cs.dst[0] = w16 + O_WLT;   cs.n[0] = 512 * 768;
        cs.src[1] = W_li;     cs.dst[1] = w16 + O_WLI;   cs.n[1] = 512 * 2048;
        cs.src[2] = W_lo;     cs.dst[2] = w16 + O_WLO;   cs.n[2] = 512 * 512;
        cs.src[3] = ua_lin_W; cs.dst[3] = w16 + O_UALIN; cs.n[3] = 512 * 2000;
        cs.src[4] = pa_lin_W; cs.dst[4] = w16 + O_PALIN; cs.n[4] = 512 * 2000;
        cs.src[5] = ua_out_W; cs.dst[5] = w16 + O_UAOUT; cs.n[5] = 2000 * 2000;
        cs.src[6] = pa_out_W; cs.dst[6] = w16 + O_PAOUT; cs.n[6] = 2000 * 2000;
        int gx = (2000 * 2000 / 8 + 255) / 256;
        cvt_many<<<dim3(gx, 1, 7), 256>>>(cs);
    }
    // ---- 2: lstm weight gathers (5 via z) ----
    {
        Lstm5 ws{ { lstm_t_W, lstm_i_W, lstm_o_W, ua_lstm_W, pa_lstm_W } };
        int gx = (3 * 2000 * 512 / 8 + 255) / 256;
        cvt_lstm5<<<dim3(gx, 1, 5), 256>>>(ws, w16);
    }
    // ---- 3: inputs (6 segs) ----
    {
        CvtSegs cs{};
        cs.src[0] = c_text;  cs.dst[0] = in16 + I_TEXT;                    cs.n[0] = BB * 768;
        cs.src[1] = p_text;  cs.dst[1] = in16 + I_TEXT + BB * 768;         cs.n[1] = MPU * 768;
        cs.src[2] = u_text;  cs.dst[2] = in16 + I_TEXT + (BB + MPU) * 768; cs.n[2] = MPU * 768;
        cs.src[3] = c_image; cs.dst[3] = in16 + I_IMG;                     cs.n[3] = BB * 2048;
        cs.src[4] = p_image; cs.dst[4] = in16 + I_IMG + BB * 2048;         cs.n[4] = MPU * 2048;
        cs.src[5] = u_other; cs.dst[5] = in16 + I_OTH;                     cs.n[5] = MPU * 512;
        int gx = (MPU * 2048 / 8 + 255) / 256;
        cvt_many<<<dim3(gx, 1, 6), 256>>>(cs);
    }

    // ---- 4: all three input linears, one z=3 launch (N=512) ----
    {
        LinSet a{in16 + I_TEXT, w16 + O_WLT, b_lt, nullptr, bufX + X_TEXT, MT, 768};
        LinSet b{in16 + I_IMG,  w16 + O_WLI, b_li, nullptr, bufX + X_IMG,  MI2, 2048};
        LinSet c{in16 + I_OTH,  w16 + O_WLO, b_lo, nullptr, bufX + X_OTH,  MPU, 512};
        gemm_lin16<true><<<dim3(4, MT / 128, 3), 256, SMEM_GEMM>>>(a, b, c, 512);
    }
    // ---- 5: text LSTM -> Ht16 fp16 ----
    {
        LstmSet t{bufX + X_TEXT, w16 + O_LT, lstm_t_b, nullptr, nullptr, Ht16,
                  MT, 0};
        gemm_lstm16<false><<<dim3(32, MT / 64, 1), 256, SMEM_GEMM>>>(t, t, 0.5f);
    }
    // ---- 6: image LSTM (split Hc/Hp16) + other LSTM (Hu16), z=2, fp16 accum --
    {
        LstmSet im{bufX + X_IMG, w16 + O_LT + 1 * 3072000, lstm_i_b, Ht16,
                   Hc, Hp16, MI2, BB};
        LstmSet ot{bufX + X_OTH, w16 + O_LT + 2 * 3072000, lstm_o_b,
                   Ht16 + (size_t)MI2 * EE, nullptr, Hu16, MPU, 0};
        gemm_lstm16<true><<<dim3(32, MI2 / 64, 2), 256, SMEM_GEMM>>>(im, ot, 0.5f);
    }
    // ---- 7: paired agg linears (z=2, N=512, K=2000) ----
    {
        LinSet a{Hu16, w16 + O_UALIN, ua_lin_b, nullptr, bufX, MPU, 2000};
        LinSet b{Hp16, w16 + O_PALIN, pa_lin_b, nullptr, bufX + (size_t)MPU * 512,
                 MPU, 2000};
        gemm_lin16<true><<<dim3(4, MPU / 128, 2), 256, SMEM_GEMM>>>(a, b, b, 512);
    }
    // ---- 8: paired agg LSTMs (z=2) ----
    {
        LstmSet a{bufX, w16 + O_LT + 3 * 3072000, ua_lstm_b, nullptr, nullptr, H2,
                  MPU, 0};
        LstmSet b{bufX + (size_t)MPU * 512, w16 + O_LT + 4 * 3072000, pa_lstm_b,
                  nullptr, nullptr, H2 + (size_t)MPU * EE, MPU, 0};
        gemm_lstm16<false><<<dim3(32, MPU / 64, 2), 256, SMEM_GEMM>>>(a, b, 1.0f);
    }
    // ---- 9: paired neighbor mean (vectorized) ----
    mean16<<<(2 * BB * EE / 8 + 255) / 256, 256>>>(H2, Hm);
    // ---- 10: paired out-linears (z=2, N=2000, fp32 out) ----
    {
        LinSet a{Hm, w16 + O_UAOUT, ua_out_b, uagg, nullptr, BB, 2000};
        LinSet b{Hm + (size_t)BB * EE, w16 + O_PAOUT, pa_out_b, pagg, nullptr,
                 BB, 2000};
        gemm_lin16<false><<<dim3(16, BB / 128, 2), 256, SMEM_GEMM>>>(a, b, b, 2000);
    }
    // ---- 11: attention combine ----
    attention_kernel<<<BB, 256>>>(Hc, uagg, pagg, p_att, out);
}